// round 1
// baseline (speedup 1.0000x reference)
#include <cuda_runtime.h>
#include <math.h>

#define BB   4
#define LL   1024
#define MM   (BB*LL)        // 4096 tokens
#define DIMS 4096
#define NH   32
#define NKV  8
#define HD   128
#define DKV  (NKV*HD)       // 1024

// Scratch (no cudaMalloc allowed) ------------------------------------------
__device__ float g_q[(size_t)MM*DIMS];
__device__ float g_k[(size_t)MM*DKV];
__device__ float g_v[(size_t)MM*DKV];
__device__ float g_attn[(size_t)MM*DIMS];

// ---------------- SGEMM: C[M,N] = A[M,K] * B[N,K]^T ------------------------
#define TBM 128
#define TBN 128
#define TBK 8

__global__ __launch_bounds__(256) void sgemm_nt(const float* __restrict__ A,
                                                const float* __restrict__ B,
                                                float* __restrict__ C,
                                                int M, int N, int K)
{
    __shared__ float As[TBK][TBM + 4];
    __shared__ float Bs[TBK][TBN + 4];

    const int tid = threadIdx.x;          // 256
    const int tx  = tid & 15;             // 0..15 (cols)
    const int ty  = tid >> 4;             // 0..15 (rows)
    const int bm  = blockIdx.y * TBM;
    const int bn  = blockIdx.x * TBN;

    const int lrow = tid >> 1;            // 0..127
    const int lcol = (tid & 1) * 4;       // 0 or 4

    const float* Ap = A + (size_t)(bm + lrow) * K + lcol;
    const float* Bp = B + (size_t)(bn + lrow) * K + lcol;

    float acc[8][8];
#pragma unroll
    for (int i = 0; i < 8; i++)
#pragma unroll
        for (int j = 0; j < 8; j++) acc[i][j] = 0.0f;

    for (int k0 = 0; k0 < K; k0 += TBK) {
        float4 av = *(const float4*)(Ap + k0);
        float4 bv = *(const float4*)(Bp + k0);
        As[lcol + 0][lrow] = av.x; As[lcol + 1][lrow] = av.y;
        As[lcol + 2][lrow] = av.z; As[lcol + 3][lrow] = av.w;
        Bs[lcol + 0][lrow] = bv.x; Bs[lcol + 1][lrow] = bv.y;
        Bs[lcol + 2][lrow] = bv.z; Bs[lcol + 3][lrow] = bv.w;
        __syncthreads();

#pragma unroll
        for (int kk = 0; kk < TBK; kk++) {
            float a[8], b[8];
            *(float4*)&a[0] = *(const float4*)&As[kk][ty * 8];
            *(float4*)&a[4] = *(const float4*)&As[kk][ty * 8 + 4];
            *(float4*)&b[0] = *(const float4*)&Bs[kk][tx * 8];
            *(float4*)&b[4] = *(const float4*)&Bs[kk][tx * 8 + 4];
#pragma unroll
            for (int i = 0; i < 8; i++)
#pragma unroll
                for (int j = 0; j < 8; j++)
                    acc[i][j] += a[i] * b[j];
        }
        __syncthreads();
    }

#pragma unroll
    for (int i = 0; i < 8; i++) {
        float* Cp = C + (size_t)(bm + ty * 8 + i) * N + bn + tx * 8;
        *(float4*)(Cp + 0) = make_float4(acc[i][0], acc[i][1], acc[i][2], acc[i][3]);
        *(float4*)(Cp + 4) = make_float4(acc[i][4], acc[i][5], acc[i][6], acc[i][7]);
    }
}

// ---------------- RoPE (interleaved pairs) ---------------------------------
__global__ void rope_kernel(float* __restrict__ t, const float* __restrict__ freqs,
                            int nheads, int total_pairs)
{
    int p = blockIdx.x * blockDim.x + threadIdx.x;
    if (p >= total_pairs) return;
    int d2 = p & 63;                        // HD/2 = 64
    int l  = (p / (64 * nheads)) % LL;
    float f = freqs[l * 64 + d2];
    float c = cosf(f), s = sinf(f);
    float a = t[2 * p], b = t[2 * p + 1];
    t[2 * p]     = a * c - b * s;
    t[2 * p + 1] = a * s + b * c;
}

// ---------------- Flash attention (fp32, causal) ---------------------------
#define AQPAD 132
#define APPAD 68
#define ATTN_SMEM ((3 * 64 * AQPAD + 64 * APPAD) * 4)   // 118784 B

__global__ __launch_bounds__(256) void attn_kernel(const float* __restrict__ q,
                                                   const float* __restrict__ k,
                                                   const float* __restrict__ v,
                                                   float* __restrict__ o)
{
    extern __shared__ float sm[];
    float* Qs = sm;                    // [64][132] row-major (row, d)
    float* Ks = Qs + 64 * AQPAD;       // [64][132]
    float* Vs = Ks + 64 * AQPAD;       // [64][132]
    float* Ps = Vs + 64 * AQPAD;       // [64][68]

    const int qt = blockIdx.x;         // 0..15
    const int h  = blockIdx.y;         // 0..31
    const int b  = blockIdx.z;         // 0..3
    const int tid = threadIdx.x;
    const int tx = tid & 15;
    const int ty = tid >> 4;
    const float scale = 0.088388347648318447f;   // 1/sqrt(128)

    // Load+scale Q tile [64][128]
    const float* qb = q + ((size_t)(b * LL + qt * 64) * NH + h) * HD;
    for (int i = tid; i < 64 * 32; i += 256) {
        int r = i >> 5, c = (i & 31) * 4;
        float4 u = *(const float4*)(qb + (size_t)r * (NH * HD) + c);
        Qs[r * AQPAD + c + 0] = u.x * scale;
        Qs[r * AQPAD + c + 1] = u.y * scale;
        Qs[r * AQPAD + c + 2] = u.z * scale;
        Qs[r * AQPAD + c + 3] = u.w * scale;
    }

    float m_[4], l_[4], o_[4][8];
#pragma unroll
    for (int i = 0; i < 4; i++) {
        m_[i] = -1e30f; l_[i] = 0.0f;
#pragma unroll
        for (int j = 0; j < 8; j++) o_[i][j] = 0.0f;
    }

    const int kvh = h >> 2;
    const float* kb = k + ((size_t)(b * LL) * NKV + kvh) * HD;
    const float* vb = v + ((size_t)(b * LL) * NKV + kvh) * HD;

    for (int kt = 0; kt <= qt; kt++) {
        __syncthreads();   // protect smem reused from previous iteration (and Q load on kt=0)
        for (int i = tid; i < 64 * 32; i += 256) {
            int r = i >> 5, c = (i & 31) * 4;
            size_t goff = (size_t)(kt * 64 + r) * DKV + c;
            *(float4*)&Ks[r * AQPAD + c] = *(const float4*)(kb + goff);
            *(float4*)&Vs[r * AQPAD + c] = *(const float4*)(vb + goff);
        }
        __syncthreads();

        // S = Qs * Ks^T  (4x4 microtile per thread)
        float s[4][4];
#pragma unroll
        for (int i = 0; i < 4; i++)
#pragma unroll
            for (int j = 0; j < 4; j++) s[i][j] = 0.0f;

        for (int d = 0; d < HD; d += 4) {
            float4 a0 = *(const float4*)&Qs[(ty * 4 + 0) * AQPAD + d];
            float4 a1 = *(const float4*)&Qs[(ty * 4 + 1) * AQPAD + d];
            float4 a2 = *(const float4*)&Qs[(ty * 4 + 2) * AQPAD + d];
            float4 a3 = *(const float4*)&Qs[(ty * 4 + 3) * AQPAD + d];
            float4 b0 = *(const float4*)&Ks[(tx * 4 + 0) * AQPAD + d];
            float4 b1 = *(const float4*)&Ks[(tx * 4 + 1) * AQPAD + d];
            float4 b2 = *(const float4*)&Ks[(tx * 4 + 2) * AQPAD + d];
            float4 b3 = *(const float4*)&Ks[(tx * 4 + 3) * AQPAD + d];
            float a[4][4] = {{a0.x,a0.y,a0.z,a0.w},{a1.x,a1.y,a1.z,a1.w},
                             {a2.x,a2.y,a2.z,a2.w},{a3.x,a3.y,a3.z,a3.w}};
            float bq[4][4] = {{b0.x,b0.y,b0.z,b0.w},{b1.x,b1.y,b1.z,b1.w},
                              {b2.x,b2.y,b2.z,b2.w},{b3.x,b3.y,b3.z,b3.w}};
#pragma unroll
            for (int i = 0; i < 4; i++)
#pragma unroll
                for (int j = 0; j < 4; j++)
#pragma unroll
                    for (int u = 0; u < 4; u++)
                        s[i][j] += a[i][u] * bq[j][u];
        }

        if (kt == qt) {
#pragma unroll
            for (int i = 0; i < 4; i++)
#pragma unroll
                for (int j = 0; j < 4; j++)
                    if (tx * 4 + j > ty * 4 + i) s[i][j] = -1e30f;
        }

        // Online softmax per row (row owned by the 16 tx-lanes of one warp half)
#pragma unroll
        for (int i = 0; i < 4; i++) {
            float rm = fmaxf(fmaxf(s[i][0], s[i][1]), fmaxf(s[i][2], s[i][3]));
#pragma unroll
            for (int w = 1; w < 16; w <<= 1)
                rm = fmaxf(rm, __shfl_xor_sync(0xffffffffu, rm, w));
            float mnew = fmaxf(m_[i], rm);
            float corr = expf(m_[i] - mnew);
            float p0 = expf(s[i][0] - mnew);
            float p1 = expf(s[i][1] - mnew);
            float p2 = expf(s[i][2] - mnew);
            float p3 = expf(s[i][3] - mnew);
            float rs = p0 + p1 + p2 + p3;
#pragma unroll
            for (int w = 1; w < 16; w <<= 1)
                rs += __shfl_xor_sync(0xffffffffu, rs, w);
            l_[i] = l_[i] * corr + rs;
            m_[i] = mnew;
#pragma unroll
            for (int jj = 0; jj < 8; jj++) o_[i][jj] *= corr;
            float* pr = &Ps[(ty * 4 + i) * APPAD + tx * 4];
            pr[0] = p0; pr[1] = p1; pr[2] = p2; pr[3] = p3;
        }
        __syncwarp();

        // O += P * V   (each thread: 4 rows x 8 dims)
        for (int j = 0; j < 64; j++) {
            float4 v0 = *(const float4*)&Vs[j * AQPAD + tx * 8];
            float4 v1 = *(const float4*)&Vs[j * AQPAD + tx * 8 + 4];
#pragma unroll
            for (int i = 0; i < 4; i++) {
                float p = Ps[(ty * 4 + i) * APPAD + j];
                o_[i][0] += p * v0.x; o_[i][1] += p * v0.y;
                o_[i][2] += p * v0.z; o_[i][3] += p * v0.w;
                o_[i][4] += p * v1.x; o_[i][5] += p * v1.y;
                o_[i][6] += p * v1.z; o_[i][7] += p * v1.w;
            }
        }
        __syncwarp();
    }

    // Epilogue: normalize and write [b, l, h*128 + d]
#pragma unroll
    for (int i = 0; i < 4; i++) {
        float inv = 1.0f / l_[i];
        float* op = o + (size_t)(b * LL + qt * 64 + ty * 4 + i) * DIMS + h * HD + tx * 8;
        *(float4*)(op + 0) = make_float4(o_[i][0]*inv, o_[i][1]*inv, o_[i][2]*inv, o_[i][3]*inv);
        *(float4*)(op + 4) = make_float4(o_[i][4]*inv, o_[i][5]*inv, o_[i][6]*inv, o_[i][7]*inv);
    }
}

// ---------------------------------------------------------------------------
extern "C" void kernel_launch(void* const* d_in, const int* in_sizes, int n_in,
                              void* d_out, int out_size)
{
    const float* x  = (const float*)d_in[0];
    const float* wq = (const float*)d_in[1];
    const float* wk = (const float*)d_in[2];
    const float* wv = (const float*)d_in[3];
    const float* wo = (const float*)d_in[4];
    const float* fr = (const float*)d_in[5];
    // d_in[6] = mask (causal, reproduced analytically), d_in[7] = starting_pos (0)
    float* out = (float*)d_out;

    float *qp, *kp, *vp, *ap;
    cudaGetSymbolAddress((void**)&qp, g_q);
    cudaGetSymbolAddress((void**)&kp, g_k);
    cudaGetSymbolAddress((void**)&vp, g_v);
    cudaGetSymbolAddress((void**)&ap, g_attn);

    dim3 gBig(DIMS / TBN, MM / TBM);   // 32 x 32
    dim3 gKV (DKV  / TBN, MM / TBM);   // 8 x 32

    sgemm_nt<<<gBig, 256>>>(x, wq, qp, MM, DIMS, DIMS);
    sgemm_nt<<<gKV , 256>>>(x, wk, kp, MM, DKV , DIMS);
    sgemm_nt<<<gKV , 256>>>(x, wv, vp, MM, DKV , DIMS);

    int qpairs = MM * NH  * (HD / 2);
    int kpairs = MM * NKV * (HD / 2);
    rope_kernel<<<(qpairs + 255) / 256, 256>>>(qp, fr, NH , qpairs);
    rope_kernel<<<(kpairs + 255) / 256, 256>>>(kp, fr, NKV, kpairs);

    cudaFuncSetAttribute(attn_kernel, cudaFuncAttributeMaxDynamicSharedMemorySize, ATTN_SMEM);
    dim3 gA(LL / 64, NH, BB);
    attn_kernel<<<gA, 256, ATTN_SMEM>>>(qp, kp, vp, ap);

    sgemm_nt<<<gBig, 256>>>(ap, wo, out, MM, DIMS, DIMS);
}

// round 3
// speedup vs baseline: 2.2270x; 2.2270x over previous
#include <cuda_runtime.h>
#include <math.h>

#define BB   4
#define LL   1024
#define MM   (BB*LL)        // 4096 tokens
#define DIMS 4096
#define NH   32
#define NKV  8
#define HD   128
#define DKV  (NKV*HD)       // 1024

// Scratch (no cudaMalloc allowed) ------------------------------------------
__device__ float g_q[(size_t)MM*DIMS];
__device__ float g_k[(size_t)MM*DKV];
__device__ float g_v[(size_t)MM*DKV];
__device__ float g_attn[(size_t)MM*DIMS];

// ---------------- TF32 tensor-core GEMM: C[M,N] = A[M,K] * B[N,K]^T --------
// mma.sync.aligned.m16n8k8.row.col : A row-major [m][k], B col-major == [n][k]
// Both operands are k-contiguous in memory -> no transpose anywhere.

__device__ __forceinline__ unsigned f2tf(float x) {
    unsigned r;
    asm("cvt.rna.tf32.f32 %0, %1;" : "=r"(r) : "f"(x));
    return r;
}

#define GTM 128
#define GTN 128
#define GTK 32
#define GSTR 36    // 32 + 4 pad: bank = (row*4 + k) % 32, conflict-free frags

__global__ __launch_bounds__(256) void tf32_gemm_nt(const float* __restrict__ A,
                                                    const float* __restrict__ B,
                                                    float* __restrict__ C,
                                                    int M, int N, int K)
{
    __shared__ unsigned As[GTM][GSTR];
    __shared__ unsigned Bs[GTN][GSTR];

    const int tid  = threadIdx.x;
    const int lane = tid & 31;
    const int warp = tid >> 5;          // 8 warps
    const int wm   = warp >> 1;         // 0..3  (M)
    const int wn   = warp & 1;          // 0..1  (N)
    const int bm   = blockIdx.y * GTM;
    const int bn   = blockIdx.x * GTN;

    const int lq = lane >> 2;           // 0..7 group
    const int lt = lane & 3;            // 0..3 thread-in-group

    float acc[2][8][4];
#pragma unroll
    for (int mt = 0; mt < 2; mt++)
#pragma unroll
        for (int nt = 0; nt < 8; nt++)
#pragma unroll
            for (int i = 0; i < 4; i++) acc[mt][nt][i] = 0.0f;

    for (int k0 = 0; k0 < K; k0 += GTK) {
        __syncthreads();   // protect smem reads of previous iteration
#pragma unroll
        for (int t = 0; t < 4; t++) {
            int idx = tid + t * 256;            // 0..1023
            int r = idx >> 3;                   // 0..127
            int c = (idx & 7) * 4;              // 0..28
            float4 av = *(const float4*)(A + (size_t)(bm + r) * K + k0 + c);
            float4 bv = *(const float4*)(B + (size_t)(bn + r) * K + k0 + c);
            As[r][c + 0] = f2tf(av.x); As[r][c + 1] = f2tf(av.y);
            As[r][c + 2] = f2tf(av.z); As[r][c + 3] = f2tf(av.w);
            Bs[r][c + 0] = f2tf(bv.x); Bs[r][c + 1] = f2tf(bv.y);
            Bs[r][c + 2] = f2tf(bv.z); Bs[r][c + 3] = f2tf(bv.w);
        }
        __syncthreads();

#pragma unroll
        for (int ks = 0; ks < 4; ks++) {
            const int kb = ks * 8;
            unsigned a[2][4], b[8][2];
#pragma unroll
            for (int mt = 0; mt < 2; mt++) {
                int r = wm * 32 + mt * 16 + lq;
                a[mt][0] = As[r    ][kb + lt];
                a[mt][1] = As[r + 8][kb + lt];
                a[mt][2] = As[r    ][kb + 4 + lt];
                a[mt][3] = As[r + 8][kb + 4 + lt];
            }
#pragma unroll
            for (int nt = 0; nt < 8; nt++) {
                int n = wn * 64 + nt * 8 + lq;
                b[nt][0] = Bs[n][kb + lt];
                b[nt][1] = Bs[n][kb + 4 + lt];
            }
#pragma unroll
            for (int mt = 0; mt < 2; mt++)
#pragma unroll
                for (int nt = 0; nt < 8; nt++)
                    asm volatile(
                        "mma.sync.aligned.m16n8k8.row.col.f32.tf32.tf32.f32 "
                        "{%0,%1,%2,%3}, {%4,%5,%6,%7}, {%8,%9}, {%0,%1,%2,%3};"
                        : "+f"(acc[mt][nt][0]), "+f"(acc[mt][nt][1]),
                          "+f"(acc[mt][nt][2]), "+f"(acc[mt][nt][3])
                        : "r"(a[mt][0]), "r"(a[mt][1]), "r"(a[mt][2]), "r"(a[mt][3]),
                          "r"(b[nt][0]), "r"(b[nt][1]));
        }
    }

    // Epilogue
#pragma unroll
    for (int mt = 0; mt < 2; mt++) {
        int r0 = bm + wm * 32 + mt * 16 + lq;
#pragma unroll
        for (int nt = 0; nt < 8; nt++) {
            int c = bn + wn * 64 + nt * 8 + 2 * lt;
            *(float2*)(C + (size_t)r0 * N + c)       = make_float2(acc[mt][nt][0], acc[mt][nt][1]);
            *(float2*)(C + (size_t)(r0 + 8) * N + c) = make_float2(acc[mt][nt][2], acc[mt][nt][3]);
        }
    }
}

// ---------------- RoPE (interleaved pairs) ---------------------------------
__global__ void rope_kernel(float* __restrict__ t, const float* __restrict__ freqs,
                            int nheads, int total_pairs)
{
    int p = blockIdx.x * blockDim.x + threadIdx.x;
    if (p >= total_pairs) return;
    int d2 = p & 63;                        // HD/2 = 64
    int l  = (p / (64 * nheads)) % LL;
    float f = freqs[l * 64 + d2];
    float c = cosf(f), s = sinf(f);
    float a = t[2 * p], b = t[2 * p + 1];
    t[2 * p]     = a * c - b * s;
    t[2 * p + 1] = a * s + b * c;
}

// ---------------- Flash attention (fp32, causal) ---------------------------
#define AQPAD 132
#define APPAD 68
#define ATTN_SMEM ((3 * 64 * AQPAD + 64 * APPAD) * 4)   // 118784 B

__global__ __launch_bounds__(256) void attn_kernel(const float* __restrict__ q,
                                                   const float* __restrict__ k,
                                                   const float* __restrict__ v,
                                                   float* __restrict__ o)
{
    extern __shared__ float sm[];
    float* Qs = sm;                    // [64][132] row-major (row, d)
    float* Ks = Qs + 64 * AQPAD;       // [64][132]
    float* Vs = Ks + 64 * AQPAD;       // [64][132]
    float* Ps = Vs + 64 * AQPAD;       // [64][68]

    const int qt = blockIdx.x;         // 0..15
    const int h  = blockIdx.y;         // 0..31
    const int b  = blockIdx.z;         // 0..3
    const int tid = threadIdx.x;
    const int tx = tid & 15;
    const int ty = tid >> 4;
    const float scale = 0.088388347648318447f;   // 1/sqrt(128)

    const float* qb = q + ((size_t)(b * LL + qt * 64) * NH + h) * HD;
    for (int i = tid; i < 64 * 32; i += 256) {
        int r = i >> 5, c = (i & 31) * 4;
        float4 u = *(const float4*)(qb + (size_t)r * (NH * HD) + c);
        Qs[r * AQPAD + c + 0] = u.x * scale;
        Qs[r * AQPAD + c + 1] = u.y * scale;
        Qs[r * AQPAD + c + 2] = u.z * scale;
        Qs[r * AQPAD + c + 3] = u.w * scale;
    }

    float m_[4], l_[4], o_[4][8];
#pragma unroll
    for (int i = 0; i < 4; i++) {
        m_[i] = -1e30f; l_[i] = 0.0f;
#pragma unroll
        for (int j = 0; j < 8; j++) o_[i][j] = 0.0f;
    }

    const int kvh = h >> 2;
    const float* kb = k + ((size_t)(b * LL) * NKV + kvh) * HD;
    const float* vb = v + ((size_t)(b * LL) * NKV + kvh) * HD;

    for (int kt = 0; kt <= qt; kt++) {
        __syncthreads();
        for (int i = tid; i < 64 * 32; i += 256) {
            int r = i >> 5, c = (i & 31) * 4;
            size_t goff = (size_t)(kt * 64 + r) * DKV + c;
            *(float4*)&Ks[r * AQPAD + c] = *(const float4*)(kb + goff);
            *(float4*)&Vs[r * AQPAD + c] = *(const float4*)(vb + goff);
        }
        __syncthreads();

        float s[4][4];
#pragma unroll
        for (int i = 0; i < 4; i++)
#pragma unroll
            for (int j = 0; j < 4; j++) s[i][j] = 0.0f;

        for (int d = 0; d < HD; d += 4) {
            float4 a0 = *(const float4*)&Qs[(ty * 4 + 0) * AQPAD + d];
            float4 a1 = *(const float4*)&Qs[(ty * 4 + 1) * AQPAD + d];
            float4 a2 = *(const float4*)&Qs[(ty * 4 + 2) * AQPAD + d];
            float4 a3 = *(const float4*)&Qs[(ty * 4 + 3) * AQPAD + d];
            float4 b0 = *(const float4*)&Ks[(tx * 4 + 0) * AQPAD + d];
            float4 b1 = *(const float4*)&Ks[(tx * 4 + 1) * AQPAD + d];
            float4 b2 = *(const float4*)&Ks[(tx * 4 + 2) * AQPAD + d];
            float4 b3 = *(const float4*)&Ks[(tx * 4 + 3) * AQPAD + d];
            float a[4][4] = {{a0.x,a0.y,a0.z,a0.w},{a1.x,a1.y,a1.z,a1.w},
                             {a2.x,a2.y,a2.z,a2.w},{a3.x,a3.y,a3.z,a3.w}};
            float bq[4][4] = {{b0.x,b0.y,b0.z,b0.w},{b1.x,b1.y,b1.z,b1.w},
                              {b2.x,b2.y,b2.z,b2.w},{b3.x,b3.y,b3.z,b3.w}};
#pragma unroll
            for (int i = 0; i < 4; i++)
#pragma unroll
                for (int j = 0; j < 4; j++)
#pragma unroll
                    for (int u = 0; u < 4; u++)
                        s[i][j] += a[i][u] * bq[j][u];
        }

        if (kt == qt) {
#pragma unroll
            for (int i = 0; i < 4; i++)
#pragma unroll
                for (int j = 0; j < 4; j++)
                    if (tx * 4 + j > ty * 4 + i) s[i][j] = -1e30f;
        }

#pragma unroll
        for (int i = 0; i < 4; i++) {
            float rm = fmaxf(fmaxf(s[i][0], s[i][1]), fmaxf(s[i][2], s[i][3]));
#pragma unroll
            for (int w = 1; w < 16; w <<= 1)
                rm = fmaxf(rm, __shfl_xor_sync(0xffffffffu, rm, w));
            float mnew = fmaxf(m_[i], rm);
            float corr = expf(m_[i] - mnew);
            float p0 = expf(s[i][0] - mnew);
            float p1 = expf(s[i][1] - mnew);
            float p2 = expf(s[i][2] - mnew);
            float p3 = expf(s[i][3] - mnew);
            float rs = p0 + p1 + p2 + p3;
#pragma unroll
            for (int w = 1; w < 16; w <<= 1)
                rs += __shfl_xor_sync(0xffffffffu, rs, w);
            l_[i] = l_[i] * corr + rs;
            m_[i] = mnew;
#pragma unroll
            for (int jj = 0; jj < 8; jj++) o_[i][jj] *= corr;
            float* pr = &Ps[(ty * 4 + i) * APPAD + tx * 4];
            pr[0] = p0; pr[1] = p1; pr[2] = p2; pr[3] = p3;
        }
        __syncwarp();

        for (int j = 0; j < 64; j++) {
            float4 v0 = *(const float4*)&Vs[j * AQPAD + tx * 8];
            float4 v1 = *(const float4*)&Vs[j * AQPAD + tx * 8 + 4];
#pragma unroll
            for (int i = 0; i < 4; i++) {
                float p = Ps[(ty * 4 + i) * APPAD + j];
                o_[i][0] += p * v0.x; o_[i][1] += p * v0.y;
                o_[i][2] += p * v0.z; o_[i][3] += p * v0.w;
                o_[i][4] += p * v1.x; o_[i][5] += p * v1.y;
                o_[i][6] += p * v1.z; o_[i][7] += p * v1.w;
            }
        }
        __syncwarp();
    }

#pragma unroll
    for (int i = 0; i < 4; i++) {
        float inv = 1.0f / l_[i];
        float* op = o + (size_t)(b * LL + qt * 64 + ty * 4 + i) * DIMS + h * HD + tx * 8;
        *(float4*)(op + 0) = make_float4(o_[i][0]*inv, o_[i][1]*inv, o_[i][2]*inv, o_[i][3]*inv);
        *(float4*)(op + 4) = make_float4(o_[i][4]*inv, o_[i][5]*inv, o_[i][6]*inv, o_[i][7]*inv);
    }
}

// ---------------------------------------------------------------------------
extern "C" void kernel_launch(void* const* d_in, const int* in_sizes, int n_in,
                              void* d_out, int out_size)
{
    const float* x  = (const float*)d_in[0];
    const float* wq = (const float*)d_in[1];
    const float* wk = (const float*)d_in[2];
    const float* wv = (const float*)d_in[3];
    const float* wo = (const float*)d_in[4];
    const float* fr = (const float*)d_in[5];
    float* out = (float*)d_out;

    float *qp, *kp, *vp, *ap;
    cudaGetSymbolAddress((void**)&qp, g_q);
    cudaGetSymbolAddress((void**)&kp, g_k);
    cudaGetSymbolAddress((void**)&vp, g_v);
    cudaGetSymbolAddress((void**)&ap, g_attn);

    dim3 gBig(DIMS / GTN, MM / GTM);   // 32 x 32
    dim3 gKV (DKV  / GTN, MM / GTM);   // 8 x 32

    tf32_gemm_nt<<<gBig, 256>>>(x, wq, qp, MM, DIMS, DIMS);
    tf32_gemm_nt<<<gKV , 256>>>(x, wk, kp, MM, DKV , DIMS);
    tf32_gemm_nt<<<gKV , 256>>>(x, wv, vp, MM, DKV , DIMS);

    int qpairs = MM * NH  * (HD / 2);
    int kpairs = MM * NKV * (HD / 2);
    rope_kernel<<<(qpairs + 255) / 256, 256>>>(qp, fr, NH , qpairs);
    rope_kernel<<<(kpairs + 255) / 256, 256>>>(kp, fr, NKV, kpairs);

    cudaFuncSetAttribute(attn_kernel, cudaFuncAttributeMaxDynamicSharedMemorySize, ATTN_SMEM);
    dim3 gA(LL / 64, NH, BB);
    attn_kernel<<<gA, 256, ATTN_SMEM>>>(qp, kp, vp, ap);

    tf32_gemm_nt<<<gBig, 256>>>(ap, wo, out, MM, DIMS, DIMS);
}

// round 7
// speedup vs baseline: 2.5447x; 1.1427x over previous
#include <cuda_runtime.h>
#include <math.h>
#include <stdint.h>

#define BB   4
#define LL   1024
#define MM   (BB*LL)        // 4096 tokens
#define DIMS 4096
#define NH   32
#define NKV  8
#define HD   128
#define DKV  (NKV*HD)       // 1024

// Scratch (no cudaMalloc allowed) ------------------------------------------
__device__ float g_q[(size_t)MM*DIMS];
__device__ float g_k[(size_t)MM*DKV];
__device__ float g_v[(size_t)MM*DKV];
__device__ float g_attn[(size_t)MM*DIMS];     // tf32-rounded attention out
// tf32 pre-converted operands
__device__ float g_xt [(size_t)MM*DIMS];
__device__ float g_wqt[(size_t)DIMS*DIMS];
__device__ float g_wkt[(size_t)DKV*DIMS];
__device__ float g_wvt[(size_t)DKV*DIMS];
__device__ float g_wot[(size_t)DIMS*DIMS];

// ======================= helpers ===========================================
__device__ __forceinline__ uint32_t smem_u32(const void* p) {
    uint32_t a;
    asm("{ .reg .u64 t; cvta.to.shared.u64 t, %1; cvt.u32.u64 %0, t; }"
        : "=r"(a) : "l"(p));
    return a;
}
__device__ __forceinline__ uint32_t f2tf(float x) {
    uint32_t r; asm("cvt.rna.tf32.f32 %0, %1;" : "=r"(r) : "f"(x)); return r;
}

// -------- tf32 pre-convert pass --------------------------------------------
__global__ void cvt_tf32(const float* __restrict__ in, float* __restrict__ out, int n4)
{
    int i = blockIdx.x * blockDim.x + threadIdx.x;
    if (i >= n4) return;
    float4 v = ((const float4*)in)[i];
    uint4 u = make_uint4(f2tf(v.x), f2tf(v.y), f2tf(v.z), f2tf(v.w));
    ((uint4*)out)[i] = u;
}

// ============ tf32 mma.sync GEMM with cp.async pipeline ====================
// C[M,N] = A[M,K] * B[N,K]^T ; A,B already tf32-rounded fp32 bits.
// Block tile 128x128, K-tile 32, 2-stage cp.async double buffer.
// Smem row pitch 144B (36 words): conflict-free 32-bit frag LDS AND
// 16B-aligned cp.async destinations. Warp layout: 4(M) x 2(N), 32x64 per warp.
#define GTK 32
#define ROW_B 144
#define A_BYTES  (128 * ROW_B)            // 18432
#define B_BYTES  (128 * ROW_B)            // 18432
#define STAGE_BYTES (A_BYTES + B_BYTES)   // 36864
#define GEMM_SMEM (2 * STAGE_BYTES)       // 73728 -> 2 CTAs/SM

__global__ __launch_bounds__(256, 2) void gemm_tc(const float* __restrict__ A,
                                                  const float* __restrict__ B0_,
                                                  const float* __restrict__ B1_,
                                                  float* __restrict__ C0_,
                                                  float* __restrict__ C1_,
                                                  int N, int K)
{
    extern __shared__ char sm[];
    const uint32_t smb = smem_u32(sm);
    const int tid  = threadIdx.x;
    const int lane = tid & 31;
    const int warp = tid >> 5;          // 8 warps
    const int wm   = warp >> 1;         // 0..3 (M)
    const int wn   = warp & 1;          // 0..1 (N)
    const int lq   = lane >> 2;         // 0..7
    const int lt   = lane & 3;          // 0..3
    const float* Bm = blockIdx.z ? B1_ : B0_;
    float*       C  = blockIdx.z ? C1_ : C0_;
    const int bm = blockIdx.y * 128;
    const int bn = blockIdx.x * 128;

    // cp.async chunks: A and B each 128 rows x 8 16B-chunks -> 4/thread each
    const float* aSrc[4]; const float* bSrc[4]; uint32_t dOff[4];
#pragma unroll
    for (int j = 0; j < 4; j++) {
        int idx = tid + j * 256;            // 0..1023
        int r = idx >> 3, c = idx & 7;
        aSrc[j] = A  + (size_t)(bm + r) * K + c * 4;
        bSrc[j] = Bm + (size_t)(bn + r) * K + c * 4;
        dOff[j] = r * ROW_B + c * 16;
    }

    float acc[2][8][4];
#pragma unroll
    for (int mt = 0; mt < 2; mt++)
#pragma unroll
        for (int nt = 0; nt < 8; nt++)
#pragma unroll
            for (int i = 0; i < 4; i++) acc[mt][nt][i] = 0.0f;

    const int KT = K / GTK;

    // Prologue: tile 0 -> buffer 0
#pragma unroll
    for (int j = 0; j < 4; j++) {
        asm volatile("cp.async.cg.shared.global [%0], [%1], 16;"
                     :: "r"(smb + dOff[j]), "l"(aSrc[j]) : "memory");
        asm volatile("cp.async.cg.shared.global [%0], [%1], 16;"
                     :: "r"(smb + A_BYTES + dOff[j]), "l"(bSrc[j]) : "memory");
    }
    asm volatile("cp.async.commit_group;" ::: "memory");

    for (int kt = 0; kt < KT; kt++) {
        const int s = kt & 1;
        if (kt + 1 < KT) {
            const uint32_t st = smb + (s ^ 1) * STAGE_BYTES;
            const size_t ko = (size_t)(kt + 1) * GTK;
#pragma unroll
            for (int j = 0; j < 4; j++) {
                asm volatile("cp.async.cg.shared.global [%0], [%1], 16;"
                             :: "r"(st + dOff[j]), "l"(aSrc[j] + ko) : "memory");
                asm volatile("cp.async.cg.shared.global [%0], [%1], 16;"
                             :: "r"(st + A_BYTES + dOff[j]), "l"(bSrc[j] + ko) : "memory");
            }
            asm volatile("cp.async.commit_group;" ::: "memory");
            asm volatile("cp.async.wait_group 1;" ::: "memory");
        } else {
            asm volatile("cp.async.wait_group 0;" ::: "memory");
        }
        __syncthreads();

        const char* bufA = sm + s * STAGE_BYTES;
        const char* bufB = bufA + A_BYTES;

#pragma unroll
        for (int ks = 0; ks < 4; ks++) {
            const int kb = ks * 8;
            unsigned a[2][4], b[8][2];
#pragma unroll
            for (int mt = 0; mt < 2; mt++) {
                int r = wm * 32 + mt * 16 + lq;
                a[mt][0] = *(const unsigned*)(bufA + r * ROW_B       + (kb + lt) * 4);
                a[mt][1] = *(const unsigned*)(bufA + (r + 8) * ROW_B + (kb + lt) * 4);
                a[mt][2] = *(const unsigned*)(bufA + r * ROW_B       + (kb + 4 + lt) * 4);
                a[mt][3] = *(const unsigned*)(bufA + (r + 8) * ROW_B + (kb + 4 + lt) * 4);
            }
#pragma unroll
            for (int nt = 0; nt < 8; nt++) {
                int n = wn * 64 + nt * 8 + lq;
                b[nt][0] = *(const unsigned*)(bufB + n * ROW_B + (kb + lt) * 4);
                b[nt][1] = *(const unsigned*)(bufB + n * ROW_B + (kb + 4 + lt) * 4);
            }
#pragma unroll
            for (int mt = 0; mt < 2; mt++)
#pragma unroll
                for (int nt = 0; nt < 8; nt++)
                    asm volatile(
                        "mma.sync.aligned.m16n8k8.row.col.f32.tf32.tf32.f32 "
                        "{%0,%1,%2,%3}, {%4,%5,%6,%7}, {%8,%9}, {%0,%1,%2,%3};"
                        : "+f"(acc[mt][nt][0]), "+f"(acc[mt][nt][1]),
                          "+f"(acc[mt][nt][2]), "+f"(acc[mt][nt][3])
                        : "r"(a[mt][0]), "r"(a[mt][1]), "r"(a[mt][2]), "r"(a[mt][3]),
                          "r"(b[nt][0]), "r"(b[nt][1]));
        }
        __syncthreads();
    }

    // Epilogue
#pragma unroll
    for (int mt = 0; mt < 2; mt++) {
        int r0 = bm + wm * 32 + mt * 16 + lq;
#pragma unroll
        for (int nt = 0; nt < 8; nt++) {
            int c = bn + wn * 64 + nt * 8 + 2 * lt;
            *(float2*)(C + (size_t)r0 * N + c)       = make_float2(acc[mt][nt][0], acc[mt][nt][1]);
            *(float2*)(C + (size_t)(r0 + 8) * N + c) = make_float2(acc[mt][nt][2], acc[mt][nt][3]);
        }
    }
}

// ---------------- RoPE (interleaved pairs) ---------------------------------
__global__ void rope_kernel(float* __restrict__ t, const float* __restrict__ freqs,
                            int nheads, int total_pairs)
{
    int p = blockIdx.x * blockDim.x + threadIdx.x;
    if (p >= total_pairs) return;
    int d2 = p & 63;                        // HD/2 = 64
    int l  = (p / (64 * nheads)) % LL;
    float f = freqs[l * 64 + d2];
    float c = cosf(f), s = sinf(f);
    float a = t[2 * p], b = t[2 * p + 1];
    t[2 * p]     = a * c - b * s;
    t[2 * p + 1] = a * s + b * c;
}

// ---------------- Flash attention (fp32, causal) ---------------------------
#define AQPAD 132
#define APPAD 68
#define ATTN_SMEM ((3 * 64 * AQPAD + 64 * APPAD) * 4)   // 118784 B

__global__ __launch_bounds__(256) void attn_kernel(const float* __restrict__ q,
                                                   const float* __restrict__ k,
                                                   const float* __restrict__ v,
                                                   float* __restrict__ o)
{
    extern __shared__ float smf[];
    float* Qs = smf;
    float* Ks = Qs + 64 * AQPAD;
    float* Vs = Ks + 64 * AQPAD;
    float* Ps = Vs + 64 * AQPAD;

    const int qt = blockIdx.x;
    const int h  = blockIdx.y;
    const int b  = blockIdx.z;
    const int tid = threadIdx.x;
    const int tx = tid & 15;
    const int ty = tid >> 4;
    const float scale = 0.088388347648318447f;   // 1/sqrt(128)

    const float* qb = q + ((size_t)(b * LL + qt * 64) * NH + h) * HD;
    for (int i = tid; i < 64 * 32; i += 256) {
        int r = i >> 5, c = (i & 31) * 4;
        float4 u = *(const float4*)(qb + (size_t)r * (NH * HD) + c);
        Qs[r * AQPAD + c + 0] = u.x * scale;
        Qs[r * AQPAD + c + 1] = u.y * scale;
        Qs[r * AQPAD + c + 2] = u.z * scale;
        Qs[r * AQPAD + c + 3] = u.w * scale;
    }

    float m_[4], l_[4], o_[4][8];
#pragma unroll
    for (int i = 0; i < 4; i++) {
        m_[i] = -1e30f; l_[i] = 0.0f;
#pragma unroll
        for (int j = 0; j < 8; j++) o_[i][j] = 0.0f;
    }

    const int kvh = h >> 2;
    const float* kb = k + ((size_t)(b * LL) * NKV + kvh) * HD;
    const float* vb = v + ((size_t)(b * LL) * NKV + kvh) * HD;

    for (int kt = 0; kt <= qt; kt++) {
        __syncthreads();
        for (int i = tid; i < 64 * 32; i += 256) {
            int r = i >> 5, c = (i & 31) * 4;
            size_t goff = (size_t)(kt * 64 + r) * DKV + c;
            *(float4*)&Ks[r * AQPAD + c] = *(const float4*)(kb + goff);
            *(float4*)&Vs[r * AQPAD + c] = *(const float4*)(vb + goff);
        }
        __syncthreads();

        float s[4][4];
#pragma unroll
        for (int i = 0; i < 4; i++)
#pragma unroll
            for (int j = 0; j < 4; j++) s[i][j] = 0.0f;

        for (int d = 0; d < HD; d += 4) {
            float4 a0 = *(const float4*)&Qs[(ty * 4 + 0) * AQPAD + d];
            float4 a1 = *(const float4*)&Qs[(ty * 4 + 1) * AQPAD + d];
            float4 a2 = *(const float4*)&Qs[(ty * 4 + 2) * AQPAD + d];
            float4 a3 = *(const float4*)&Qs[(ty * 4 + 3) * AQPAD + d];
            float4 b0 = *(const float4*)&Ks[(tx * 4 + 0) * AQPAD + d];
            float4 b1 = *(const float4*)&Ks[(tx * 4 + 1) * AQPAD + d];
            float4 b2 = *(const float4*)&Ks[(tx * 4 + 2) * AQPAD + d];
            float4 b3 = *(const float4*)&Ks[(tx * 4 + 3) * AQPAD + d];
            float a[4][4] = {{a0.x,a0.y,a0.z,a0.w},{a1.x,a1.y,a1.z,a1.w},
                             {a2.x,a2.y,a2.z,a2.w},{a3.x,a3.y,a3.z,a3.w}};
            float bq[4][4] = {{b0.x,b0.y,b0.z,b0.w},{b1.x,b1.y,b1.z,b1.w},
                              {b2.x,b2.y,b2.z,b2.w},{b3.x,b3.y,b3.z,b3.w}};
#pragma unroll
            for (int i = 0; i < 4; i++)
#pragma unroll
                for (int j = 0; j < 4; j++)
#pragma unroll
                    for (int u = 0; u < 4; u++)
                        s[i][j] += a[i][u] * bq[j][u];
        }

        if (kt == qt) {
#pragma unroll
            for (int i = 0; i < 4; i++)
#pragma unroll
                for (int j = 0; j < 4; j++)
                    if (tx * 4 + j > ty * 4 + i) s[i][j] = -1e30f;
        }

#pragma unroll
        for (int i = 0; i < 4; i++) {
            float rm = fmaxf(fmaxf(s[i][0], s[i][1]), fmaxf(s[i][2], s[i][3]));
#pragma unroll
            for (int w = 1; w < 16; w <<= 1)
                rm = fmaxf(rm, __shfl_xor_sync(0xffffffffu, rm, w));
            float mnew = fmaxf(m_[i], rm);
            float corr = __expf(m_[i] - mnew);
            float p0 = __expf(s[i][0] - mnew);
            float p1 = __expf(s[i][1] - mnew);
            float p2 = __expf(s[i][2] - mnew);
            float p3 = __expf(s[i][3] - mnew);
            float rs = p0 + p1 + p2 + p3;
#pragma unroll
            for (int w = 1; w < 16; w <<= 1)
                rs += __shfl_xor_sync(0xffffffffu, rs, w);
            l_[i] = l_[i] * corr + rs;
            m_[i] = mnew;
#pragma unroll
            for (int jj = 0; jj < 8; jj++) o_[i][jj] *= corr;
            float* pr = &Ps[(ty * 4 + i) * APPAD + tx * 4];
            pr[0] = p0; pr[1] = p1; pr[2] = p2; pr[3] = p3;
        }
        __syncwarp();

        for (int j = 0; j < 64; j++) {
            float4 v0 = *(const float4*)&Vs[j * AQPAD + tx * 8];
            float4 v1 = *(const float4*)&Vs[j * AQPAD + tx * 8 + 4];
#pragma unroll
            for (int i = 0; i < 4; i++) {
                float p = Ps[(ty * 4 + i) * APPAD + j];
                o_[i][0] += p * v0.x; o_[i][1] += p * v0.y;
                o_[i][2] += p * v0.z; o_[i][3] += p * v0.w;
                o_[i][4] += p * v1.x; o_[i][5] += p * v1.y;
                o_[i][6] += p * v1.z; o_[i][7] += p * v1.w;
            }
        }
        __syncwarp();
    }

    // Epilogue: normalize, round to tf32 bits (wo GEMM consumes directly)
#pragma unroll
    for (int i = 0; i < 4; i++) {
        float inv = 1.0f / l_[i];
        float* op = o + (size_t)(b * LL + qt * 64 + ty * 4 + i) * DIMS + h * HD + tx * 8;
        float r[8];
#pragma unroll
        for (int jj = 0; jj < 8; jj++)
            r[jj] = __uint_as_float(f2tf(o_[i][jj] * inv));
        *(float4*)(op + 0) = make_float4(r[0], r[1], r[2], r[3]);
        *(float4*)(op + 4) = make_float4(r[4], r[5], r[6], r[7]);
    }
}

// ---------------------------------------------------------------------------
extern "C" void kernel_launch(void* const* d_in, const int* in_sizes, int n_in,
                              void* d_out, int out_size)
{
    const float* x  = (const float*)d_in[0];
    const float* wq = (const float*)d_in[1];
    const float* wk = (const float*)d_in[2];
    const float* wv = (const float*)d_in[3];
    const float* wo = (const float*)d_in[4];
    const float* fr = (const float*)d_in[5];
    float* out = (float*)d_out;

    float *qp, *kp, *vp, *ap, *xt, *wqt, *wkt, *wvt, *wot;
    cudaGetSymbolAddress((void**)&qp,  g_q);
    cudaGetSymbolAddress((void**)&kp,  g_k);
    cudaGetSymbolAddress((void**)&vp,  g_v);
    cudaGetSymbolAddress((void**)&ap,  g_attn);
    cudaGetSymbolAddress((void**)&xt,  g_xt);
    cudaGetSymbolAddress((void**)&wqt, g_wqt);
    cudaGetSymbolAddress((void**)&wkt, g_wkt);
    cudaGetSymbolAddress((void**)&wvt, g_wvt);
    cudaGetSymbolAddress((void**)&wot, g_wot);

    cudaFuncSetAttribute(gemm_tc, cudaFuncAttributeMaxDynamicSharedMemorySize, GEMM_SMEM);
    cudaFuncSetAttribute(attn_kernel, cudaFuncAttributeMaxDynamicSharedMemorySize, ATTN_SMEM);

    // tf32 pre-convert
    const int n_big = MM * DIMS / 4;     // also DIMS*DIMS/4
    const int n_kv  = DKV * DIMS / 4;
    cvt_tf32<<<(n_big + 255) / 256, 256>>>(x,  xt,  n_big);
    cvt_tf32<<<(n_big + 255) / 256, 256>>>(wq, wqt, n_big);
    cvt_tf32<<<(n_kv  + 255) / 256, 256>>>(wk, wkt, n_kv);
    cvt_tf32<<<(n_kv  + 255) / 256, 256>>>(wv, wvt, n_kv);
    cvt_tf32<<<(n_big + 255) / 256, 256>>>(wo, wot, n_big);

    // Projections
    gemm_tc<<<dim3(DIMS / 128, MM / 128, 1), 256, GEMM_SMEM>>>(xt, wqt, wqt, qp, qp, DIMS, DIMS);
    gemm_tc<<<dim3(DKV  / 128, MM / 128, 2), 256, GEMM_SMEM>>>(xt, wkt, wvt, kp, vp, DKV, DIMS);

    int qpairs = MM * NH  * (HD / 2);
    int kpairs = MM * NKV * (HD / 2);
    rope_kernel<<<(qpairs + 255) / 256, 256>>>(qp, fr, NH , qpairs);
    rope_kernel<<<(kpairs + 255) / 256, 256>>>(kp, fr, NKV, kpairs);

    dim3 gA(LL / 64, NH, BB);
    attn_kernel<<<gA, 256, ATTN_SMEM>>>(qp, kp, vp, ap);

    // Output projection (ap already tf32-rounded)
    gemm_tc<<<dim3(DIMS / 128, MM / 128, 1), 256, GEMM_SMEM>>>(ap, wot, wot, out, out, DIMS, DIMS);
}

// round 8
// speedup vs baseline: 3.4946x; 1.3733x over previous
#include <cuda_runtime.h>
#include <cuda_fp16.h>
#include <math.h>
#include <stdint.h>

#define BB   4
#define LL   1024
#define MM   (BB*LL)        // 4096 tokens
#define DIMS 4096
#define NH   32
#define NKV  8
#define HD   128
#define DKV  (NKV*HD)       // 1024

// Scratch (no cudaMalloc allowed) ------------------------------------------
__device__ float g_q[(size_t)MM*DIMS];
__device__ float g_k[(size_t)MM*DKV];
__device__ float g_v[(size_t)MM*DKV];
// fp16 pre-converted operands
__device__ __half g_xh [(size_t)MM*DIMS];
__device__ __half g_wqh[(size_t)DIMS*DIMS];
__device__ __half g_wkh[(size_t)DKV*DIMS];
__device__ __half g_wvh[(size_t)DKV*DIMS];
__device__ __half g_woh[(size_t)DIMS*DIMS];
__device__ __half g_ah [(size_t)MM*DIMS];   // attention out (half, feeds wo GEMM)

// ======================= helpers ===========================================
__device__ __forceinline__ uint32_t smem_u32(const void* p) {
    uint32_t a;
    asm("{ .reg .u64 t; cvta.to.shared.u64 t, %1; cvt.u32.u64 %0, t; }"
        : "=r"(a) : "l"(p));
    return a;
}

// -------- fp32 -> fp16 pre-convert pass ------------------------------------
__global__ void cvt_h(const float* __restrict__ in, __half* __restrict__ out, int n4)
{
    int i = blockIdx.x * blockDim.x + threadIdx.x;
    if (i >= n4) return;
    float4 v = ((const float4*)in)[i];
    __half2 h0 = __floats2half2_rn(v.x, v.y);
    __half2 h1 = __floats2half2_rn(v.z, v.w);
    ((uint2*)out)[i] = make_uint2(*(uint32_t*)&h0, *(uint32_t*)&h1);
}

// ============ fp16 mma.sync GEMM, 4-stage cp.async pipeline ================
// C[M,N](fp32) = A[M,K](f16) * B[N,K](f16)^T
// Block tile 128x128, K-tile 32 halves (64B/row), smem row pitch 80B:
// ldmatrix row-phases hit banks {0,20,8,28,16,4,24,12} -> conflict-free.
// Warp layout 4(M) x 2(N), 32x64 per warp, m16n8k16 frags via ldmatrix.x4.
#define GTK 32
#define HROW 80
#define HTILE_B (128 * HROW)        // 10240 per operand
#define STAGE_B (2 * HTILE_B)       // 20480
#define NSTAGE  4
#define GEMM_SMEM (NSTAGE * STAGE_B)  // 81920 -> 2 CTAs/SM

__global__ __launch_bounds__(256, 2) void gemm_h(const __half* __restrict__ A,
                                                 const __half* __restrict__ B0_,
                                                 const __half* __restrict__ B1_,
                                                 float* __restrict__ C0_,
                                                 float* __restrict__ C1_,
                                                 int N, int K)
{
    extern __shared__ char sm[];
    const uint32_t smb = smem_u32(sm);
    const int tid  = threadIdx.x;
    const int lane = tid & 31;
    const int warp = tid >> 5;          // 8 warps
    const int wm   = warp >> 1;         // 0..3 (M)
    const int wn   = warp & 1;          // 0..1 (N)
    const int lq   = lane >> 2;         // 0..7
    const int lt   = lane & 3;          // 0..3
    const int lrow = lane & 7;          // ldmatrix row-in-group
    const int lsel = lane >> 3;         // ldmatrix matrix id 0..3
    const __half* Bm = blockIdx.z ? B1_ : B0_;
    float*        C  = blockIdx.z ? C1_ : C0_;
    const int bm = blockIdx.y * 128;
    const int bn = blockIdx.x * 128;

    // cp.async: each tile 128 rows x 4 16B-chunks = 512 chunks -> 2/thread/operand
    const __half* aSrc[2]; const __half* bSrc[2]; uint32_t dOff[2];
#pragma unroll
    for (int j = 0; j < 2; j++) {
        int idx = tid + j * 256;            // 0..511
        int r = idx >> 2, c = idx & 3;
        aSrc[j] = A  + (size_t)(bm + r) * K + c * 8;
        bSrc[j] = Bm + (size_t)(bn + r) * K + c * 8;
        dOff[j] = r * HROW + c * 16;
    }

    // ldmatrix per-thread byte offsets (within a stage buffer)
    // A frag (mt, ks): base + aOff + mt*16*HROW + ks*32
    const uint32_t aOff = (uint32_t)(wm * 32 + (lsel & 1) * 8 + lrow) * HROW
                        + (uint32_t)(lsel >> 1) * 16;
    // B frag pair p covers nt=2p,2p+1: base + HTILE_B + bOff + p*16*HROW + ks*32
    const uint32_t bOff = (uint32_t)(wn * 64 + (lsel >> 1) * 8 + lrow) * HROW
                        + (uint32_t)(lsel & 1) * 16;

    float acc[2][8][4];
#pragma unroll
    for (int mt = 0; mt < 2; mt++)
#pragma unroll
        for (int nt = 0; nt < 8; nt++)
#pragma unroll
            for (int i = 0; i < 4; i++) acc[mt][nt][i] = 0.0f;

    const int KT = K / GTK;

    // Prologue: stages 0..2
#pragma unroll
    for (int st = 0; st < NSTAGE - 1; st++) {
        const uint32_t sb = smb + st * STAGE_B;
        const size_t ko = (size_t)st * GTK;
#pragma unroll
        for (int j = 0; j < 2; j++) {
            asm volatile("cp.async.cg.shared.global [%0], [%1], 16;"
                         :: "r"(sb + dOff[j]), "l"(aSrc[j] + ko) : "memory");
            asm volatile("cp.async.cg.shared.global [%0], [%1], 16;"
                         :: "r"(sb + HTILE_B + dOff[j]), "l"(bSrc[j] + ko) : "memory");
        }
        asm volatile("cp.async.commit_group;" ::: "memory");
    }

    for (int kt = 0; kt < KT; kt++) {
        asm volatile("cp.async.wait_group %0;" :: "n"(NSTAGE - 2) : "memory");
        __syncthreads();

        const uint32_t bufA = smb + (kt & (NSTAGE - 1)) * STAGE_B;
        const uint32_t bufB = bufA + HTILE_B;

#pragma unroll
        for (int ks = 0; ks < 2; ks++) {
            uint32_t a[2][4], b[4][4];
#pragma unroll
            for (int mt = 0; mt < 2; mt++)
                asm volatile("ldmatrix.sync.aligned.m8n8.x4.shared.b16 {%0,%1,%2,%3}, [%4];"
                             : "=r"(a[mt][0]), "=r"(a[mt][1]), "=r"(a[mt][2]), "=r"(a[mt][3])
                             : "r"(bufA + aOff + mt * (16 * HROW) + ks * 32));
#pragma unroll
            for (int p = 0; p < 4; p++)
                asm volatile("ldmatrix.sync.aligned.m8n8.x4.shared.b16 {%0,%1,%2,%3}, [%4];"
                             : "=r"(b[p][0]), "=r"(b[p][1]), "=r"(b[p][2]), "=r"(b[p][3])
                             : "r"(bufB + bOff + p * (16 * HROW) + ks * 32));
#pragma unroll
            for (int mt = 0; mt < 2; mt++)
#pragma unroll
                for (int nt = 0; nt < 8; nt++) {
                    const uint32_t bb0 = b[nt >> 1][(nt & 1) * 2];
                    const uint32_t bb1 = b[nt >> 1][(nt & 1) * 2 + 1];
                    asm volatile(
                        "mma.sync.aligned.m16n8k16.row.col.f32.f16.f16.f32 "
                        "{%0,%1,%2,%3}, {%4,%5,%6,%7}, {%8,%9}, {%0,%1,%2,%3};"
                        : "+f"(acc[mt][nt][0]), "+f"(acc[mt][nt][1]),
                          "+f"(acc[mt][nt][2]), "+f"(acc[mt][nt][3])
                        : "r"(a[mt][0]), "r"(a[mt][1]), "r"(a[mt][2]), "r"(a[mt][3]),
                          "r"(bb0), "r"(bb1));
                }
        }

        // Prefetch kt+3 (clamped; redundant tail loads land in unused buffers)
        {
            const int kp = (kt + NSTAGE - 1 < KT) ? (kt + NSTAGE - 1) : (KT - 1);
            const uint32_t sb = smb + ((kt + NSTAGE - 1) & (NSTAGE - 1)) * STAGE_B;
            const size_t ko = (size_t)kp * GTK;
            __syncthreads();   // all warps done reading buffer being overwritten
#pragma unroll
            for (int j = 0; j < 2; j++) {
                asm volatile("cp.async.cg.shared.global [%0], [%1], 16;"
                             :: "r"(sb + dOff[j]), "l"(aSrc[j] + ko) : "memory");
                asm volatile("cp.async.cg.shared.global [%0], [%1], 16;"
                             :: "r"(sb + HTILE_B + dOff[j]), "l"(bSrc[j] + ko) : "memory");
            }
            asm volatile("cp.async.commit_group;" ::: "memory");
        }
    }

    // Epilogue (c-frag layout identical to tf32 case)
#pragma unroll
    for (int mt = 0; mt < 2; mt++) {
        int r0 = bm + wm * 32 + mt * 16 + lq;
#pragma unroll
        for (int nt = 0; nt < 8; nt++) {
            int c = bn + wn * 64 + nt * 8 + 2 * lt;
            *(float2*)(C + (size_t)r0 * N + c)       = make_float2(acc[mt][nt][0], acc[mt][nt][1]);
            *(float2*)(C + (size_t)(r0 + 8) * N + c) = make_float2(acc[mt][nt][2], acc[mt][nt][3]);
        }
    }
}

// ---------------- RoPE (interleaved pairs) ---------------------------------
__global__ void rope_kernel(float* __restrict__ t, const float* __restrict__ freqs,
                            int nheads, int total_pairs)
{
    int p = blockIdx.x * blockDim.x + threadIdx.x;
    if (p >= total_pairs) return;
    int d2 = p & 63;                        // HD/2 = 64
    int l  = (p / (64 * nheads)) % LL;
    float f = freqs[l * 64 + d2];
    float c = cosf(f), s = sinf(f);
    float a = t[2 * p], b = t[2 * p + 1];
    t[2 * p]     = a * c - b * s;
    t[2 * p + 1] = a * s + b * c;
}

// ---------------- Flash attention (fp32, causal) ---------------------------
#define AQPAD 132
#define APPAD 68
#define ATTN_SMEM ((3 * 64 * AQPAD + 64 * APPAD) * 4)   // 118784 B

__global__ __launch_bounds__(256) void attn_kernel(const float* __restrict__ q,
                                                   const float* __restrict__ k,
                                                   const float* __restrict__ v,
                                                   __half* __restrict__ o)
{
    extern __shared__ float smf[];
    float* Qs = smf;
    float* Ks = Qs + 64 * AQPAD;
    float* Vs = Ks + 64 * AQPAD;
    float* Ps = Vs + 64 * AQPAD;

    const int qt = blockIdx.x;
    const int h  = blockIdx.y;
    const int b  = blockIdx.z;
    const int tid = threadIdx.x;
    const int tx = tid & 15;
    const int ty = tid >> 4;
    const float scale = 0.088388347648318447f;   // 1/sqrt(128)

    const float* qb = q + ((size_t)(b * LL + qt * 64) * NH + h) * HD;
    for (int i = tid; i < 64 * 32; i += 256) {
        int r = i >> 5, c = (i & 31) * 4;
        float4 u = *(const float4*)(qb + (size_t)r * (NH * HD) + c);
        Qs[r * AQPAD + c + 0] = u.x * scale;
        Qs[r * AQPAD + c + 1] = u.y * scale;
        Qs[r * AQPAD + c + 2] = u.z * scale;
        Qs[r * AQPAD + c + 3] = u.w * scale;
    }

    float m_[4], l_[4], o_[4][8];
#pragma unroll
    for (int i = 0; i < 4; i++) {
        m_[i] = -1e30f; l_[i] = 0.0f;
#pragma unroll
        for (int j = 0; j < 8; j++) o_[i][j] = 0.0f;
    }

    const int kvh = h >> 2;
    const float* kb = k + ((size_t)(b * LL) * NKV + kvh) * HD;
    const float* vb = v + ((size_t)(b * LL) * NKV + kvh) * HD;

    for (int kt = 0; kt <= qt; kt++) {
        __syncthreads();
        for (int i = tid; i < 64 * 32; i += 256) {
            int r = i >> 5, c = (i & 31) * 4;
            size_t goff = (size_t)(kt * 64 + r) * DKV + c;
            *(float4*)&Ks[r * AQPAD + c] = *(const float4*)(kb + goff);
            *(float4*)&Vs[r * AQPAD + c] = *(const float4*)(vb + goff);
        }
        __syncthreads();

        float s[4][4];
#pragma unroll
        for (int i = 0; i < 4; i++)
#pragma unroll
            for (int j = 0; j < 4; j++) s[i][j] = 0.0f;

        for (int d = 0; d < HD; d += 4) {
            float4 a0 = *(const float4*)&Qs[(ty * 4 + 0) * AQPAD + d];
            float4 a1 = *(const float4*)&Qs[(ty * 4 + 1) * AQPAD + d];
            float4 a2 = *(const float4*)&Qs[(ty * 4 + 2) * AQPAD + d];
            float4 a3 = *(const float4*)&Qs[(ty * 4 + 3) * AQPAD + d];
            float4 b0 = *(const float4*)&Ks[(tx * 4 + 0) * AQPAD + d];
            float4 b1 = *(const float4*)&Ks[(tx * 4 + 1) * AQPAD + d];
            float4 b2 = *(const float4*)&Ks[(tx * 4 + 2) * AQPAD + d];
            float4 b3 = *(const float4*)&Ks[(tx * 4 + 3) * AQPAD + d];
            float a[4][4] = {{a0.x,a0.y,a0.z,a0.w},{a1.x,a1.y,a1.z,a1.w},
                             {a2.x,a2.y,a2.z,a2.w},{a3.x,a3.y,a3.z,a3.w}};
            float bq[4][4] = {{b0.x,b0.y,b0.z,b0.w},{b1.x,b1.y,b1.z,b1.w},
                              {b2.x,b2.y,b2.z,b2.w},{b3.x,b3.y,b3.z,b3.w}};
#pragma unroll
            for (int i = 0; i < 4; i++)
#pragma unroll
                for (int j = 0; j < 4; j++)
#pragma unroll
                    for (int u = 0; u < 4; u++)
                        s[i][j] += a[i][u] * bq[j][u];
        }

        if (kt == qt) {
#pragma unroll
            for (int i = 0; i < 4; i++)
#pragma unroll
                for (int j = 0; j < 4; j++)
                    if (tx * 4 + j > ty * 4 + i) s[i][j] = -1e30f;
        }

#pragma unroll
        for (int i = 0; i < 4; i++) {
            float rm = fmaxf(fmaxf(s[i][0], s[i][1]), fmaxf(s[i][2], s[i][3]));
#pragma unroll
            for (int w = 1; w < 16; w <<= 1)
                rm = fmaxf(rm, __shfl_xor_sync(0xffffffffu, rm, w));
            float mnew = fmaxf(m_[i], rm);
            float corr = __expf(m_[i] - mnew);
            float p0 = __expf(s[i][0] - mnew);
            float p1 = __expf(s[i][1] - mnew);
            float p2 = __expf(s[i][2] - mnew);
            float p3 = __expf(s[i][3] - mnew);
            float rs = p0 + p1 + p2 + p3;
#pragma unroll
            for (int w = 1; w < 16; w <<= 1)
                rs += __shfl_xor_sync(0xffffffffu, rs, w);
            l_[i] = l_[i] * corr + rs;
            m_[i] = mnew;
#pragma unroll
            for (int jj = 0; jj < 8; jj++) o_[i][jj] *= corr;
            float* pr = &Ps[(ty * 4 + i) * APPAD + tx * 4];
            pr[0] = p0; pr[1] = p1; pr[2] = p2; pr[3] = p3;
        }
        __syncwarp();

        for (int j = 0; j < 64; j++) {
            float4 v0 = *(const float4*)&Vs[j * AQPAD + tx * 8];
            float4 v1 = *(const float4*)&Vs[j * AQPAD + tx * 8 + 4];
#pragma unroll
            for (int i = 0; i < 4; i++) {
                float p = Ps[(ty * 4 + i) * APPAD + j];
                o_[i][0] += p * v0.x; o_[i][1] += p * v0.y;
                o_[i][2] += p * v0.z; o_[i][3] += p * v0.w;
                o_[i][4] += p * v1.x; o_[i][5] += p * v1.y;
                o_[i][6] += p * v1.z; o_[i][7] += p * v1.w;
            }
        }
        __syncwarp();
    }

    // Epilogue: normalize, convert to half (wo GEMM consumes directly)
#pragma unroll
    for (int i = 0; i < 4; i++) {
        float inv = 1.0f / l_[i];
        __half* op = o + (size_t)(b * LL + qt * 64 + ty * 4 + i) * DIMS + h * HD + tx * 8;
        __half2 h0 = __floats2half2_rn(o_[i][0] * inv, o_[i][1] * inv);
        __half2 h1 = __floats2half2_rn(o_[i][2] * inv, o_[i][3] * inv);
        __half2 h2 = __floats2half2_rn(o_[i][4] * inv, o_[i][5] * inv);
        __half2 h3 = __floats2half2_rn(o_[i][6] * inv, o_[i][7] * inv);
        *(uint4*)op = make_uint4(*(uint32_t*)&h0, *(uint32_t*)&h1,
                                 *(uint32_t*)&h2, *(uint32_t*)&h3);
    }
}

// ---------------------------------------------------------------------------
extern "C" void kernel_launch(void* const* d_in, const int* in_sizes, int n_in,
                              void* d_out, int out_size)
{
    const float* x  = (const float*)d_in[0];
    const float* wq = (const float*)d_in[1];
    const float* wk = (const float*)d_in[2];
    const float* wv = (const float*)d_in[3];
    const float* wo = (const float*)d_in[4];
    const float* fr = (const float*)d_in[5];
    float* out = (float*)d_out;

    float *qp, *kp, *vp;
    __half *xh, *wqh, *wkh, *wvh, *woh, *ah;
    cudaGetSymbolAddress((void**)&qp,  g_q);
    cudaGetSymbolAddress((void**)&kp,  g_k);
    cudaGetSymbolAddress((void**)&vp,  g_v);
    cudaGetSymbolAddress((void**)&xh,  g_xh);
    cudaGetSymbolAddress((void**)&wqh, g_wqh);
    cudaGetSymbolAddress((void**)&wkh, g_wkh);
    cudaGetSymbolAddress((void**)&wvh, g_wvh);
    cudaGetSymbolAddress((void**)&woh, g_woh);
    cudaGetSymbolAddress((void**)&ah,  g_ah);

    cudaFuncSetAttribute(gemm_h, cudaFuncAttributeMaxDynamicSharedMemorySize, GEMM_SMEM);
    cudaFuncSetAttribute(attn_kernel, cudaFuncAttributeMaxDynamicSharedMemorySize, ATTN_SMEM);

    // fp16 pre-convert
    const int n_big = MM * DIMS / 4;     // also DIMS*DIMS/4
    const int n_kv  = DKV * DIMS / 4;
    cvt_h<<<(n_big + 255) / 256, 256>>>(x,  xh,  n_big);
    cvt_h<<<(n_big + 255) / 256, 256>>>(wq, wqh, n_big);
    cvt_h<<<(n_kv  + 255) / 256, 256>>>(wk, wkh, n_kv);
    cvt_h<<<(n_kv  + 255) / 256, 256>>>(wv, wvh, n_kv);
    cvt_h<<<(n_big + 255) / 256, 256>>>(wo, woh, n_big);

    // Projections
    gemm_h<<<dim3(DIMS / 128, MM / 128, 1), 256, GEMM_SMEM>>>(xh, wqh, wqh, qp, qp, DIMS, DIMS);
    gemm_h<<<dim3(DKV  / 128, MM / 128, 2), 256, GEMM_SMEM>>>(xh, wkh, wvh, kp, vp, DKV, DIMS);

    int qpairs = MM * NH  * (HD / 2);
    int kpairs = MM * NKV * (HD / 2);
    rope_kernel<<<(qpairs + 255) / 256, 256>>>(qp, fr, NH , qpairs);
    rope_kernel<<<(kpairs + 255) / 256, 256>>>(kp, fr, NKV, kpairs);

    dim3 gA(LL / 64, NH, BB);
    attn_kernel<<<gA, 256, ATTN_SMEM>>>(qp, kp, vp, ah);

    // Output projection (attention out already half)
    gemm_h<<<dim3(DIMS / 128, MM / 128, 1), 256, GEMM_SMEM>>>(ah, woh, woh, out, out, DIMS, DIMS);
}

// round 9
// speedup vs baseline: 7.0655x; 2.0218x over previous
#include <cuda_runtime.h>
#include <cuda_fp16.h>
#include <math.h>
#include <stdint.h>

#define BB   4
#define LL   1024
#define MM   (BB*LL)        // 4096 tokens
#define DIMS 4096
#define NH   32
#define NKV  8
#define HD   128
#define DKV  (NKV*HD)       // 1024

// Scratch (no cudaMalloc allowed) ------------------------------------------
__device__ float g_q[(size_t)MM*DIMS];
__device__ float g_k[(size_t)MM*DKV];
__device__ float g_v[(size_t)MM*DKV];
// fp16 pre-converted operands
__device__ __half g_xh [(size_t)MM*DIMS];
__device__ __half g_wqh[(size_t)DIMS*DIMS];
__device__ __half g_wkh[(size_t)DKV*DIMS];
__device__ __half g_wvh[(size_t)DKV*DIMS];
__device__ __half g_woh[(size_t)DIMS*DIMS];
__device__ __half g_ah [(size_t)MM*DIMS];   // attention out (half, feeds wo GEMM)

// ======================= helpers ===========================================
__device__ __forceinline__ uint32_t smem_u32(const void* p) {
    uint32_t a;
    asm("{ .reg .u64 t; cvta.to.shared.u64 t, %1; cvt.u32.u64 %0, t; }"
        : "=r"(a) : "l"(p));
    return a;
}
__device__ __forceinline__ void ldx4(uint32_t* r, uint32_t addr) {
    asm volatile("ldmatrix.sync.aligned.m8n8.x4.shared.b16 {%0,%1,%2,%3}, [%4];"
                 : "=r"(r[0]), "=r"(r[1]), "=r"(r[2]), "=r"(r[3]) : "r"(addr));
}
__device__ __forceinline__ void ldx4t(uint32_t* r, uint32_t addr) {
    asm volatile("ldmatrix.sync.aligned.m8n8.x4.trans.shared.b16 {%0,%1,%2,%3}, [%4];"
                 : "=r"(r[0]), "=r"(r[1]), "=r"(r[2]), "=r"(r[3]) : "r"(addr));
}
__device__ __forceinline__ void mma16816(float* c, const uint32_t* a,
                                         uint32_t b0, uint32_t b1) {
    asm volatile(
        "mma.sync.aligned.m16n8k16.row.col.f32.f16.f16.f32 "
        "{%0,%1,%2,%3}, {%4,%5,%6,%7}, {%8,%9}, {%0,%1,%2,%3};"
        : "+f"(c[0]), "+f"(c[1]), "+f"(c[2]), "+f"(c[3])
        : "r"(a[0]), "r"(a[1]), "r"(a[2]), "r"(a[3]), "r"(b0), "r"(b1));
}

// -------- fp32 -> fp16 pre-convert pass ------------------------------------
__global__ void cvt_h(const float* __restrict__ in, __half* __restrict__ out, int n4)
{
    int i = blockIdx.x * blockDim.x + threadIdx.x;
    if (i >= n4) return;
    float4 v = ((const float4*)in)[i];
    __half2 h0 = __floats2half2_rn(v.x, v.y);
    __half2 h1 = __floats2half2_rn(v.z, v.w);
    ((uint2*)out)[i] = make_uint2(*(uint32_t*)&h0, *(uint32_t*)&h1);
}

// ============ fp16 mma.sync GEMM, 4-stage cp.async pipeline ================
#define GTK 32
#define HROW 80
#define HTILE_B (128 * HROW)
#define STAGE_B (2 * HTILE_B)
#define NSTAGE  4
#define GEMM_SMEM (NSTAGE * STAGE_B)  // 81920 -> 2 CTAs/SM

__global__ __launch_bounds__(256, 2) void gemm_h(const __half* __restrict__ A,
                                                 const __half* __restrict__ B0_,
                                                 const __half* __restrict__ B1_,
                                                 float* __restrict__ C0_,
                                                 float* __restrict__ C1_,
                                                 int N, int K)
{
    extern __shared__ char sm[];
    const uint32_t smb = smem_u32(sm);
    const int tid  = threadIdx.x;
    const int lane = tid & 31;
    const int warp = tid >> 5;
    const int wm   = warp >> 1;
    const int wn   = warp & 1;
    const int lq   = lane >> 2;
    const int lt   = lane & 3;
    const int lrow = lane & 7;
    const int lsel = lane >> 3;
    const __half* Bm = blockIdx.z ? B1_ : B0_;
    float*        C  = blockIdx.z ? C1_ : C0_;
    const int bm = blockIdx.y * 128;
    const int bn = blockIdx.x * 128;

    const __half* aSrc[2]; const __half* bSrc[2]; uint32_t dOff[2];
#pragma unroll
    for (int j = 0; j < 2; j++) {
        int idx = tid + j * 256;
        int r = idx >> 2, c = idx & 3;
        aSrc[j] = A  + (size_t)(bm + r) * K + c * 8;
        bSrc[j] = Bm + (size_t)(bn + r) * K + c * 8;
        dOff[j] = r * HROW + c * 16;
    }

    const uint32_t aOff = (uint32_t)(wm * 32 + (lsel & 1) * 8 + lrow) * HROW
                        + (uint32_t)(lsel >> 1) * 16;
    const uint32_t bOff = (uint32_t)(wn * 64 + (lsel >> 1) * 8 + lrow) * HROW
                        + (uint32_t)(lsel & 1) * 16;

    float acc[2][8][4];
#pragma unroll
    for (int mt = 0; mt < 2; mt++)
#pragma unroll
        for (int nt = 0; nt < 8; nt++)
#pragma unroll
            for (int i = 0; i < 4; i++) acc[mt][nt][i] = 0.0f;

    const int KT = K / GTK;

#pragma unroll
    for (int st = 0; st < NSTAGE - 1; st++) {
        const uint32_t sb = smb + st * STAGE_B;
        const size_t ko = (size_t)st * GTK;
#pragma unroll
        for (int j = 0; j < 2; j++) {
            asm volatile("cp.async.cg.shared.global [%0], [%1], 16;"
                         :: "r"(sb + dOff[j]), "l"(aSrc[j] + ko) : "memory");
            asm volatile("cp.async.cg.shared.global [%0], [%1], 16;"
                         :: "r"(sb + HTILE_B + dOff[j]), "l"(bSrc[j] + ko) : "memory");
        }
        asm volatile("cp.async.commit_group;" ::: "memory");
    }

    for (int kt = 0; kt < KT; kt++) {
        asm volatile("cp.async.wait_group %0;" :: "n"(NSTAGE - 2) : "memory");
        __syncthreads();

        const uint32_t bufA = smb + (kt & (NSTAGE - 1)) * STAGE_B;
        const uint32_t bufB = bufA + HTILE_B;

#pragma unroll
        for (int ks = 0; ks < 2; ks++) {
            uint32_t a[2][4], b[4][4];
#pragma unroll
            for (int mt = 0; mt < 2; mt++)
                ldx4(a[mt], bufA + aOff + mt * (16 * HROW) + ks * 32);
#pragma unroll
            for (int p = 0; p < 4; p++)
                ldx4(b[p], bufB + bOff + p * (16 * HROW) + ks * 32);
#pragma unroll
            for (int mt = 0; mt < 2; mt++)
#pragma unroll
                for (int nt = 0; nt < 8; nt++)
                    mma16816(acc[mt][nt], a[mt],
                             b[nt >> 1][(nt & 1) * 2], b[nt >> 1][(nt & 1) * 2 + 1]);
        }

        {
            const int kp = (kt + NSTAGE - 1 < KT) ? (kt + NSTAGE - 1) : (KT - 1);
            const uint32_t sb = smb + ((kt + NSTAGE - 1) & (NSTAGE - 1)) * STAGE_B;
            const size_t ko = (size_t)kp * GTK;
            __syncthreads();
#pragma unroll
            for (int j = 0; j < 2; j++) {
                asm volatile("cp.async.cg.shared.global [%0], [%1], 16;"
                             :: "r"(sb + dOff[j]), "l"(aSrc[j] + ko) : "memory");
                asm volatile("cp.async.cg.shared.global [%0], [%1], 16;"
                             :: "r"(sb + HTILE_B + dOff[j]), "l"(bSrc[j] + ko) : "memory");
            }
            asm volatile("cp.async.commit_group;" ::: "memory");
        }
    }

#pragma unroll
    for (int mt = 0; mt < 2; mt++) {
        int r0 = bm + wm * 32 + mt * 16 + lq;
#pragma unroll
        for (int nt = 0; nt < 8; nt++) {
            int c = bn + wn * 64 + nt * 8 + 2 * lt;
            *(float2*)(C + (size_t)r0 * N + c)       = make_float2(acc[mt][nt][0], acc[mt][nt][1]);
            *(float2*)(C + (size_t)(r0 + 8) * N + c) = make_float2(acc[mt][nt][2], acc[mt][nt][3]);
        }
    }
}

// ---------------- RoPE (interleaved pairs) ---------------------------------
__global__ void rope_kernel(float* __restrict__ t, const float* __restrict__ freqs,
                            int nheads, int total_pairs)
{
    int p = blockIdx.x * blockDim.x + threadIdx.x;
    if (p >= total_pairs) return;
    int d2 = p & 63;
    int l  = (p / (64 * nheads)) % LL;
    float f = freqs[l * 64 + d2];
    float c = cosf(f), s = sinf(f);
    float a = t[2 * p], b = t[2 * p + 1];
    t[2 * p]     = a * c - b * s;
    t[2 * p + 1] = a * s + b * c;
}

// ======== MMA flash attention (fp16 split-precision, causal) ===============
// CTA: 128 q-rows x 1 head. 8 warps x 16 rows. kv-tiles of 64.
// Q/K/V split into (hi, lo) fp16 pairs; S = QhKh + QhKl + QlKh;
// O += PhVh + PhVl + PlVh. Accum fp32. Pitch 272B -> conflict-free ldmatrix.
#define PIT   272
#define AQHI  0
#define AQLO  34816                 // 128*272
#define AKHI  69632
#define AKLO  (AKHI + 17408)        // 64*272
#define AVHI  (AKHI + 2*17408)
#define AVLO  (AKHI + 3*17408)
#define ATTN_SMEM (AKHI + 4*17408)  // 139264 B

__global__ __launch_bounds__(256, 1) void attn_mma(const float* __restrict__ q,
                                                   const float* __restrict__ k,
                                                   const float* __restrict__ v,
                                                   __half* __restrict__ o)
{
    extern __shared__ char smx[];
    const uint32_t smb = smem_u32(smx);
    const int tid = threadIdx.x, lane = tid & 31, w = tid >> 5;
    const int lq = lane >> 2, lt = lane & 3, lrow = lane & 7, lsel = lane >> 3;
    const int qt = blockIdx.x, h = blockIdx.y, b = blockIdx.z;
    const int qbase = qt * 128;
    const int kvh = h >> 2;
    const float scale = 0.088388347648318447f;   // 1/sqrt(128)

    // ---- load + scale + split Q tile [128][128] ----
    const float* qg = q + ((size_t)(b * LL + qbase) * NH + h) * HD;
    for (int i = tid; i < 128 * 32; i += 256) {
        int r = i >> 5, c = (i & 31) * 4;
        float4 u = *(const float4*)(qg + (size_t)r * (NH * HD) + c);
        u.x *= scale; u.y *= scale; u.z *= scale; u.w *= scale;
        __half hx = __float2half_rn(u.x), hy = __float2half_rn(u.y);
        __half hz = __float2half_rn(u.z), hw = __float2half_rn(u.w);
        __half2 hi0 = __halves2half2(hx, hy), hi1 = __halves2half2(hz, hw);
        __half2 lo0 = __floats2half2_rn(u.x - __half2float(hx), u.y - __half2float(hy));
        __half2 lo1 = __floats2half2_rn(u.z - __half2float(hz), u.w - __half2float(hw));
        uint32_t off = (uint32_t)r * PIT + c * 2;
        *(uint2*)(smx + AQHI + off) = make_uint2(*(uint32_t*)&hi0, *(uint32_t*)&hi1);
        *(uint2*)(smx + AQLO + off) = make_uint2(*(uint32_t*)&lo0, *(uint32_t*)&lo1);
    }

    float oacc[16][4];
#pragma unroll
    for (int j = 0; j < 16; j++)
#pragma unroll
        for (int i = 0; i < 4; i++) oacc[j][i] = 0.0f;
    float m0 = -1e30f, m1 = -1e30f, l0 = 0.0f, l1 = 0.0f;

    const float* kg = k + ((size_t)(b * LL) * NKV + kvh) * HD;
    const float* vg = v + ((size_t)(b * LL) * NKV + kvh) * HD;

    // per-thread ldmatrix base offsets
    const uint32_t qOff = (uint32_t)(w * 16 + (lsel & 1) * 8 + lrow) * PIT
                        + (uint32_t)(lsel >> 1) * 16;
    const uint32_t kOff = (uint32_t)((lsel >> 1) * 8 + lrow) * PIT
                        + (uint32_t)(lsel & 1) * 16;
    const uint32_t vRow = (uint32_t)((lsel & 1) * 8 + lrow) * PIT
                        + (uint32_t)(lsel >> 1) * 16;

    const int ntiles = 2 * qt + 2;
    for (int kt = 0; kt < ntiles; kt++) {
        __syncthreads();   // protect smem from prior reads (and Q store on kt=0)
        // ---- load + split K,V tile [64][128] ----
        for (int i = tid; i < 64 * 32; i += 256) {
            int r = i >> 5, c = (i & 31) * 4;
            size_t go = (size_t)(kt * 64 + r) * DKV + c;
            float4 uk = *(const float4*)(kg + go);
            float4 uv = *(const float4*)(vg + go);
            uint32_t off = (uint32_t)r * PIT + c * 2;
            {
                __half hx = __float2half_rn(uk.x), hy = __float2half_rn(uk.y);
                __half hz = __float2half_rn(uk.z), hw = __float2half_rn(uk.w);
                __half2 hi0 = __halves2half2(hx, hy), hi1 = __halves2half2(hz, hw);
                __half2 lo0 = __floats2half2_rn(uk.x - __half2float(hx), uk.y - __half2float(hy));
                __half2 lo1 = __floats2half2_rn(uk.z - __half2float(hz), uk.w - __half2float(hw));
                *(uint2*)(smx + AKHI + off) = make_uint2(*(uint32_t*)&hi0, *(uint32_t*)&hi1);
                *(uint2*)(smx + AKLO + off) = make_uint2(*(uint32_t*)&lo0, *(uint32_t*)&lo1);
            }
            {
                __half hx = __float2half_rn(uv.x), hy = __float2half_rn(uv.y);
                __half hz = __float2half_rn(uv.z), hw = __float2half_rn(uv.w);
                __half2 hi0 = __halves2half2(hx, hy), hi1 = __halves2half2(hz, hw);
                __half2 lo0 = __floats2half2_rn(uv.x - __half2float(hx), uv.y - __half2float(hy));
                __half2 lo1 = __floats2half2_rn(uv.z - __half2float(hz), uv.w - __half2float(hw));
                *(uint2*)(smx + AVHI + off) = make_uint2(*(uint32_t*)&hi0, *(uint32_t*)&hi1);
                *(uint2*)(smx + AVLO + off) = make_uint2(*(uint32_t*)&lo0, *(uint32_t*)&lo1);
            }
        }
        __syncthreads();

        // ---- S = Q K^T (split: hh + hl + lh) ----
        float sacc[8][4];
#pragma unroll
        for (int nt = 0; nt < 8; nt++)
#pragma unroll
            for (int i = 0; i < 4; i++) sacc[nt][i] = 0.0f;

#pragma unroll
        for (int c = 0; c < 8; c++) {
            uint32_t qh[4], ql[4];
            ldx4(qh, smb + AQHI + qOff + c * 32);
            ldx4(ql, smb + AQLO + qOff + c * 32);
#pragma unroll
            for (int p = 0; p < 4; p++) {
                uint32_t kh[4], kl[4];
                ldx4(kh, smb + AKHI + kOff + p * (16 * PIT) + c * 32);
                ldx4(kl, smb + AKLO + kOff + p * (16 * PIT) + c * 32);
                mma16816(sacc[2 * p],     qh, kh[0], kh[1]);
                mma16816(sacc[2 * p],     qh, kl[0], kl[1]);
                mma16816(sacc[2 * p],     ql, kh[0], kh[1]);
                mma16816(sacc[2 * p + 1], qh, kh[2], kh[3]);
                mma16816(sacc[2 * p + 1], qh, kl[2], kl[3]);
                mma16816(sacc[2 * p + 1], ql, kh[2], kh[3]);
            }
        }

        // ---- causal mask (only the last two tiles can touch the diagonal) --
        if (kt >= 2 * qt) {
            const int qg0 = qbase + w * 16 + lq;
            const int qg1 = qg0 + 8;
            const int kvb = kt * 64;
#pragma unroll
            for (int nt = 0; nt < 8; nt++) {
                int cv = kvb + nt * 8 + 2 * lt;
                if (cv     > qg0) sacc[nt][0] = -1e30f;
                if (cv + 1 > qg0) sacc[nt][1] = -1e30f;
                if (cv     > qg1) sacc[nt][2] = -1e30f;
                if (cv + 1 > qg1) sacc[nt][3] = -1e30f;
            }
        }

        // ---- online softmax (rows lq and lq+8; 4 lanes per row) ----
        float mx0 = -1e30f, mx1 = -1e30f;
#pragma unroll
        for (int nt = 0; nt < 8; nt++) {
            mx0 = fmaxf(mx0, fmaxf(sacc[nt][0], sacc[nt][1]));
            mx1 = fmaxf(mx1, fmaxf(sacc[nt][2], sacc[nt][3]));
        }
        mx0 = fmaxf(mx0, __shfl_xor_sync(0xffffffffu, mx0, 1));
        mx0 = fmaxf(mx0, __shfl_xor_sync(0xffffffffu, mx0, 2));
        mx1 = fmaxf(mx1, __shfl_xor_sync(0xffffffffu, mx1, 1));
        mx1 = fmaxf(mx1, __shfl_xor_sync(0xffffffffu, mx1, 2));
        float mn0 = fmaxf(m0, mx0), mn1 = fmaxf(m1, mx1);
        float cr0 = __expf(m0 - mn0), cr1 = __expf(m1 - mn1);
        m0 = mn0; m1 = mn1;
        float sum0 = 0.0f, sum1 = 0.0f;
#pragma unroll
        for (int nt = 0; nt < 8; nt++) {
            sacc[nt][0] = __expf(sacc[nt][0] - m0); sum0 += sacc[nt][0];
            sacc[nt][1] = __expf(sacc[nt][1] - m0); sum0 += sacc[nt][1];
            sacc[nt][2] = __expf(sacc[nt][2] - m1); sum1 += sacc[nt][2];
            sacc[nt][3] = __expf(sacc[nt][3] - m1); sum1 += sacc[nt][3];
        }
        sum0 += __shfl_xor_sync(0xffffffffu, sum0, 1);
        sum0 += __shfl_xor_sync(0xffffffffu, sum0, 2);
        sum1 += __shfl_xor_sync(0xffffffffu, sum1, 1);
        sum1 += __shfl_xor_sync(0xffffffffu, sum1, 2);
        l0 = l0 * cr0 + sum0;
        l1 = l1 * cr1 + sum1;
#pragma unroll
        for (int j = 0; j < 16; j++) {
            oacc[j][0] *= cr0; oacc[j][1] *= cr0;
            oacc[j][2] *= cr1; oacc[j][3] *= cr1;
        }

        // ---- O += P V (split: PhVh + PhVl + PlVh) ----
#pragma unroll
        for (int c = 0; c < 4; c++) {
            uint32_t phi[4], plo[4];
#pragma unroll
            for (int u = 0; u < 4; u++) {
                // u: 0=(row0, nt=2c), 1=(row1, nt=2c), 2=(row0, nt=2c+1), 3=(row1, nt=2c+1)
                float pa = sacc[2 * c + (u >> 1)][(u & 1) * 2];
                float pb = sacc[2 * c + (u >> 1)][(u & 1) * 2 + 1];
                __half ha = __float2half_rn(pa), hb = __float2half_rn(pb);
                __half2 hh = __halves2half2(ha, hb);
                __half2 ll = __floats2half2_rn(pa - __half2float(ha), pb - __half2float(hb));
                phi[u] = *(uint32_t*)&hh;
                plo[u] = *(uint32_t*)&ll;
            }
#pragma unroll
            for (int jp = 0; jp < 8; jp++) {
                uint32_t vh[4], vl[4];
                uint32_t va = smb + vRow + c * (16 * PIT) + jp * 32;
                ldx4t(vh, va + AVHI);
                ldx4t(vl, va + AVLO);
                mma16816(oacc[2 * jp],     phi, vh[0], vh[1]);
                mma16816(oacc[2 * jp],     phi, vl[0], vl[1]);
                mma16816(oacc[2 * jp],     plo, vh[0], vh[1]);
                mma16816(oacc[2 * jp + 1], phi, vh[2], vh[3]);
                mma16816(oacc[2 * jp + 1], phi, vl[2], vl[3]);
                mma16816(oacc[2 * jp + 1], plo, vh[2], vh[3]);
            }
        }
    }

    // ---- epilogue: normalize, write half to [token][h*128 + d] ----
    const float i0 = 1.0f / l0, i1 = 1.0f / l1;
    const int row0 = qbase + w * 16 + lq;
    __half* ob0 = o + (size_t)(b * LL + row0) * DIMS + h * HD;
    __half* ob1 = ob0 + (size_t)8 * DIMS;
#pragma unroll
    for (int j = 0; j < 16; j++) {
        int col = j * 8 + 2 * lt;
        __half2 h0 = __floats2half2_rn(oacc[j][0] * i0, oacc[j][1] * i0);
        __half2 h1 = __floats2half2_rn(oacc[j][2] * i1, oacc[j][3] * i1);
        *(uint32_t*)(ob0 + col) = *(uint32_t*)&h0;
        *(uint32_t*)(ob1 + col) = *(uint32_t*)&h1;
    }
}

// ---------------------------------------------------------------------------
extern "C" void kernel_launch(void* const* d_in, const int* in_sizes, int n_in,
                              void* d_out, int out_size)
{
    const float* x  = (const float*)d_in[0];
    const float* wq = (const float*)d_in[1];
    const float* wk = (const float*)d_in[2];
    const float* wv = (const float*)d_in[3];
    const float* wo = (const float*)d_in[4];
    const float* fr = (const float*)d_in[5];
    float* out = (float*)d_out;

    float *qp, *kp, *vp;
    __half *xh, *wqh, *wkh, *wvh, *woh, *ah;
    cudaGetSymbolAddress((void**)&qp,  g_q);
    cudaGetSymbolAddress((void**)&kp,  g_k);
    cudaGetSymbolAddress((void**)&vp,  g_v);
    cudaGetSymbolAddress((void**)&xh,  g_xh);
    cudaGetSymbolAddress((void**)&wqh, g_wqh);
    cudaGetSymbolAddress((void**)&wkh, g_wkh);
    cudaGetSymbolAddress((void**)&wvh, g_wvh);
    cudaGetSymbolAddress((void**)&woh, g_woh);
    cudaGetSymbolAddress((void**)&ah,  g_ah);

    cudaFuncSetAttribute(gemm_h, cudaFuncAttributeMaxDynamicSharedMemorySize, GEMM_SMEM);
    cudaFuncSetAttribute(attn_mma, cudaFuncAttributeMaxDynamicSharedMemorySize, ATTN_SMEM);

    const int n_big = MM * DIMS / 4;
    const int n_kv  = DKV * DIMS / 4;
    cvt_h<<<(n_big + 255) / 256, 256>>>(x,  xh,  n_big);
    cvt_h<<<(n_big + 255) / 256, 256>>>(wq, wqh, n_big);
    cvt_h<<<(n_kv  + 255) / 256, 256>>>(wk, wkh, n_kv);
    cvt_h<<<(n_kv  + 255) / 256, 256>>>(wv, wvh, n_kv);
    cvt_h<<<(n_big + 255) / 256, 256>>>(wo, woh, n_big);

    gemm_h<<<dim3(DIMS / 128, MM / 128, 1), 256, GEMM_SMEM>>>(xh, wqh, wqh, qp, qp, DIMS, DIMS);
    gemm_h<<<dim3(DKV  / 128, MM / 128, 2), 256, GEMM_SMEM>>>(xh, wkh, wvh, kp, vp, DKV, DIMS);

    int qpairs = MM * NH  * (HD / 2);
    int kpairs = MM * NKV * (HD / 2);
    rope_kernel<<<(qpairs + 255) / 256, 256>>>(qp, fr, NH , qpairs);
    rope_kernel<<<(kpairs + 255) / 256, 256>>>(kp, fr, NKV, kpairs);

    attn_mma<<<dim3(LL / 128, NH, BB), 256, ATTN_SMEM>>>(qp, kp, vp, ah);

    gemm_h<<<dim3(DIMS / 128, MM / 128, 1), 256, GEMM_SMEM>>>(ah, woh, woh, out, out, DIMS, DIMS);
}

// round 10
// speedup vs baseline: 7.4950x; 1.0608x over previous
#include <cuda_runtime.h>
#include <cuda_fp16.h>
#include <math.h>
#include <stdint.h>

#define BB   4
#define LL   1024
#define MM   (BB*LL)        // 4096 tokens
#define DIMS 4096
#define NH   32
#define NKV  8
#define HD   128
#define DKV  (NKV*HD)       // 1024

// Scratch (no cudaMalloc allowed) ------------------------------------------
__device__ float g_q[(size_t)MM*DIMS];
__device__ float g_k[(size_t)MM*DKV];
__device__ float g_v[(size_t)MM*DKV];
// fp16 pre-converted GEMM operands
__device__ __half g_xh [(size_t)MM*DIMS];
__device__ __half g_wqh[(size_t)DIMS*DIMS];
__device__ __half g_wkh[(size_t)DKV*DIMS];
__device__ __half g_wvh[(size_t)DKV*DIMS];
__device__ __half g_woh[(size_t)DIMS*DIMS];
__device__ __half g_ah [(size_t)MM*DIMS];   // attention out (half, feeds wo GEMM)
// pre-split hi/lo fp16 Q/K/V, head-major layout [b][head][seq][d]
__device__ __half g_qhi[(size_t)MM*DIMS];
__device__ __half g_qlo[(size_t)MM*DIMS];
__device__ __half g_khi[(size_t)MM*DKV];
__device__ __half g_klo[(size_t)MM*DKV];
__device__ __half g_vhi[(size_t)MM*DKV];
__device__ __half g_vlo[(size_t)MM*DKV];

// ======================= helpers ===========================================
__device__ __forceinline__ uint32_t smem_u32(const void* p) {
    uint32_t a;
    asm("{ .reg .u64 t; cvta.to.shared.u64 t, %1; cvt.u32.u64 %0, t; }"
        : "=r"(a) : "l"(p));
    return a;
}
__device__ __forceinline__ void ldx4(uint32_t* r, uint32_t addr) {
    asm volatile("ldmatrix.sync.aligned.m8n8.x4.shared.b16 {%0,%1,%2,%3}, [%4];"
                 : "=r"(r[0]), "=r"(r[1]), "=r"(r[2]), "=r"(r[3]) : "r"(addr));
}
__device__ __forceinline__ void ldx4t(uint32_t* r, uint32_t addr) {
    asm volatile("ldmatrix.sync.aligned.m8n8.x4.trans.shared.b16 {%0,%1,%2,%3}, [%4];"
                 : "=r"(r[0]), "=r"(r[1]), "=r"(r[2]), "=r"(r[3]) : "r"(addr));
}
__device__ __forceinline__ void mma16816(float* c, const uint32_t* a,
                                         uint32_t b0, uint32_t b1) {
    asm volatile(
        "mma.sync.aligned.m16n8k16.row.col.f32.f16.f16.f32 "
        "{%0,%1,%2,%3}, {%4,%5,%6,%7}, {%8,%9}, {%0,%1,%2,%3};"
        : "+f"(c[0]), "+f"(c[1]), "+f"(c[2]), "+f"(c[3])
        : "r"(a[0]), "r"(a[1]), "r"(a[2]), "r"(a[3]), "r"(b0), "r"(b1));
}
__device__ __forceinline__ void cpa16(uint32_t dst, const void* src) {
    asm volatile("cp.async.cg.shared.global [%0], [%1], 16;"
                 :: "r"(dst), "l"(src) : "memory");
}

// -------- fp32 -> fp16 pre-convert pass ------------------------------------
__global__ void cvt_h(const float* __restrict__ in, __half* __restrict__ out, int n4)
{
    int i = blockIdx.x * blockDim.x + threadIdx.x;
    if (i >= n4) return;
    float4 v = ((const float4*)in)[i];
    __half2 h0 = __floats2half2_rn(v.x, v.y);
    __half2 h1 = __floats2half2_rn(v.z, v.w);
    ((uint2*)out)[i] = make_uint2(*(uint32_t*)&h0, *(uint32_t*)&h1);
}

// ============ fp16 mma.sync GEMM, 4-stage cp.async pipeline ================
#define GTK 32
#define HROW 80
#define HTILE_B (128 * HROW)
#define STAGE_B (2 * HTILE_B)
#define NSTAGE  4
#define GEMM_SMEM (NSTAGE * STAGE_B)  // 81920 -> 2 CTAs/SM

__global__ __launch_bounds__(256, 2) void gemm_h(const __half* __restrict__ A,
                                                 const __half* __restrict__ B0_,
                                                 const __half* __restrict__ B1_,
                                                 float* __restrict__ C0_,
                                                 float* __restrict__ C1_,
                                                 int N, int K)
{
    extern __shared__ char sm[];
    const uint32_t smb = smem_u32(sm);
    const int tid  = threadIdx.x;
    const int lane = tid & 31;
    const int warp = tid >> 5;
    const int wm   = warp >> 1;
    const int wn   = warp & 1;
    const int lq   = lane >> 2;
    const int lt   = lane & 3;
    const int lrow = lane & 7;
    const int lsel = lane >> 3;
    const __half* Bm = blockIdx.z ? B1_ : B0_;
    float*        C  = blockIdx.z ? C1_ : C0_;
    const int bm = blockIdx.y * 128;
    const int bn = blockIdx.x * 128;

    const __half* aSrc[2]; const __half* bSrc[2]; uint32_t dOff[2];
#pragma unroll
    for (int j = 0; j < 2; j++) {
        int idx = tid + j * 256;
        int r = idx >> 2, c = idx & 3;
        aSrc[j] = A  + (size_t)(bm + r) * K + c * 8;
        bSrc[j] = Bm + (size_t)(bn + r) * K + c * 8;
        dOff[j] = r * HROW + c * 16;
    }

    const uint32_t aOff = (uint32_t)(wm * 32 + (lsel & 1) * 8 + lrow) * HROW
                        + (uint32_t)(lsel >> 1) * 16;
    const uint32_t bOff = (uint32_t)(wn * 64 + (lsel >> 1) * 8 + lrow) * HROW
                        + (uint32_t)(lsel & 1) * 16;

    float acc[2][8][4];
#pragma unroll
    for (int mt = 0; mt < 2; mt++)
#pragma unroll
        for (int nt = 0; nt < 8; nt++)
#pragma unroll
            for (int i = 0; i < 4; i++) acc[mt][nt][i] = 0.0f;

    const int KT = K / GTK;

#pragma unroll
    for (int st = 0; st < NSTAGE - 1; st++) {
        const uint32_t sb = smb + st * STAGE_B;
        const size_t ko = (size_t)st * GTK;
#pragma unroll
        for (int j = 0; j < 2; j++) {
            cpa16(sb + dOff[j], aSrc[j] + ko);
            cpa16(sb + HTILE_B + dOff[j], bSrc[j] + ko);
        }
        asm volatile("cp.async.commit_group;" ::: "memory");
    }

    for (int kt = 0; kt < KT; kt++) {
        asm volatile("cp.async.wait_group %0;" :: "n"(NSTAGE - 2) : "memory");
        __syncthreads();
        // Prefetch kt+3 now: the target buffer's readers finished before the
        // sync above (they read it during iteration kt-1).
        {
            const int kp = (kt + NSTAGE - 1 < KT) ? (kt + NSTAGE - 1) : (KT - 1);
            const uint32_t sb = smb + ((kt + NSTAGE - 1) & (NSTAGE - 1)) * STAGE_B;
            const size_t ko = (size_t)kp * GTK;
#pragma unroll
            for (int j = 0; j < 2; j++) {
                cpa16(sb + dOff[j], aSrc[j] + ko);
                cpa16(sb + HTILE_B + dOff[j], bSrc[j] + ko);
            }
            asm volatile("cp.async.commit_group;" ::: "memory");
        }

        const uint32_t bufA = smb + (kt & (NSTAGE - 1)) * STAGE_B;
        const uint32_t bufB = bufA + HTILE_B;

#pragma unroll
        for (int ks = 0; ks < 2; ks++) {
            uint32_t a[2][4], b[4][4];
#pragma unroll
            for (int mt = 0; mt < 2; mt++)
                ldx4(a[mt], bufA + aOff + mt * (16 * HROW) + ks * 32);
#pragma unroll
            for (int p = 0; p < 4; p++)
                ldx4(b[p], bufB + bOff + p * (16 * HROW) + ks * 32);
#pragma unroll
            for (int mt = 0; mt < 2; mt++)
#pragma unroll
                for (int nt = 0; nt < 8; nt++)
                    mma16816(acc[mt][nt], a[mt],
                             b[nt >> 1][(nt & 1) * 2], b[nt >> 1][(nt & 1) * 2 + 1]);
        }
    }

#pragma unroll
    for (int mt = 0; mt < 2; mt++) {
        int r0 = bm + wm * 32 + mt * 16 + lq;
#pragma unroll
        for (int nt = 0; nt < 8; nt++) {
            int c = bn + wn * 64 + nt * 8 + 2 * lt;
            *(float2*)(C + (size_t)r0 * N + c)       = make_float2(acc[mt][nt][0], acc[mt][nt][1]);
            *(float2*)(C + (size_t)(r0 + 8) * N + c) = make_float2(acc[mt][nt][2], acc[mt][nt][3]);
        }
    }
}

// -------- RoPE + hi/lo split + layout transform ----------------------------
// in : [b][l][head][d] fp32 ; out hi/lo : [b][head][l][d] fp16
__global__ void rope_split(const float* __restrict__ in,
                           __half* __restrict__ hi, __half* __restrict__ lo,
                           const float* __restrict__ freqs,
                           int nheads, float scale, int total_pairs)
{
    int p = blockIdx.x * blockDim.x + threadIdx.x;
    if (p >= total_pairs) return;
    int d2 = p & 63;
    int h  = (p >> 6) % nheads;
    int bl = p / (64 * nheads);
    int l  = bl & (LL - 1);
    int b  = bl / LL;
    float f = freqs[l * 64 + d2];
    float c = cosf(f), s = sinf(f);
    float a  = in[2 * (size_t)p];
    float bb = in[2 * (size_t)p + 1];
    float x0 = (a * c - bb * s) * scale;
    float x1 = (a * s + bb * c) * scale;
    __half h0 = __float2half_rn(x0), h1 = __float2half_rn(x1);
    __half2 hh = __halves2half2(h0, h1);
    __half2 llv = __floats2half2_rn(x0 - __half2float(h0), x1 - __half2float(h1));
    size_t op = (((size_t)(b * nheads + h) * LL + l) * HD + 2 * d2);
    *(uint32_t*)(hi + op) = *(uint32_t*)&hh;
    *(uint32_t*)(lo + op) = *(uint32_t*)&llv;
}

// -------- V hi/lo split + layout transform (no rope) -----------------------
__global__ void split_v(const float* __restrict__ in,
                        __half* __restrict__ hi, __half* __restrict__ lo, int n2)
{
    int p = blockIdx.x * blockDim.x + threadIdx.x;
    if (p >= n2) return;                     // p indexes float2
    int d2 = p & 63;
    int h  = (p >> 6) & (NKV - 1);
    int bl = p >> 9;                          // / (64*NKV)
    int l  = bl & (LL - 1);
    int b  = bl / LL;
    float2 u = ((const float2*)in)[p];
    __half h0 = __float2half_rn(u.x), h1 = __float2half_rn(u.y);
    __half2 hh = __halves2half2(h0, h1);
    __half2 llv = __floats2half2_rn(u.x - __half2float(h0), u.y - __half2float(h1));
    size_t op = (((size_t)(b * NKV + h) * LL + l) * HD + 2 * d2);
    *(uint32_t*)(hi + op) = *(uint32_t*)&hh;
    *(uint32_t*)(lo + op) = *(uint32_t*)&llv;
}

// ======== MMA flash attention v2: pre-split fp16, 64-row Q tiles ==========
// CTA: 64 q-rows x 1 head, 128 threads (4 warps x 16 rows), kv-tiles of 64.
// S = QhKh + QhKl + QlKh ; O += PhVh + PhVl + PlVh ; fp32 accum.
#define PIT   272
#define AQHI  0
#define AQLO  17408
#define AKHI  34816
#define AKLO  52224
#define AVHI  69632
#define AVLO  87040
#define ATTN_SMEM 104448   // x2 CTAs = 208896 <= 228KB/SM

__global__ __launch_bounds__(128, 2) void attn_mma(const __half* __restrict__ qhi,
                                                   const __half* __restrict__ qlo,
                                                   const __half* __restrict__ khi,
                                                   const __half* __restrict__ klo,
                                                   const __half* __restrict__ vhi,
                                                   const __half* __restrict__ vlo,
                                                   __half* __restrict__ o)
{
    extern __shared__ char smx[];
    const uint32_t smb = smem_u32(smx);
    const int tid = threadIdx.x, lane = tid & 31, w = tid >> 5;
    const int lq = lane >> 2, lt = lane & 3, lrow = lane & 7, lsel = lane >> 3;
    const int qt = (gridDim.x - 1) - blockIdx.x;   // heavy tiles first
    const int h = blockIdx.y, b = blockIdx.z;
    const int qbase = qt * 64;
    const int kvh = h >> 2;

    // ---- Q tile cp.async: [64][128] hi+lo, 2048 16B-chunks, 16/thread ----
    const __half* qhg = qhi + (((size_t)(b * NH + h) * LL + qbase) * HD);
    const __half* qlg = qlo + (((size_t)(b * NH + h) * LL + qbase) * HD);
#pragma unroll
    for (int j = 0; j < 16; j++) {
        int idx = tid + j * 128;              // 0..2047
        int arr = idx >> 10;                  // 0=hi 1=lo
        int e = idx & 1023;
        int r = e >> 4, c = e & 15;
        const __half* src = (arr ? qlg : qhg) + (size_t)r * HD + c * 8;
        cpa16(smb + (arr ? AQLO : AQHI) + r * PIT + c * 16, src);
    }
    asm volatile("cp.async.commit_group;" ::: "memory");

    float oacc[16][4];
#pragma unroll
    for (int j = 0; j < 16; j++)
#pragma unroll
        for (int i = 0; i < 4; i++) oacc[j][i] = 0.0f;
    float m0 = -1e30f, m1 = -1e30f, l0 = 0.0f, l1 = 0.0f;

    const __half* khg = khi + ((size_t)(b * NKV + kvh) * LL) * HD;
    const __half* klg = klo + ((size_t)(b * NKV + kvh) * LL) * HD;
    const __half* vhg = vhi + ((size_t)(b * NKV + kvh) * LL) * HD;
    const __half* vlg = vlo + ((size_t)(b * NKV + kvh) * LL) * HD;

    const uint32_t qOff = (uint32_t)(w * 16 + (lsel & 1) * 8 + lrow) * PIT
                        + (uint32_t)(lsel >> 1) * 16;
    const uint32_t kOff = (uint32_t)((lsel >> 1) * 8 + lrow) * PIT
                        + (uint32_t)(lsel & 1) * 16;
    const uint32_t vRow = (uint32_t)((lsel & 1) * 8 + lrow) * PIT
                        + (uint32_t)(lsel >> 1) * 16;

    for (int kt = 0; kt <= qt; kt++) {
        __syncthreads();   // prior reads of K/V smem done before overwrite
        // ---- K,V tile cp.async: 4 arrays x [64][128] = 4096 chunks, 32/thread
#pragma unroll
        for (int j = 0; j < 32; j++) {
            int idx = tid + j * 128;          // 0..4095
            int arr = idx >> 10;              // 0=khi 1=klo 2=vhi 3=vlo
            int e = idx & 1023;
            int r = e >> 4, c = e & 15;
            size_t go = (size_t)(kt * 64 + r) * HD + c * 8;
            const __half* src = (arr == 0 ? khg : arr == 1 ? klg : arr == 2 ? vhg : vlg) + go;
            uint32_t dst = smb + (arr == 0 ? AKHI : arr == 1 ? AKLO : arr == 2 ? AVHI : AVLO)
                         + r * PIT + c * 16;
            cpa16(dst, src);
        }
        asm volatile("cp.async.commit_group;" ::: "memory");
        asm volatile("cp.async.wait_group 0;" ::: "memory");
        __syncthreads();

        // ---- S = Q K^T (hh + hl + lh) ----
        float sacc[8][4];
#pragma unroll
        for (int nt = 0; nt < 8; nt++)
#pragma unroll
            for (int i = 0; i < 4; i++) sacc[nt][i] = 0.0f;

#pragma unroll
        for (int c = 0; c < 8; c++) {
            uint32_t qh[4], ql[4];
            ldx4(qh, smb + AQHI + qOff + c * 32);
            ldx4(ql, smb + AQLO + qOff + c * 32);
#pragma unroll
            for (int p = 0; p < 4; p++) {
                uint32_t kh[4], kl[4];
                ldx4(kh, smb + AKHI + kOff + p * (16 * PIT) + c * 32);
                ldx4(kl, smb + AKLO + kOff + p * (16 * PIT) + c * 32);
                mma16816(sacc[2 * p],     qh, kh[0], kh[1]);
                mma16816(sacc[2 * p],     qh, kl[0], kl[1]);
                mma16816(sacc[2 * p],     ql, kh[0], kh[1]);
                mma16816(sacc[2 * p + 1], qh, kh[2], kh[3]);
                mma16816(sacc[2 * p + 1], qh, kl[2], kl[3]);
                mma16816(sacc[2 * p + 1], ql, kh[2], kh[3]);
            }
        }

        // ---- causal mask (diagonal tile only) ----
        if (kt == qt) {
            const int qg0 = qbase + w * 16 + lq;
            const int qg1 = qg0 + 8;
            const int kvb = kt * 64;
#pragma unroll
            for (int nt = 0; nt < 8; nt++) {
                int cv = kvb + nt * 8 + 2 * lt;
                if (cv     > qg0) sacc[nt][0] = -1e30f;
                if (cv + 1 > qg0) sacc[nt][1] = -1e30f;
                if (cv     > qg1) sacc[nt][2] = -1e30f;
                if (cv + 1 > qg1) sacc[nt][3] = -1e30f;
            }
        }

        // ---- online softmax ----
        float mx0 = -1e30f, mx1 = -1e30f;
#pragma unroll
        for (int nt = 0; nt < 8; nt++) {
            mx0 = fmaxf(mx0, fmaxf(sacc[nt][0], sacc[nt][1]));
            mx1 = fmaxf(mx1, fmaxf(sacc[nt][2], sacc[nt][3]));
        }
        mx0 = fmaxf(mx0, __shfl_xor_sync(0xffffffffu, mx0, 1));
        mx0 = fmaxf(mx0, __shfl_xor_sync(0xffffffffu, mx0, 2));
        mx1 = fmaxf(mx1, __shfl_xor_sync(0xffffffffu, mx1, 1));
        mx1 = fmaxf(mx1, __shfl_xor_sync(0xffffffffu, mx1, 2));
        float mn0 = fmaxf(m0, mx0), mn1 = fmaxf(m1, mx1);
        float cr0 = __expf(m0 - mn0), cr1 = __expf(m1 - mn1);
        m0 = mn0; m1 = mn1;
        float sum0 = 0.0f, sum1 = 0.0f;
#pragma unroll
        for (int nt = 0; nt < 8; nt++) {
            sacc[nt][0] = __expf(sacc[nt][0] - m0); sum0 += sacc[nt][0];
            sacc[nt][1] = __expf(sacc[nt][1] - m0); sum0 += sacc[nt][1];
            sacc[nt][2] = __expf(sacc[nt][2] - m1); sum1 += sacc[nt][2];
            sacc[nt][3] = __expf(sacc[nt][3] - m1); sum1 += sacc[nt][3];
        }
        sum0 += __shfl_xor_sync(0xffffffffu, sum0, 1);
        sum0 += __shfl_xor_sync(0xffffffffu, sum0, 2);
        sum1 += __shfl_xor_sync(0xffffffffu, sum1, 1);
        sum1 += __shfl_xor_sync(0xffffffffu, sum1, 2);
        l0 = l0 * cr0 + sum0;
        l1 = l1 * cr1 + sum1;
#pragma unroll
        for (int j = 0; j < 16; j++) {
            oacc[j][0] *= cr0; oacc[j][1] *= cr0;
            oacc[j][2] *= cr1; oacc[j][3] *= cr1;
        }

        // ---- O += P V (PhVh + PhVl + PlVh) ----
#pragma unroll
        for (int c = 0; c < 4; c++) {
            uint32_t phi[4], plo[4];
#pragma unroll
            for (int u = 0; u < 4; u++) {
                float pa = sacc[2 * c + (u >> 1)][(u & 1) * 2];
                float pb = sacc[2 * c + (u >> 1)][(u & 1) * 2 + 1];
                __half ha = __float2half_rn(pa), hb = __float2half_rn(pb);
                __half2 hh = __halves2half2(ha, hb);
                __half2 llv = __floats2half2_rn(pa - __half2float(ha), pb - __half2float(hb));
                phi[u] = *(uint32_t*)&hh;
                plo[u] = *(uint32_t*)&llv;
            }
#pragma unroll
            for (int jp = 0; jp < 8; jp++) {
                uint32_t vh[4], vl[4];
                uint32_t va = smb + vRow + c * (16 * PIT) + jp * 32;
                ldx4t(vh, va + AVHI);
                ldx4t(vl, va + AVLO);
                mma16816(oacc[2 * jp],     phi, vh[0], vh[1]);
                mma16816(oacc[2 * jp],     phi, vl[0], vl[1]);
                mma16816(oacc[2 * jp],     plo, vh[0], vh[1]);
                mma16816(oacc[2 * jp + 1], phi, vh[2], vh[3]);
                mma16816(oacc[2 * jp + 1], phi, vl[2], vl[3]);
                mma16816(oacc[2 * jp + 1], plo, vh[2], vh[3]);
            }
        }
    }

    // ---- epilogue ----
    const float i0 = 1.0f / l0, i1 = 1.0f / l1;
    const int row0 = qbase + w * 16 + lq;
    __half* ob0 = o + (size_t)(b * LL + row0) * DIMS + h * HD;
    __half* ob1 = ob0 + (size_t)8 * DIMS;
#pragma unroll
    for (int j = 0; j < 16; j++) {
        int col = j * 8 + 2 * lt;
        __half2 h0 = __floats2half2_rn(oacc[j][0] * i0, oacc[j][1] * i0);
        __half2 h1 = __floats2half2_rn(oacc[j][2] * i1, oacc[j][3] * i1);
        *(uint32_t*)(ob0 + col) = *(uint32_t*)&h0;
        *(uint32_t*)(ob1 + col) = *(uint32_t*)&h1;
    }
}

// ---------------------------------------------------------------------------
extern "C" void kernel_launch(void* const* d_in, const int* in_sizes, int n_in,
                              void* d_out, int out_size)
{
    const float* x  = (const float*)d_in[0];
    const float* wq = (const float*)d_in[1];
    const float* wk = (const float*)d_in[2];
    const float* wv = (const float*)d_in[3];
    const float* wo = (const float*)d_in[4];
    const float* fr = (const float*)d_in[5];
    float* out = (float*)d_out;

    float *qp, *kp, *vp;
    __half *xh, *wqh, *wkh, *wvh, *woh, *ah;
    __half *qhi, *qlo, *khi, *klo, *vhi, *vlo;
    cudaGetSymbolAddress((void**)&qp,  g_q);
    cudaGetSymbolAddress((void**)&kp,  g_k);
    cudaGetSymbolAddress((void**)&vp,  g_v);
    cudaGetSymbolAddress((void**)&xh,  g_xh);
    cudaGetSymbolAddress((void**)&wqh, g_wqh);
    cudaGetSymbolAddress((void**)&wkh, g_wkh);
    cudaGetSymbolAddress((void**)&wvh, g_wvh);
    cudaGetSymbolAddress((void**)&woh, g_woh);
    cudaGetSymbolAddress((void**)&ah,  g_ah);
    cudaGetSymbolAddress((void**)&qhi, g_qhi);
    cudaGetSymbolAddress((void**)&qlo, g_qlo);
    cudaGetSymbolAddress((void**)&khi, g_khi);
    cudaGetSymbolAddress((void**)&klo, g_klo);
    cudaGetSymbolAddress((void**)&vhi, g_vhi);
    cudaGetSymbolAddress((void**)&vlo, g_vlo);

    cudaFuncSetAttribute(gemm_h, cudaFuncAttributeMaxDynamicSharedMemorySize, GEMM_SMEM);
    cudaFuncSetAttribute(attn_mma, cudaFuncAttributeMaxDynamicSharedMemorySize, ATTN_SMEM);

    const int n_big = MM * DIMS / 4;
    const int n_kv  = DKV * DIMS / 4;
    cvt_h<<<(n_big + 255) / 256, 256>>>(x,  xh,  n_big);
    cvt_h<<<(n_big + 255) / 256, 256>>>(wq, wqh, n_big);
    cvt_h<<<(n_kv  + 255) / 256, 256>>>(wk, wkh, n_kv);
    cvt_h<<<(n_kv  + 255) / 256, 256>>>(wv, wvh, n_kv);
    cvt_h<<<(n_big + 255) / 256, 256>>>(wo, woh, n_big);

    gemm_h<<<dim3(DIMS / 128, MM / 128, 1), 256, GEMM_SMEM>>>(xh, wqh, wqh, qp, qp, DIMS, DIMS);
    gemm_h<<<dim3(DKV  / 128, MM / 128, 2), 256, GEMM_SMEM>>>(xh, wkh, wvh, kp, vp, DKV, DIMS);

    const float qscale = 0.088388347648318447f;   // 1/sqrt(128)
    int qpairs = MM * NH  * (HD / 2);
    int kpairs = MM * NKV * (HD / 2);
    rope_split<<<(qpairs + 255) / 256, 256>>>(qp, qhi, qlo, fr, NH , qscale, qpairs);
    rope_split<<<(kpairs + 255) / 256, 256>>>(kp, khi, klo, fr, NKV, 1.0f,   kpairs);
    split_v   <<<(kpairs + 255) / 256, 256>>>(vp, vhi, vlo, kpairs);

    attn_mma<<<dim3(LL / 64, NH, BB), 128, ATTN_SMEM>>>(qhi, qlo, khi, klo, vhi, vlo, ah);

    gemm_h<<<dim3(DIMS / 128, MM / 128, 1), 256, GEMM_SMEM>>>(ah, woh, woh, out, out, DIMS, DIMS);
}

// round 12
// speedup vs baseline: 7.8518x; 1.0476x over previous
#include <cuda_runtime.h>
#include <cuda_fp16.h>
#include <math.h>
#include <stdint.h>

#define BB   4
#define LL   1024
#define MM   (BB*LL)        // 4096 tokens
#define DIMS 4096
#define NH   32
#define NKV  8
#define HD   128
#define DKV  (NKV*HD)       // 1024

// Scratch (no cudaMalloc allowed) ------------------------------------------
__device__ __half g_xh [(size_t)MM*DIMS];
__device__ __half g_wqh[(size_t)DIMS*DIMS];
__device__ __half g_wkh[(size_t)DKV*DIMS];
__device__ __half g_wvh[(size_t)DKV*DIMS];
__device__ __half g_woh[(size_t)DIMS*DIMS];
__device__ __half g_ah [(size_t)MM*DIMS];   // attention out (half, feeds wo GEMM)
// pre-split hi/lo fp16 Q/K/V, head-major layout [b][head][seq][d]
__device__ __half g_qhi[(size_t)MM*DIMS];
__device__ __half g_qlo[(size_t)MM*DIMS];
__device__ __half g_khi[(size_t)MM*DKV];
__device__ __half g_klo[(size_t)MM*DKV];
__device__ __half g_vhi[(size_t)MM*DKV];
__device__ __half g_vlo[(size_t)MM*DKV];

// ======================= helpers ===========================================
__device__ __forceinline__ uint32_t smem_u32(const void* p) {
    uint32_t a;
    asm("{ .reg .u64 t; cvta.to.shared.u64 t, %1; cvt.u32.u64 %0, t; }"
        : "=r"(a) : "l"(p));
    return a;
}
__device__ __forceinline__ void ldx4(uint32_t* r, uint32_t addr) {
    asm volatile("ldmatrix.sync.aligned.m8n8.x4.shared.b16 {%0,%1,%2,%3}, [%4];"
                 : "=r"(r[0]), "=r"(r[1]), "=r"(r[2]), "=r"(r[3]) : "r"(addr));
}
__device__ __forceinline__ void ldx4t(uint32_t* r, uint32_t addr) {
    asm volatile("ldmatrix.sync.aligned.m8n8.x4.trans.shared.b16 {%0,%1,%2,%3}, [%4];"
                 : "=r"(r[0]), "=r"(r[1]), "=r"(r[2]), "=r"(r[3]) : "r"(addr));
}
__device__ __forceinline__ void mma16816(float* c, const uint32_t* a,
                                         uint32_t b0, uint32_t b1) {
    asm volatile(
        "mma.sync.aligned.m16n8k16.row.col.f32.f16.f16.f32 "
        "{%0,%1,%2,%3}, {%4,%5,%6,%7}, {%8,%9}, {%0,%1,%2,%3};"
        : "+f"(c[0]), "+f"(c[1]), "+f"(c[2]), "+f"(c[3])
        : "r"(a[0]), "r"(a[1]), "r"(a[2]), "r"(a[3]), "r"(b0), "r"(b1));
}
__device__ __forceinline__ void cpa16(uint32_t dst, const void* src) {
    asm volatile("cp.async.cg.shared.global [%0], [%1], 16;"
                 :: "r"(dst), "l"(src) : "memory");
}
__device__ __forceinline__ void split_store(__half* hi, __half* lo, size_t idx,
                                            float x0, float x1) {
    __half h0 = __float2half_rn(x0), h1 = __float2half_rn(x1);
    __half2 hh = __halves2half2(h0, h1);
    __half2 llv = __floats2half2_rn(x0 - __half2float(h0), x1 - __half2float(h1));
    *(uint32_t*)(hi + idx) = *(uint32_t*)&hh;
    *(uint32_t*)(lo + idx) = *(uint32_t*)&llv;
}

// -------- fp32 -> fp16 pre-convert pass ------------------------------------
__global__ void cvt_h(const float* __restrict__ in, __half* __restrict__ out, int n4)
{
    int i = blockIdx.x * blockDim.x + threadIdx.x;
    if (i >= n4) return;
    float4 v = ((const float4*)in)[i];
    __half2 h0 = __floats2half2_rn(v.x, v.y);
    __half2 h1 = __floats2half2_rn(v.z, v.w);
    ((uint2*)out)[i] = make_uint2(*(uint32_t*)&h0, *(uint32_t*)&h1);
}

// ============ shared GEMM mainloop macro bits ==============================
#define GTK 32
#define HROW 80
#define HTILE_B (128 * HROW)
#define STAGE_B (2 * HTILE_B)
#define NSTAGE  4
#define GEMM_SMEM (NSTAGE * STAGE_B)  // 81920 -> 2 CTAs/SM

// ======== Fused QKV projection GEMM + RoPE + hi/lo split epilogue ==========
// grid.x: [0,32) Q-tiles, [32,40) K-tiles, [40,48) V-tiles ; grid.y: M-tiles
__global__ __launch_bounds__(256, 2) void gemm_qkv(const __half* __restrict__ A,
                                                   const __half* __restrict__ WQ,
                                                   const __half* __restrict__ WK,
                                                   const __half* __restrict__ WV,
                                                   __half* __restrict__ qhi, __half* __restrict__ qlo,
                                                   __half* __restrict__ khi, __half* __restrict__ klo,
                                                   __half* __restrict__ vhi, __half* __restrict__ vlo,
                                                   const float* __restrict__ freqs)
{
    extern __shared__ char sm[];
    const uint32_t smb = smem_u32(sm);
    const int tid  = threadIdx.x;
    const int lane = tid & 31;
    const int warp = tid >> 5;
    const int wm   = warp >> 1;
    const int wn   = warp & 1;
    const int lq   = lane >> 2;
    const int lt   = lane & 3;
    const int lrow = lane & 7;
    const int lsel = lane >> 3;

    const int bx = blockIdx.x;
    int mode; const __half* Bm; int bnl;
    if (bx < 32)      { mode = 0; Bm = WQ; bnl = bx * 128; }
    else if (bx < 40) { mode = 1; Bm = WK; bnl = (bx - 32) * 128; }
    else              { mode = 2; Bm = WV; bnl = (bx - 40) * 128; }
    const int bm = blockIdx.y * 128;
    const int K = DIMS;

    const __half* aSrc[2]; const __half* bSrc[2]; uint32_t dOff[2];
#pragma unroll
    for (int j = 0; j < 2; j++) {
        int idx = tid + j * 256;
        int r = idx >> 2, c = idx & 3;
        aSrc[j] = A  + (size_t)(bm + r) * K + c * 8;
        bSrc[j] = Bm + (size_t)(bnl + r) * K + c * 8;
        dOff[j] = r * HROW + c * 16;
    }

    const uint32_t aOff = (uint32_t)(wm * 32 + (lsel & 1) * 8 + lrow) * HROW
                        + (uint32_t)(lsel >> 1) * 16;
    const uint32_t bOff = (uint32_t)(wn * 64 + (lsel >> 1) * 8 + lrow) * HROW
                        + (uint32_t)(lsel & 1) * 16;

    float acc[2][8][4];
#pragma unroll
    for (int mt = 0; mt < 2; mt++)
#pragma unroll
        for (int nt = 0; nt < 8; nt++)
#pragma unroll
            for (int i = 0; i < 4; i++) acc[mt][nt][i] = 0.0f;

    const int KT = K / GTK;

#pragma unroll
    for (int st = 0; st < NSTAGE - 1; st++) {
        const uint32_t sb = smb + st * STAGE_B;
        const size_t ko = (size_t)st * GTK;
#pragma unroll
        for (int j = 0; j < 2; j++) {
            cpa16(sb + dOff[j], aSrc[j] + ko);
            cpa16(sb + HTILE_B + dOff[j], bSrc[j] + ko);
        }
        asm volatile("cp.async.commit_group;" ::: "memory");
    }

    for (int kt = 0; kt < KT; kt++) {
        asm volatile("cp.async.wait_group %0;" :: "n"(NSTAGE - 2) : "memory");
        __syncthreads();
        {
            const int kp = (kt + NSTAGE - 1 < KT) ? (kt + NSTAGE - 1) : (KT - 1);
            const uint32_t sb = smb + ((kt + NSTAGE - 1) & (NSTAGE - 1)) * STAGE_B;
            const size_t ko = (size_t)kp * GTK;
#pragma unroll
            for (int j = 0; j < 2; j++) {
                cpa16(sb + dOff[j], aSrc[j] + ko);
                cpa16(sb + HTILE_B + dOff[j], bSrc[j] + ko);
            }
            asm volatile("cp.async.commit_group;" ::: "memory");
        }

        const uint32_t bufA = smb + (kt & (NSTAGE - 1)) * STAGE_B;
        const uint32_t bufB = bufA + HTILE_B;

#pragma unroll
        for (int ks = 0; ks < 2; ks++) {
            uint32_t a[2][4], b[4][4];
#pragma unroll
            for (int mt = 0; mt < 2; mt++)
                ldx4(a[mt], bufA + aOff + mt * (16 * HROW) + ks * 32);
#pragma unroll
            for (int p = 0; p < 4; p++)
                ldx4(b[p], bufB + bOff + p * (16 * HROW) + ks * 32);
#pragma unroll
            for (int mt = 0; mt < 2; mt++)
#pragma unroll
                for (int nt = 0; nt < 8; nt++)
                    mma16816(acc[mt][nt], a[mt],
                             b[nt >> 1][(nt & 1) * 2], b[nt >> 1][(nt & 1) * 2 + 1]);
        }
    }

    // ---- fused epilogue: RoPE (Q,K) + hi/lo split + head-major store ----
    const float qscale = 0.088388347648318447f;   // 1/sqrt(128)
    const int nh  = (mode == 0) ? NH : NKV;
    __half* hiB = (mode == 0) ? qhi : (mode == 1) ? khi : vhi;
    __half* loB = (mode == 0) ? qlo : (mode == 1) ? klo : vlo;
    const float scl = (mode == 0) ? qscale : 1.0f;

#pragma unroll
    for (int mt = 0; mt < 2; mt++) {
        const int r0 = bm + wm * 32 + mt * 16 + lq;
#pragma unroll
        for (int nt = 0; nt < 8; nt++) {
            const int c  = bnl + wn * 64 + nt * 8 + 2 * lt;   // even
            const int h  = c >> 7;
            const int d  = c & 127;
            if (mode == 2) {
#pragma unroll
                for (int rr = 0; rr < 2; rr++) {
                    const int r = r0 + rr * 8;
                    const int l = r & (LL - 1), bq = r >> 10;
                    size_t idx = (((size_t)(bq * nh + h) * LL + l) * HD + d);
                    split_store(hiB, loB, idx, acc[mt][nt][rr * 2], acc[mt][nt][rr * 2 + 1]);
                }
            } else {
                const int d2 = d >> 1;
#pragma unroll
                for (int rr = 0; rr < 2; rr++) {
                    const int r = r0 + rr * 8;
                    const int l = r & (LL - 1), bq = r >> 10;
                    const float f = freqs[l * 64 + d2];
                    const float cs = cosf(f), sn = sinf(f);
                    const float a0 = acc[mt][nt][rr * 2], a1 = acc[mt][nt][rr * 2 + 1];
                    const float x0 = (a0 * cs - a1 * sn) * scl;
                    const float x1 = (a0 * sn + a1 * cs) * scl;
                    size_t idx = (((size_t)(bq * nh + h) * LL + l) * HD + d);
                    split_store(hiB, loB, idx, x0, x1);
                }
            }
        }
    }
}

// ============ plain fp16 GEMM (wo projection), fp32 C out ==================
__global__ __launch_bounds__(256, 2) void gemm_h(const __half* __restrict__ A,
                                                 const __half* __restrict__ Bm,
                                                 float* __restrict__ C,
                                                 int N, int K)
{
    extern __shared__ char sm[];
    const uint32_t smb = smem_u32(sm);
    const int tid  = threadIdx.x;
    const int lane = tid & 31;
    const int warp = tid >> 5;
    const int wm   = warp >> 1;
    const int wn   = warp & 1;
    const int lq   = lane >> 2;
    const int lt   = lane & 3;
    const int lrow = lane & 7;
    const int lsel = lane >> 3;
    const int bm = blockIdx.y * 128;
    const int bn = blockIdx.x * 128;

    const __half* aSrc[2]; const __half* bSrc[2]; uint32_t dOff[2];
#pragma unroll
    for (int j = 0; j < 2; j++) {
        int idx = tid + j * 256;
        int r = idx >> 2, c = idx & 3;
        aSrc[j] = A  + (size_t)(bm + r) * K + c * 8;
        bSrc[j] = Bm + (size_t)(bn + r) * K + c * 8;
        dOff[j] = r * HROW + c * 16;
    }

    const uint32_t aOff = (uint32_t)(wm * 32 + (lsel & 1) * 8 + lrow) * HROW
                        + (uint32_t)(lsel >> 1) * 16;
    const uint32_t bOff = (uint32_t)(wn * 64 + (lsel >> 1) * 8 + lrow) * HROW
                        + (uint32_t)(lsel & 1) * 16;

    float acc[2][8][4];
#pragma unroll
    for (int mt = 0; mt < 2; mt++)
#pragma unroll
        for (int nt = 0; nt < 8; nt++)
#pragma unroll
            for (int i = 0; i < 4; i++) acc[mt][nt][i] = 0.0f;

    const int KT = K / GTK;

#pragma unroll
    for (int st = 0; st < NSTAGE - 1; st++) {
        const uint32_t sb = smb + st * STAGE_B;
        const size_t ko = (size_t)st * GTK;
#pragma unroll
        for (int j = 0; j < 2; j++) {
            cpa16(sb + dOff[j], aSrc[j] + ko);
            cpa16(sb + HTILE_B + dOff[j], bSrc[j] + ko);
        }
        asm volatile("cp.async.commit_group;" ::: "memory");
    }

    for (int kt = 0; kt < KT; kt++) {
        asm volatile("cp.async.wait_group %0;" :: "n"(NSTAGE - 2) : "memory");
        __syncthreads();
        {
            const int kp = (kt + NSTAGE - 1 < KT) ? (kt + NSTAGE - 1) : (KT - 1);
            const uint32_t sb = smb + ((kt + NSTAGE - 1) & (NSTAGE - 1)) * STAGE_B;
            const size_t ko = (size_t)kp * GTK;
#pragma unroll
            for (int j = 0; j < 2; j++) {
                cpa16(sb + dOff[j], aSrc[j] + ko);
                cpa16(sb + HTILE_B + dOff[j], bSrc[j] + ko);
            }
            asm volatile("cp.async.commit_group;" ::: "memory");
        }

        const uint32_t bufA = smb + (kt & (NSTAGE - 1)) * STAGE_B;
        const uint32_t bufB = bufA + HTILE_B;

#pragma unroll
        for (int ks = 0; ks < 2; ks++) {
            uint32_t a[2][4], b[4][4];
#pragma unroll
            for (int mt = 0; mt < 2; mt++)
                ldx4(a[mt], bufA + aOff + mt * (16 * HROW) + ks * 32);
#pragma unroll
            for (int p = 0; p < 4; p++)
                ldx4(b[p], bufB + bOff + p * (16 * HROW) + ks * 32);
#pragma unroll
            for (int mt = 0; mt < 2; mt++)
#pragma unroll
                for (int nt = 0; nt < 8; nt++)
                    mma16816(acc[mt][nt], a[mt],
                             b[nt >> 1][(nt & 1) * 2], b[nt >> 1][(nt & 1) * 2 + 1]);
        }
    }

#pragma unroll
    for (int mt = 0; mt < 2; mt++) {
        int r0 = bm + wm * 32 + mt * 16 + lq;
#pragma unroll
        for (int nt = 0; nt < 8; nt++) {
            int c = bn + wn * 64 + nt * 8 + 2 * lt;
            *(float2*)(C + (size_t)r0 * N + c)       = make_float2(acc[mt][nt][0], acc[mt][nt][1]);
            *(float2*)(C + (size_t)(r0 + 8) * N + c) = make_float2(acc[mt][nt][2], acc[mt][nt][3]);
        }
    }
}

// ======== MMA flash attention: pre-split fp16, 64-row Q tiles ==============
#define PIT   272
#define AQHI  0
#define AQLO  17408
#define AKHI  34816
#define AKLO  52224
#define AVHI  69632
#define AVLO  87040
#define ATTN_SMEM 104448   // x2 CTAs = 208896 <= 228KB/SM

__global__ __launch_bounds__(128, 2) void attn_mma(const __half* __restrict__ qhi,
                                                   const __half* __restrict__ qlo,
                                                   const __half* __restrict__ khi,
                                                   const __half* __restrict__ klo,
                                                   const __half* __restrict__ vhi,
                                                   const __half* __restrict__ vlo,
                                                   __half* __restrict__ o)
{
    extern __shared__ char smx[];
    const uint32_t smb = smem_u32(smx);
    const int tid = threadIdx.x, lane = tid & 31, w = tid >> 5;
    const int lq = lane >> 2, lt = lane & 3, lrow = lane & 7, lsel = lane >> 3;
    const int qt = (gridDim.x - 1) - blockIdx.x;   // heavy tiles first
    const int h = blockIdx.y, b = blockIdx.z;
    const int qbase = qt * 64;
    const int kvh = h >> 2;

    const __half* qhg = qhi + (((size_t)(b * NH + h) * LL + qbase) * HD);
    const __half* qlg = qlo + (((size_t)(b * NH + h) * LL + qbase) * HD);
#pragma unroll
    for (int j = 0; j < 16; j++) {
        int idx = tid + j * 128;
        int arr = idx >> 10;
        int e = idx & 1023;
        int r = e >> 4, c = e & 15;
        const __half* src = (arr ? qlg : qhg) + (size_t)r * HD + c * 8;
        cpa16(smb + (arr ? AQLO : AQHI) + r * PIT + c * 16, src);
    }
    asm volatile("cp.async.commit_group;" ::: "memory");

    float oacc[16][4];
#pragma unroll
    for (int j = 0; j < 16; j++)
#pragma unroll
        for (int i = 0; i < 4; i++) oacc[j][i] = 0.0f;
    float m0 = -1e30f, m1 = -1e30f, l0 = 0.0f, l1 = 0.0f;

    const __half* khg = khi + ((size_t)(b * NKV + kvh) * LL) * HD;
    const __half* klg = klo + ((size_t)(b * NKV + kvh) * LL) * HD;
    const __half* vhg = vhi + ((size_t)(b * NKV + kvh) * LL) * HD;
    const __half* vlg = vlo + ((size_t)(b * NKV + kvh) * LL) * HD;

    const uint32_t qOff = (uint32_t)(w * 16 + (lsel & 1) * 8 + lrow) * PIT
                        + (uint32_t)(lsel >> 1) * 16;
    const uint32_t kOff = (uint32_t)((lsel >> 1) * 8 + lrow) * PIT
                        + (uint32_t)(lsel & 1) * 16;
    const uint32_t vRow = (uint32_t)((lsel & 1) * 8 + lrow) * PIT
                        + (uint32_t)(lsel >> 1) * 16;

    for (int kt = 0; kt <= qt; kt++) {
        __syncthreads();
#pragma unroll
        for (int j = 0; j < 32; j++) {
            int idx = tid + j * 128;
            int arr = idx >> 10;
            int e = idx & 1023;
            int r = e >> 4, c = e & 15;
            size_t go = (size_t)(kt * 64 + r) * HD + c * 8;
            const __half* src = (arr == 0 ? khg : arr == 1 ? klg : arr == 2 ? vhg : vlg) + go;
            uint32_t dst = smb + (arr == 0 ? AKHI : arr == 1 ? AKLO : arr == 2 ? AVHI : AVLO)
                         + r * PIT + c * 16;
            cpa16(dst, src);
        }
        asm volatile("cp.async.commit_group;" ::: "memory");
        asm volatile("cp.async.wait_group 0;" ::: "memory");
        __syncthreads();

        float sacc[8][4];
#pragma unroll
        for (int nt = 0; nt < 8; nt++)
#pragma unroll
            for (int i = 0; i < 4; i++) sacc[nt][i] = 0.0f;

#pragma unroll
        for (int c = 0; c < 8; c++) {
            uint32_t qh[4], ql[4];
            ldx4(qh, smb + AQHI + qOff + c * 32);
            ldx4(ql, smb + AQLO + qOff + c * 32);
#pragma unroll
            for (int p = 0; p < 4; p++) {
                uint32_t kh[4], kl[4];
                ldx4(kh, smb + AKHI + kOff + p * (16 * PIT) + c * 32);
                ldx4(kl, smb + AKLO + kOff + p * (16 * PIT) + c * 32);
                mma16816(sacc[2 * p],     qh, kh[0], kh[1]);
                mma16816(sacc[2 * p],     qh, kl[0], kl[1]);
                mma16816(sacc[2 * p],     ql, kh[0], kh[1]);
                mma16816(sacc[2 * p + 1], qh, kh[2], kh[3]);
                mma16816(sacc[2 * p + 1], qh, kl[2], kl[3]);
                mma16816(sacc[2 * p + 1], ql, kh[2], kh[3]);
            }
        }

        if (kt == qt) {
            const int qg0 = qbase + w * 16 + lq;
            const int qg1 = qg0 + 8;
            const int kvb = kt * 64;
#pragma unroll
            for (int nt = 0; nt < 8; nt++) {
                int cv = kvb + nt * 8 + 2 * lt;
                if (cv     > qg0) sacc[nt][0] = -1e30f;
                if (cv + 1 > qg0) sacc[nt][1] = -1e30f;
                if (cv     > qg1) sacc[nt][2] = -1e30f;
                if (cv + 1 > qg1) sacc[nt][3] = -1e30f;
            }
        }

        float mx0 = -1e30f, mx1 = -1e30f;
#pragma unroll
        for (int nt = 0; nt < 8; nt++) {
            mx0 = fmaxf(mx0, fmaxf(sacc[nt][0], sacc[nt][1]));
            mx1 = fmaxf(mx1, fmaxf(sacc[nt][2], sacc[nt][3]));
        }
        mx0 = fmaxf(mx0, __shfl_xor_sync(0xffffffffu, mx0, 1));
        mx0 = fmaxf(mx0, __shfl_xor_sync(0xffffffffu, mx0, 2));
        mx1 = fmaxf(mx1, __shfl_xor_sync(0xffffffffu, mx1, 1));
        mx1 = fmaxf(mx1, __shfl_xor_sync(0xffffffffu, mx1, 2));
        float mn0 = fmaxf(m0, mx0), mn1 = fmaxf(m1, mx1);
        float cr0 = __expf(m0 - mn0), cr1 = __expf(m1 - mn1);
        m0 = mn0; m1 = mn1;
        float sum0 = 0.0f, sum1 = 0.0f;
#pragma unroll
        for (int nt = 0; nt < 8; nt++) {
            sacc[nt][0] = __expf(sacc[nt][0] - m0); sum0 += sacc[nt][0];
            sacc[nt][1] = __expf(sacc[nt][1] - m0); sum0 += sacc[nt][1];
            sacc[nt][2] = __expf(sacc[nt][2] - m1); sum1 += sacc[nt][2];
            sacc[nt][3] = __expf(sacc[nt][3] - m1); sum1 += sacc[nt][3];
        }
        sum0 += __shfl_xor_sync(0xffffffffu, sum0, 1);
        sum0 += __shfl_xor_sync(0xffffffffu, sum0, 2);
        sum1 += __shfl_xor_sync(0xffffffffu, sum1, 1);
        sum1 += __shfl_xor_sync(0xffffffffu, sum1, 2);
        l0 = l0 * cr0 + sum0;
        l1 = l1 * cr1 + sum1;
#pragma unroll
        for (int j = 0; j < 16; j++) {
            oacc[j][0] *= cr0; oacc[j][1] *= cr0;
            oacc[j][2] *= cr1; oacc[j][3] *= cr1;
        }

#pragma unroll
        for (int c = 0; c < 4; c++) {
            uint32_t phi[4], plo[4];
#pragma unroll
            for (int u = 0; u < 4; u++) {
                float pa = sacc[2 * c + (u >> 1)][(u & 1) * 2];
                float pb = sacc[2 * c + (u >> 1)][(u & 1) * 2 + 1];
                __half ha = __float2half_rn(pa), hb = __float2half_rn(pb);
                __half2 hh = __halves2half2(ha, hb);
                __half2 llv = __floats2half2_rn(pa - __half2float(ha), pb - __half2float(hb));
                phi[u] = *(uint32_t*)&hh;
                plo[u] = *(uint32_t*)&llv;
            }
#pragma unroll
            for (int jp = 0; jp < 8; jp++) {
                uint32_t vh[4], vl[4];
                uint32_t va = smb + vRow + c * (16 * PIT) + jp * 32;
                ldx4t(vh, va + AVHI);
                ldx4t(vl, va + AVLO);
                mma16816(oacc[2 * jp],     phi, vh[0], vh[1]);
                mma16816(oacc[2 * jp],     phi, vl[0], vl[1]);
                mma16816(oacc[2 * jp],     plo, vh[0], vh[1]);
                mma16816(oacc[2 * jp + 1], phi, vh[2], vh[3]);
                mma16816(oacc[2 * jp + 1], phi, vl[2], vl[3]);
                mma16816(oacc[2 * jp + 1], plo, vh[2], vh[3]);
            }
        }
    }

    const float i0 = 1.0f / l0, i1 = 1.0f / l1;
    const int row0 = qbase + w * 16 + lq;
    __half* ob0 = o + (size_t)(b * LL + row0) * DIMS + h * HD;
    __half* ob1 = ob0 + (size_t)8 * DIMS;
#pragma unroll
    for (int j = 0; j < 16; j++) {
        int col = j * 8 + 2 * lt;
        __half2 h0 = __floats2half2_rn(oacc[j][0] * i0, oacc[j][1] * i0);
        __half2 h1 = __floats2half2_rn(oacc[j][2] * i1, oacc[j][3] * i1);
        *(uint32_t*)(ob0 + col) = *(uint32_t*)&h0;
        *(uint32_t*)(ob1 + col) = *(uint32_t*)&h1;
    }
}

// ---------------------------------------------------------------------------
extern "C" void kernel_launch(void* const* d_in, const int* in_sizes, int n_in,
                              void* d_out, int out_size)
{
    const float* x  = (const float*)d_in[0];
    const float* wq = (const float*)d_in[1];
    const float* wk = (const float*)d_in[2];
    const float* wv = (const float*)d_in[3];
    const float* wo = (const float*)d_in[4];
    const float* fr = (const float*)d_in[5];
    float* out = (float*)d_out;

    __half *xh, *wqh, *wkh, *wvh, *woh, *ah;
    __half *qhi, *qlo, *khi, *klo, *vhi, *vlo;
    cudaGetSymbolAddress((void**)&xh,  g_xh);
    cudaGetSymbolAddress((void**)&wqh, g_wqh);
    cudaGetSymbolAddress((void**)&wkh, g_wkh);
    cudaGetSymbolAddress((void**)&wvh, g_wvh);
    cudaGetSymbolAddress((void**)&woh, g_woh);
    cudaGetSymbolAddress((void**)&ah,  g_ah);
    cudaGetSymbolAddress((void**)&qhi, g_qhi);
    cudaGetSymbolAddress((void**)&qlo, g_qlo);
    cudaGetSymbolAddress((void**)&khi, g_khi);
    cudaGetSymbolAddress((void**)&klo, g_klo);
    cudaGetSymbolAddress((void**)&vhi, g_vhi);
    cudaGetSymbolAddress((void**)&vlo, g_vlo);

    cudaFuncSetAttribute(gemm_qkv, cudaFuncAttributeMaxDynamicSharedMemorySize, GEMM_SMEM);
    cudaFuncSetAttribute(gemm_h,   cudaFuncAttributeMaxDynamicSharedMemorySize, GEMM_SMEM);
    cudaFuncSetAttribute(attn_mma, cudaFuncAttributeMaxDynamicSharedMemorySize, ATTN_SMEM);

    const int n_big = MM * DIMS / 4;     // also DIMS*DIMS/4
    const int n_kv  = DKV * DIMS / 4;
    cvt_h<<<(n_big + 255) / 256, 256>>>(x,  xh,  n_big);
    cvt_h<<<(n_big + 255) / 256, 256>>>(wq, wqh, n_big);
    cvt_h<<<(n_kv  + 255) / 256, 256>>>(wk, wkh, n_kv);
    cvt_h<<<(n_kv  + 255) / 256, 256>>>(wv, wvh, n_kv);
    cvt_h<<<(n_big + 255) / 256, 256>>>(wo, woh, n_big);

    // Fused QKV projections + RoPE + split (one launch, 48x32 CTAs)
    gemm_qkv<<<dim3(48, MM / 128), 256, GEMM_SMEM>>>(
        xh, wqh, wkh, wvh, qhi, qlo, khi, klo, vhi, vlo, fr);

    attn_mma<<<dim3(LL / 64, NH, BB), 128, ATTN_SMEM>>>(qhi, qlo, khi, klo, vhi, vlo, ah);

    gemm_h<<<dim3(DIMS / 128, MM / 128), 256, GEMM_SMEM>>>(ah, woh, out, DIMS, DIMS);
}

// round 13
// speedup vs baseline: 8.1714x; 1.0407x over previous
#include <cuda_runtime.h>
#include <cuda_fp16.h>
#include <math.h>
#include <stdint.h>

#define BB   4
#define LL   1024
#define MM   (BB*LL)        // 4096 tokens
#define DIMS 4096
#define NH   32
#define NKV  8
#define HD   128
#define DKV  (NKV*HD)       // 1024

// Scratch (no cudaMalloc allowed) ------------------------------------------
__device__ __half g_xh [(size_t)MM*DIMS];
__device__ __half g_wqh[(size_t)DIMS*DIMS];
__device__ __half g_wkh[(size_t)DKV*DIMS];
__device__ __half g_wvh[(size_t)DKV*DIMS];
__device__ __half g_woh[(size_t)DIMS*DIMS];
__device__ __half g_ah [(size_t)MM*DIMS];   // attention out (half, feeds wo GEMM)
// pre-split hi/lo fp16 Q/K/V, head-major layout [b][head][seq][d]
__device__ __half g_qhi[(size_t)MM*DIMS];
__device__ __half g_qlo[(size_t)MM*DIMS];
__device__ __half g_khi[(size_t)MM*DKV];
__device__ __half g_klo[(size_t)MM*DKV];
__device__ __half g_vhi[(size_t)MM*DKV];
__device__ __half g_vlo[(size_t)MM*DKV];

// ======================= helpers ===========================================
__device__ __forceinline__ uint32_t smem_u32(const void* p) {
    uint32_t a;
    asm("{ .reg .u64 t; cvta.to.shared.u64 t, %1; cvt.u32.u64 %0, t; }"
        : "=r"(a) : "l"(p));
    return a;
}
__device__ __forceinline__ void ldx4(uint32_t* r, uint32_t addr) {
    asm volatile("ldmatrix.sync.aligned.m8n8.x4.shared.b16 {%0,%1,%2,%3}, [%4];"
                 : "=r"(r[0]), "=r"(r[1]), "=r"(r[2]), "=r"(r[3]) : "r"(addr));
}
__device__ __forceinline__ void ldx4t(uint32_t* r, uint32_t addr) {
    asm volatile("ldmatrix.sync.aligned.m8n8.x4.trans.shared.b16 {%0,%1,%2,%3}, [%4];"
                 : "=r"(r[0]), "=r"(r[1]), "=r"(r[2]), "=r"(r[3]) : "r"(addr));
}
__device__ __forceinline__ void mma16816(float* c, const uint32_t* a,
                                         uint32_t b0, uint32_t b1) {
    asm volatile(
        "mma.sync.aligned.m16n8k16.row.col.f32.f16.f16.f32 "
        "{%0,%1,%2,%3}, {%4,%5,%6,%7}, {%8,%9}, {%0,%1,%2,%3};"
        : "+f"(c[0]), "+f"(c[1]), "+f"(c[2]), "+f"(c[3])
        : "r"(a[0]), "r"(a[1]), "r"(a[2]), "r"(a[3]), "r"(b0), "r"(b1));
}
__device__ __forceinline__ void cpa16(uint32_t dst, const void* src) {
    asm volatile("cp.async.cg.shared.global [%0], [%1], 16;"
                 :: "r"(dst), "l"(src) : "memory");
}
__device__ __forceinline__ void split_store(__half* hi, __half* lo, size_t idx,
                                            float x0, float x1) {
    __half h0 = __float2half_rn(x0), h1 = __float2half_rn(x1);
    __half2 hh = __halves2half2(h0, h1);
    __half2 llv = __floats2half2_rn(x0 - __half2float(h0), x1 - __half2float(h1));
    *(uint32_t*)(hi + idx) = *(uint32_t*)&hh;
    *(uint32_t*)(lo + idx) = *(uint32_t*)&llv;
}

// -------- fused fp32 -> fp16 convert of ALL operands (grid-stride) ---------
__global__ void cvt_all(const float* __restrict__ x,  const float* __restrict__ wq,
                        const float* __restrict__ wk, const float* __restrict__ wv,
                        const float* __restrict__ wo,
                        __half* __restrict__ xh,  __half* __restrict__ wqh,
                        __half* __restrict__ wkh, __half* __restrict__ wvh,
                        __half* __restrict__ woh)
{
    const long NB = (long)MM * DIMS / 4;    // 4M float4
    const long NK = (long)DKV * DIMS / 4;   // 1M float4
    const long total = 3 * NB + 2 * NK;
    const long stride = (long)gridDim.x * blockDim.x;
    for (long i = (long)blockIdx.x * blockDim.x + threadIdx.x; i < total; i += stride) {
        const float* in; __half* out; long j = i;
        if (j < NB)                   { in = x;  out = xh; }
        else if (j < 2 * NB)          { in = wq; out = wqh; j -= NB; }
        else if (j < 2 * NB + NK)     { in = wk; out = wkh; j -= 2 * NB; }
        else if (j < 2 * NB + 2 * NK) { in = wv; out = wvh; j -= 2 * NB + NK; }
        else                          { in = wo; out = woh; j -= 2 * NB + 2 * NK; }
        float4 v = ((const float4*)in)[j];
        __half2 h0 = __floats2half2_rn(v.x, v.y);
        __half2 h1 = __floats2half2_rn(v.z, v.w);
        ((uint2*)out)[j] = make_uint2(*(uint32_t*)&h0, *(uint32_t*)&h1);
    }
}

// ============ shared GEMM mainloop constants (GTK=64, 3-stage) =============
#define GTK 64
#define HROW 144                     // 128B data + 16B pad per row
#define HTILE_B (128 * HROW)         // 18432 per operand
#define STAGE_B (2 * HTILE_B)        // 36864
#define NSTAGE  3
#define GEMM_SMEM (NSTAGE * STAGE_B) // 110592 -> 2 CTAs/SM (221184 <= 228KB)

// Mainloop body shared by both GEMM kernels via macro (identical numerics:
// K processed 0..4095 in the same 16-wide MMA order).
#define GEMM_MAINLOOP(A_, B_, K_)                                              \
    const __half* aSrc[4]; const __half* bSrc[4]; uint32_t dOff[4];            \
    _Pragma("unroll")                                                          \
    for (int j = 0; j < 4; j++) {                                              \
        int idx = tid + j * 256;            /* 0..1023 */                      \
        int r = idx >> 3, c = idx & 7;                                         \
        aSrc[j] = A_ + (size_t)(bm + r) * K_ + c * 8;                          \
        bSrc[j] = B_ + (size_t)(bnl + r) * K_ + c * 8;                         \
        dOff[j] = r * HROW + c * 16;                                           \
    }                                                                          \
    const uint32_t aOff = (uint32_t)(wm * 32 + (lsel & 1) * 8 + lrow) * HROW   \
                        + (uint32_t)(lsel >> 1) * 16;                          \
    const uint32_t bOff = (uint32_t)(wn * 64 + (lsel >> 1) * 8 + lrow) * HROW  \
                        + (uint32_t)(lsel & 1) * 16;                           \
    float acc[2][8][4];                                                        \
    _Pragma("unroll")                                                          \
    for (int mt = 0; mt < 2; mt++)                                             \
        _Pragma("unroll")                                                      \
        for (int nt = 0; nt < 8; nt++)                                         \
            _Pragma("unroll")                                                  \
            for (int i = 0; i < 4; i++) acc[mt][nt][i] = 0.0f;                 \
    const int KT = K_ / GTK;                                                   \
    _Pragma("unroll")                                                          \
    for (int st = 0; st < NSTAGE - 1; st++) {                                  \
        const uint32_t sb = smb + st * STAGE_B;                                \
        const size_t ko = (size_t)st * GTK;                                    \
        _Pragma("unroll")                                                      \
        for (int j = 0; j < 4; j++) {                                          \
            cpa16(sb + dOff[j], aSrc[j] + ko);                                 \
            cpa16(sb + HTILE_B + dOff[j], bSrc[j] + ko);                       \
        }                                                                      \
        asm volatile("cp.async.commit_group;" ::: "memory");                   \
    }                                                                          \
    int cb = 0, pb = NSTAGE - 1;                                               \
    for (int kt = 0; kt < KT; kt++) {                                          \
        asm volatile("cp.async.wait_group %0;" :: "n"(NSTAGE - 2) : "memory"); \
        __syncthreads();                                                       \
        {                                                                      \
            const int kp = (kt + NSTAGE - 1 < KT) ? (kt + NSTAGE - 1) : (KT - 1); \
            const uint32_t sb = smb + pb * STAGE_B;                            \
            const size_t ko = (size_t)kp * GTK;                                \
            _Pragma("unroll")                                                  \
            for (int j = 0; j < 4; j++) {                                      \
                cpa16(sb + dOff[j], aSrc[j] + ko);                             \
                cpa16(sb + HTILE_B + dOff[j], bSrc[j] + ko);                   \
            }                                                                  \
            asm volatile("cp.async.commit_group;" ::: "memory");               \
        }                                                                      \
        if (++pb == NSTAGE) pb = 0;                                            \
        const uint32_t bufA = smb + cb * STAGE_B;                              \
        const uint32_t bufB = bufA + HTILE_B;                                  \
        if (++cb == NSTAGE) cb = 0;                                            \
        _Pragma("unroll")                                                      \
        for (int ks = 0; ks < 4; ks++) {                                       \
            uint32_t a[2][4], b[4][4];                                         \
            _Pragma("unroll")                                                  \
            for (int mt = 0; mt < 2; mt++)                                     \
                ldx4(a[mt], bufA + aOff + mt * (16 * HROW) + ks * 32);         \
            _Pragma("unroll")                                                  \
            for (int p = 0; p < 4; p++)                                        \
                ldx4(b[p], bufB + bOff + p * (16 * HROW) + ks * 32);           \
            _Pragma("unroll")                                                  \
            for (int mt = 0; mt < 2; mt++)                                     \
                _Pragma("unroll")                                              \
                for (int nt = 0; nt < 8; nt++)                                 \
                    mma16816(acc[mt][nt], a[mt],                               \
                             b[nt >> 1][(nt & 1) * 2], b[nt >> 1][(nt & 1) * 2 + 1]); \
        }                                                                      \
    }

// ======== Fused QKV projection GEMM + RoPE + hi/lo split epilogue ==========
// grid.x: [0,32) Q-tiles, [32,40) K-tiles, [40,48) V-tiles ; grid.y: M-tiles
__global__ __launch_bounds__(256, 2) void gemm_qkv(const __half* __restrict__ A,
                                                   const __half* __restrict__ WQ,
                                                   const __half* __restrict__ WK,
                                                   const __half* __restrict__ WV,
                                                   __half* __restrict__ qhi, __half* __restrict__ qlo,
                                                   __half* __restrict__ khi, __half* __restrict__ klo,
                                                   __half* __restrict__ vhi, __half* __restrict__ vlo,
                                                   const float* __restrict__ freqs)
{
    extern __shared__ char sm[];
    const uint32_t smb = smem_u32(sm);
    const int tid  = threadIdx.x;
    const int lane = tid & 31;
    const int warp = tid >> 5;
    const int wm   = warp >> 1;
    const int wn   = warp & 1;
    const int lq   = lane >> 2;
    const int lt   = lane & 3;
    const int lrow = lane & 7;
    const int lsel = lane >> 3;

    const int bx = blockIdx.x;
    int mode; const __half* Bm; int bnl;
    if (bx < 32)      { mode = 0; Bm = WQ; bnl = bx * 128; }
    else if (bx < 40) { mode = 1; Bm = WK; bnl = (bx - 32) * 128; }
    else              { mode = 2; Bm = WV; bnl = (bx - 40) * 128; }
    const int bm = blockIdx.y * 128;

    GEMM_MAINLOOP(A, Bm, DIMS)

    // ---- fused epilogue: RoPE (Q,K) + hi/lo split + head-major store ----
    const float qscale = 0.088388347648318447f;   // 1/sqrt(128)
    const int nh  = (mode == 0) ? NH : NKV;
    __half* hiB = (mode == 0) ? qhi : (mode == 1) ? khi : vhi;
    __half* loB = (mode == 0) ? qlo : (mode == 1) ? klo : vlo;
    const float scl = (mode == 0) ? qscale : 1.0f;

#pragma unroll
    for (int mt = 0; mt < 2; mt++) {
        const int r0 = bm + wm * 32 + mt * 16 + lq;
#pragma unroll
        for (int nt = 0; nt < 8; nt++) {
            const int c  = bnl + wn * 64 + nt * 8 + 2 * lt;   // even
            const int h  = c >> 7;
            const int d  = c & 127;
            if (mode == 2) {
#pragma unroll
                for (int rr = 0; rr < 2; rr++) {
                    const int r = r0 + rr * 8;
                    const int l = r & (LL - 1), bq = r >> 10;
                    size_t idx = (((size_t)(bq * nh + h) * LL + l) * HD + d);
                    split_store(hiB, loB, idx, acc[mt][nt][rr * 2], acc[mt][nt][rr * 2 + 1]);
                }
            } else {
                const int d2 = d >> 1;
#pragma unroll
                for (int rr = 0; rr < 2; rr++) {
                    const int r = r0 + rr * 8;
                    const int l = r & (LL - 1), bq = r >> 10;
                    const float f = freqs[l * 64 + d2];
                    const float cs = cosf(f), sn = sinf(f);
                    const float a0 = acc[mt][nt][rr * 2], a1 = acc[mt][nt][rr * 2 + 1];
                    const float x0 = (a0 * cs - a1 * sn) * scl;
                    const float x1 = (a0 * sn + a1 * cs) * scl;
                    size_t idx = (((size_t)(bq * nh + h) * LL + l) * HD + d);
                    split_store(hiB, loB, idx, x0, x1);
                }
            }
        }
    }
}

// ============ plain fp16 GEMM (wo projection), fp32 C out ==================
__global__ __launch_bounds__(256, 2) void gemm_h(const __half* __restrict__ A,
                                                 const __half* __restrict__ Bw,
                                                 float* __restrict__ C,
                                                 int N, int K)
{
    extern __shared__ char sm[];
    const uint32_t smb = smem_u32(sm);
    const int tid  = threadIdx.x;
    const int lane = tid & 31;
    const int warp = tid >> 5;
    const int wm   = warp >> 1;
    const int wn   = warp & 1;
    const int lq   = lane >> 2;
    const int lt   = lane & 3;
    const int lrow = lane & 7;
    const int lsel = lane >> 3;
    const int bm  = blockIdx.y * 128;
    const int bnl = blockIdx.x * 128;

    GEMM_MAINLOOP(A, Bw, K)

#pragma unroll
    for (int mt = 0; mt < 2; mt++) {
        int r0 = bm + wm * 32 + mt * 16 + lq;
#pragma unroll
        for (int nt = 0; nt < 8; nt++) {
            int c = bnl + wn * 64 + nt * 8 + 2 * lt;
            *(float2*)(C + (size_t)r0 * N + c)       = make_float2(acc[mt][nt][0], acc[mt][nt][1]);
            *(float2*)(C + (size_t)(r0 + 8) * N + c) = make_float2(acc[mt][nt][2], acc[mt][nt][3]);
        }
    }
}

// ======== MMA flash attention: pre-split fp16, 64-row Q tiles ==============
#define PIT   272
#define AQHI  0
#define AQLO  17408
#define AKHI  34816
#define AKLO  52224
#define AVHI  69632
#define AVLO  87040
#define ATTN_SMEM 104448   // x2 CTAs = 208896 <= 228KB/SM

__global__ __launch_bounds__(128, 2) void attn_mma(const __half* __restrict__ qhi,
                                                   const __half* __restrict__ qlo,
                                                   const __half* __restrict__ khi,
                                                   const __half* __restrict__ klo,
                                                   const __half* __restrict__ vhi,
                                                   const __half* __restrict__ vlo,
                                                   __half* __restrict__ o)
{
    extern __shared__ char smx[];
    const uint32_t smb = smem_u32(smx);
    const int tid = threadIdx.x, lane = tid & 31, w = tid >> 5;
    const int lq = lane >> 2, lt = lane & 3, lrow = lane & 7, lsel = lane >> 3;
    const int qt = (gridDim.x - 1) - blockIdx.x;   // heavy tiles first
    const int h = blockIdx.y, b = blockIdx.z;
    const int qbase = qt * 64;
    const int kvh = h >> 2;

    const __half* qhg = qhi + (((size_t)(b * NH + h) * LL + qbase) * HD);
    const __half* qlg = qlo + (((size_t)(b * NH + h) * LL + qbase) * HD);
#pragma unroll
    for (int j = 0; j < 16; j++) {
        int idx = tid + j * 128;
        int arr = idx >> 10;
        int e = idx & 1023;
        int r = e >> 4, c = e & 15;
        const __half* src = (arr ? qlg : qhg) + (size_t)r * HD + c * 8;
        cpa16(smb + (arr ? AQLO : AQHI) + r * PIT + c * 16, src);
    }
    asm volatile("cp.async.commit_group;" ::: "memory");

    float oacc[16][4];
#pragma unroll
    for (int j = 0; j < 16; j++)
#pragma unroll
        for (int i = 0; i < 4; i++) oacc[j][i] = 0.0f;
    float m0 = -1e30f, m1 = -1e30f, l0 = 0.0f, l1 = 0.0f;

    const __half* khg = khi + ((size_t)(b * NKV + kvh) * LL) * HD;
    const __half* klg = klo + ((size_t)(b * NKV + kvh) * LL) * HD;
    const __half* vhg = vhi + ((size_t)(b * NKV + kvh) * LL) * HD;
    const __half* vlg = vlo + ((size_t)(b * NKV + kvh) * LL) * HD;

    const uint32_t qOff = (uint32_t)(w * 16 + (lsel & 1) * 8 + lrow) * PIT
                        + (uint32_t)(lsel >> 1) * 16;
    const uint32_t kOff = (uint32_t)((lsel >> 1) * 8 + lrow) * PIT
                        + (uint32_t)(lsel & 1) * 16;
    const uint32_t vRow = (uint32_t)((lsel & 1) * 8 + lrow) * PIT
                        + (uint32_t)(lsel >> 1) * 16;

    for (int kt = 0; kt <= qt; kt++) {
        __syncthreads();
#pragma unroll
        for (int j = 0; j < 32; j++) {
            int idx = tid + j * 128;
            int arr = idx >> 10;
            int e = idx & 1023;
            int r = e >> 4, c = e & 15;
            size_t go = (size_t)(kt * 64 + r) * HD + c * 8;
            const __half* src = (arr == 0 ? khg : arr == 1 ? klg : arr == 2 ? vhg : vlg) + go;
            uint32_t dst = smb + (arr == 0 ? AKHI : arr == 1 ? AKLO : arr == 2 ? AVHI : AVLO)
                         + r * PIT + c * 16;
            cpa16(dst, src);
        }
        asm volatile("cp.async.commit_group;" ::: "memory");
        asm volatile("cp.async.wait_group 0;" ::: "memory");
        __syncthreads();

        float sacc[8][4];
#pragma unroll
        for (int nt = 0; nt < 8; nt++)
#pragma unroll
            for (int i = 0; i < 4; i++) sacc[nt][i] = 0.0f;

#pragma unroll
        for (int c = 0; c < 8; c++) {
            uint32_t qh[4], ql[4];
            ldx4(qh, smb + AQHI + qOff + c * 32);
            ldx4(ql, smb + AQLO + qOff + c * 32);
#pragma unroll
            for (int p = 0; p < 4; p++) {
                uint32_t kh[4], kl[4];
                ldx4(kh, smb + AKHI + kOff + p * (16 * PIT) + c * 32);
                ldx4(kl, smb + AKLO + kOff + p * (16 * PIT) + c * 32);
                mma16816(sacc[2 * p],     qh, kh[0], kh[1]);
                mma16816(sacc[2 * p],     qh, kl[0], kl[1]);
                mma16816(sacc[2 * p],     ql, kh[0], kh[1]);
                mma16816(sacc[2 * p + 1], qh, kh[2], kh[3]);
                mma16816(sacc[2 * p + 1], qh, kl[2], kl[3]);
                mma16816(sacc[2 * p + 1], ql, kh[2], kh[3]);
            }
        }

        if (kt == qt) {
            const int qg0 = qbase + w * 16 + lq;
            const int qg1 = qg0 + 8;
            const int kvb = kt * 64;
#pragma unroll
            for (int nt = 0; nt < 8; nt++) {
                int cv = kvb + nt * 8 + 2 * lt;
                if (cv     > qg0) sacc[nt][0] = -1e30f;
                if (cv + 1 > qg0) sacc[nt][1] = -1e30f;
                if (cv     > qg1) sacc[nt][2] = -1e30f;
                if (cv + 1 > qg1) sacc[nt][3] = -1e30f;
            }
        }

        float mx0 = -1e30f, mx1 = -1e30f;
#pragma unroll
        for (int nt = 0; nt < 8; nt++) {
            mx0 = fmaxf(mx0, fmaxf(sacc[nt][0], sacc[nt][1]));
            mx1 = fmaxf(mx1, fmaxf(sacc[nt][2], sacc[nt][3]));
        }
        mx0 = fmaxf(mx0, __shfl_xor_sync(0xffffffffu, mx0, 1));
        mx0 = fmaxf(mx0, __shfl_xor_sync(0xffffffffu, mx0, 2));
        mx1 = fmaxf(mx1, __shfl_xor_sync(0xffffffffu, mx1, 1));
        mx1 = fmaxf(mx1, __shfl_xor_sync(0xffffffffu, mx1, 2));
        float mn0 = fmaxf(m0, mx0), mn1 = fmaxf(m1, mx1);
        float cr0 = __expf(m0 - mn0), cr1 = __expf(m1 - mn1);
        m0 = mn0; m1 = mn1;
        float sum0 = 0.0f, sum1 = 0.0f;
#pragma unroll
        for (int nt = 0; nt < 8; nt++) {
            sacc[nt][0] = __expf(sacc[nt][0] - m0); sum0 += sacc[nt][0];
            sacc[nt][1] = __expf(sacc[nt][1] - m0); sum0 += sacc[nt][1];
            sacc[nt][2] = __expf(sacc[nt][2] - m1); sum1 += sacc[nt][2];
            sacc[nt][3] = __expf(sacc[nt][3] - m1); sum1 += sacc[nt][3];
        }
        sum0 += __shfl_xor_sync(0xffffffffu, sum0, 1);
        sum0 += __shfl_xor_sync(0xffffffffu, sum0, 2);
        sum1 += __shfl_xor_sync(0xffffffffu, sum1, 1);
        sum1 += __shfl_xor_sync(0xffffffffu, sum1, 2);
        l0 = l0 * cr0 + sum0;
        l1 = l1 * cr1 + sum1;
#pragma unroll
        for (int j = 0; j < 16; j++) {
            oacc[j][0] *= cr0; oacc[j][1] *= cr0;
            oacc[j][2] *= cr1; oacc[j][3] *= cr1;
        }

#pragma unroll
        for (int c = 0; c < 4; c++) {
            uint32_t phi[4], plo[4];
#pragma unroll
            for (int u = 0; u < 4; u++) {
                float pa = sacc[2 * c + (u >> 1)][(u & 1) * 2];
                float pb = sacc[2 * c + (u >> 1)][(u & 1) * 2 + 1];
                __half ha = __float2half_rn(pa), hb = __float2half_rn(pb);
                __half2 hh = __halves2half2(ha, hb);
                __half2 llv = __floats2half2_rn(pa - __half2float(ha), pb - __half2float(hb));
                phi[u] = *(uint32_t*)&hh;
                plo[u] = *(uint32_t*)&llv;
            }
#pragma unroll
            for (int jp = 0; jp < 8; jp++) {
                uint32_t vh[4], vl[4];
                uint32_t va = smb + vRow + c * (16 * PIT) + jp * 32;
                ldx4t(vh, va + AVHI);
                ldx4t(vl, va + AVLO);
                mma16816(oacc[2 * jp],     phi, vh[0], vh[1]);
                mma16816(oacc[2 * jp],     phi, vl[0], vl[1]);
                mma16816(oacc[2 * jp],     plo, vh[0], vh[1]);
                mma16816(oacc[2 * jp + 1], phi, vh[2], vh[3]);
                mma16816(oacc[2 * jp + 1], phi, vl[2], vl[3]);
                mma16816(oacc[2 * jp + 1], plo, vh[2], vh[3]);
            }
        }
    }

    const float i0 = 1.0f / l0, i1 = 1.0f / l1;
    const int row0 = qbase + w * 16 + lq;
    __half* ob0 = o + (size_t)(b * LL + row0) * DIMS + h * HD;
    __half* ob1 = ob0 + (size_t)8 * DIMS;
#pragma unroll
    for (int j = 0; j < 16; j++) {
        int col = j * 8 + 2 * lt;
        __half2 h0 = __floats2half2_rn(oacc[j][0] * i0, oacc[j][1] * i0);
        __half2 h1 = __floats2half2_rn(oacc[j][2] * i1, oacc[j][3] * i1);
        *(uint32_t*)(ob0 + col) = *(uint32_t*)&h0;
        *(uint32_t*)(ob1 + col) = *(uint32_t*)&h1;
    }
}

// ---------------------------------------------------------------------------
extern "C" void kernel_launch(void* const* d_in, const int* in_sizes, int n_in,
                              void* d_out, int out_size)
{
    const float* x  = (const float*)d_in[0];
    const float* wq = (const float*)d_in[1];
    const float* wk = (const float*)d_in[2];
    const float* wv = (const float*)d_in[3];
    const float* wo = (const float*)d_in[4];
    const float* fr = (const float*)d_in[5];
    float* out = (float*)d_out;

    __half *xh, *wqh, *wkh, *wvh, *woh, *ah;
    __half *qhi, *qlo, *khi, *klo, *vhi, *vlo;
    cudaGetSymbolAddress((void**)&xh,  g_xh);
    cudaGetSymbolAddress((void**)&wqh, g_wqh);
    cudaGetSymbolAddress((void**)&wkh, g_wkh);
    cudaGetSymbolAddress((void**)&wvh, g_wvh);
    cudaGetSymbolAddress((void**)&woh, g_woh);
    cudaGetSymbolAddress((void**)&ah,  g_ah);
    cudaGetSymbolAddress((void**)&qhi, g_qhi);
    cudaGetSymbolAddress((void**)&qlo, g_qlo);
    cudaGetSymbolAddress((void**)&khi, g_khi);
    cudaGetSymbolAddress((void**)&klo, g_klo);
    cudaGetSymbolAddress((void**)&vhi, g_vhi);
    cudaGetSymbolAddress((void**)&vlo, g_vlo);

    cudaFuncSetAttribute(gemm_qkv, cudaFuncAttributeMaxDynamicSharedMemorySize, GEMM_SMEM);
    cudaFuncSetAttribute(gemm_h,   cudaFuncAttributeMaxDynamicSharedMemorySize, GEMM_SMEM);
    cudaFuncSetAttribute(attn_mma, cudaFuncAttributeMaxDynamicSharedMemorySize, ATTN_SMEM);

    // One fused conversion pass (grid-stride, deep MLP)
    cvt_all<<<2048, 256>>>(x, wq, wk, wv, wo, xh, wqh, wkh, wvh, woh);

    // Fused QKV projections + RoPE + split (one launch, 48x32 CTAs)
    gemm_qkv<<<dim3(48, MM / 128), 256, GEMM_SMEM>>>(
        xh, wqh, wkh, wvh, qhi, qlo, khi, klo, vhi, vlo, fr);

    attn_mma<<<dim3(LL / 64, NH, BB), 128, ATTN_SMEM>>>(qhi, qlo, khi, klo, vhi, vlo, ah);

    gemm_h<<<dim3(DIMS / 128, MM / 128), 256, GEMM_SMEM>>>(ah, woh, out, DIMS, DIMS);
}

// round 14
// speedup vs baseline: 8.1880x; 1.0020x over previous
#include <cuda_runtime.h>
#include <cuda_fp16.h>
#include <math.h>
#include <stdint.h>

#define BB   4
#define LL   1024
#define MM   (BB*LL)        // 4096 tokens
#define DIMS 4096
#define NH   32
#define NKV  8
#define HD   128
#define DKV  (NKV*HD)       // 1024

// Scratch (no cudaMalloc allowed) ------------------------------------------
__device__ __half g_xh [(size_t)MM*DIMS];
__device__ __half g_wqh[(size_t)DIMS*DIMS];
__device__ __half g_wkh[(size_t)DKV*DIMS];
__device__ __half g_wvh[(size_t)DKV*DIMS];
__device__ __half g_woh[(size_t)DIMS*DIMS];
__device__ __half g_ah [(size_t)MM*DIMS];   // attention out (half, feeds wo GEMM)
// pre-split hi/lo fp16 Q/K/V, head-major layout [b][head][seq][d]
__device__ __half g_qhi[(size_t)MM*DIMS];
__device__ __half g_qlo[(size_t)MM*DIMS];
__device__ __half g_khi[(size_t)MM*DKV];
__device__ __half g_klo[(size_t)MM*DKV];
__device__ __half g_vhi[(size_t)MM*DKV];
__device__ __half g_vlo[(size_t)MM*DKV];

// ======================= helpers ===========================================
__device__ __forceinline__ uint32_t smem_u32(const void* p) {
    uint32_t a;
    asm("{ .reg .u64 t; cvta.to.shared.u64 t, %1; cvt.u32.u64 %0, t; }"
        : "=r"(a) : "l"(p));
    return a;
}
__device__ __forceinline__ void ldx4(uint32_t* r, uint32_t addr) {
    asm volatile("ldmatrix.sync.aligned.m8n8.x4.shared.b16 {%0,%1,%2,%3}, [%4];"
                 : "=r"(r[0]), "=r"(r[1]), "=r"(r[2]), "=r"(r[3]) : "r"(addr));
}
__device__ __forceinline__ void ldx4t(uint32_t* r, uint32_t addr) {
    asm volatile("ldmatrix.sync.aligned.m8n8.x4.trans.shared.b16 {%0,%1,%2,%3}, [%4];"
                 : "=r"(r[0]), "=r"(r[1]), "=r"(r[2]), "=r"(r[3]) : "r"(addr));
}
__device__ __forceinline__ void mma16816(float* c, const uint32_t* a,
                                         uint32_t b0, uint32_t b1) {
    asm volatile(
        "mma.sync.aligned.m16n8k16.row.col.f32.f16.f16.f32 "
        "{%0,%1,%2,%3}, {%4,%5,%6,%7}, {%8,%9}, {%0,%1,%2,%3};"
        : "+f"(c[0]), "+f"(c[1]), "+f"(c[2]), "+f"(c[3])
        : "r"(a[0]), "r"(a[1]), "r"(a[2]), "r"(a[3]), "r"(b0), "r"(b1));
}
__device__ __forceinline__ void cpa16(uint32_t dst, const void* src) {
    asm volatile("cp.async.cg.shared.global [%0], [%1], 16;"
                 :: "r"(dst), "l"(src) : "memory");
}
__device__ __forceinline__ void split_store(__half* hi, __half* lo, size_t idx,
                                            float x0, float x1) {
    __half h0 = __float2half_rn(x0), h1 = __float2half_rn(x1);
    __half2 hh = __halves2half2(h0, h1);
    __half2 llv = __floats2half2_rn(x0 - __half2float(h0), x1 - __half2float(h1));
    *(uint32_t*)(hi + idx) = *(uint32_t*)&hh;
    *(uint32_t*)(lo + idx) = *(uint32_t*)&llv;
}

// -------- fused fp32 -> fp16 convert of ALL operands (grid-stride) ---------
__global__ void cvt_all(const float* __restrict__ x,  const float* __restrict__ wq,
                        const float* __restrict__ wk, const float* __restrict__ wv,
                        const float* __restrict__ wo,
                        __half* __restrict__ xh,  __half* __restrict__ wqh,
                        __half* __restrict__ wkh, __half* __restrict__ wvh,
                        __half* __restrict__ woh)
{
    const long NB = (long)MM * DIMS / 4;    // 4M float4
    const long NK = (long)DKV * DIMS / 4;   // 1M float4
    const long total = 3 * NB + 2 * NK;
    const long stride = (long)gridDim.x * blockDim.x;
    for (long i = (long)blockIdx.x * blockDim.x + threadIdx.x; i < total; i += stride) {
        const float* in; __half* out; long j = i;
        if (j < NB)                   { in = x;  out = xh; }
        else if (j < 2 * NB)          { in = wq; out = wqh; j -= NB; }
        else if (j < 2 * NB + NK)     { in = wk; out = wkh; j -= 2 * NB; }
        else if (j < 2 * NB + 2 * NK) { in = wv; out = wvh; j -= 2 * NB + NK; }
        else                          { in = wo; out = woh; j -= 2 * NB + 2 * NK; }
        float4 v = ((const float4*)in)[j];
        __half2 h0 = __floats2half2_rn(v.x, v.y);
        __half2 h1 = __floats2half2_rn(v.z, v.w);
        ((uint2*)out)[j] = make_uint2(*(uint32_t*)&h0, *(uint32_t*)&h1);
    }
}

// ============ shared GEMM mainloop constants (GTK=64, 3-stage) =============
#define GTK 64
#define HROW 144                     // 128B data + 16B pad per row
#define HTILE_B (128 * HROW)         // 18432 per operand
#define STAGE_B (2 * HTILE_B)        // 36864
#define NSTAGE  3
#define GEMM_SMEM (NSTAGE * STAGE_B) // 110592 -> 2 CTAs/SM (221184 <= 228KB)

// Mainloop: per k-tile, prefetch cp.asyncs are issued AFTER the ks=0 MMA
// batch so their LSU issue overlaps tensor-pipe-busy time instead of sitting
// in front of the first MMA. Numerics identical (same K order).
#define GEMM_MAINLOOP(A_, B_, K_)                                              \
    const __half* aSrc[4]; const __half* bSrc[4]; uint32_t dOff[4];            \
    _Pragma("unroll")                                                          \
    for (int j = 0; j < 4; j++) {                                              \
        int idx = tid + j * 256;            /* 0..1023 */                      \
        int r = idx >> 3, c = idx & 7;                                         \
        aSrc[j] = A_ + (size_t)(bm + r) * K_ + c * 8;                          \
        bSrc[j] = B_ + (size_t)(bnl + r) * K_ + c * 8;                         \
        dOff[j] = r * HROW + c * 16;                                           \
    }                                                                          \
    const uint32_t aOff = (uint32_t)(wm * 32 + (lsel & 1) * 8 + lrow) * HROW   \
                        + (uint32_t)(lsel >> 1) * 16;                          \
    const uint32_t bOff = (uint32_t)(wn * 64 + (lsel >> 1) * 8 + lrow) * HROW  \
                        + (uint32_t)(lsel & 1) * 16;                           \
    float acc[2][8][4];                                                        \
    _Pragma("unroll")                                                          \
    for (int mt = 0; mt < 2; mt++)                                             \
        _Pragma("unroll")                                                      \
        for (int nt = 0; nt < 8; nt++)                                         \
            _Pragma("unroll")                                                  \
            for (int i = 0; i < 4; i++) acc[mt][nt][i] = 0.0f;                 \
    const int KT = K_ / GTK;                                                   \
    _Pragma("unroll")                                                          \
    for (int st = 0; st < NSTAGE - 1; st++) {                                  \
        const uint32_t sb = smb + st * STAGE_B;                                \
        const size_t ko = (size_t)st * GTK;                                    \
        _Pragma("unroll")                                                      \
        for (int j = 0; j < 4; j++) {                                          \
            cpa16(sb + dOff[j], aSrc[j] + ko);                                 \
            cpa16(sb + HTILE_B + dOff[j], bSrc[j] + ko);                       \
        }                                                                      \
        asm volatile("cp.async.commit_group;" ::: "memory");                   \
    }                                                                          \
    int cb = 0, pb = NSTAGE - 1;                                               \
    for (int kt = 0; kt < KT; kt++) {                                          \
        asm volatile("cp.async.wait_group %0;" :: "n"(NSTAGE - 2) : "memory"); \
        __syncthreads();                                                       \
        const uint32_t bufA = smb + cb * STAGE_B;                              \
        const uint32_t bufB = bufA + HTILE_B;                                  \
        if (++cb == NSTAGE) cb = 0;                                            \
        _Pragma("unroll")                                                      \
        for (int ks = 0; ks < 4; ks++) {                                       \
            uint32_t a[2][4], b[4][4];                                         \
            _Pragma("unroll")                                                  \
            for (int mt = 0; mt < 2; mt++)                                     \
                ldx4(a[mt], bufA + aOff + mt * (16 * HROW) + ks * 32);         \
            _Pragma("unroll")                                                  \
            for (int p = 0; p < 4; p++)                                        \
                ldx4(b[p], bufB + bOff + p * (16 * HROW) + ks * 32);           \
            _Pragma("unroll")                                                  \
            for (int mt = 0; mt < 2; mt++)                                     \
                _Pragma("unroll")                                              \
                for (int nt = 0; nt < 8; nt++)                                 \
                    mma16816(acc[mt][nt], a[mt],                               \
                             b[nt >> 1][(nt & 1) * 2], b[nt >> 1][(nt & 1) * 2 + 1]); \
            if (ks == 0) {   /* prefetch overlapped with busy tensor pipe */   \
                const int kp = (kt + NSTAGE - 1 < KT) ? (kt + NSTAGE - 1) : (KT - 1); \
                const uint32_t sb = smb + pb * STAGE_B;                        \
                const size_t ko = (size_t)kp * GTK;                            \
                _Pragma("unroll")                                              \
                for (int j = 0; j < 4; j++) {                                  \
                    cpa16(sb + dOff[j], aSrc[j] + ko);                         \
                    cpa16(sb + HTILE_B + dOff[j], bSrc[j] + ko);               \
                }                                                              \
                asm volatile("cp.async.commit_group;" ::: "memory");           \
                if (++pb == NSTAGE) pb = 0;                                    \
            }                                                                  \
        }                                                                      \
    }

// ======== Fused QKV projection GEMM + RoPE + hi/lo split epilogue ==========
// grid.x: [0,32) Q-tiles, [32,40) K-tiles, [40,48) V-tiles ; grid.y: M-tiles
__global__ __launch_bounds__(256, 2) void gemm_qkv(const __half* __restrict__ A,
                                                   const __half* __restrict__ WQ,
                                                   const __half* __restrict__ WK,
                                                   const __half* __restrict__ WV,
                                                   __half* __restrict__ qhi, __half* __restrict__ qlo,
                                                   __half* __restrict__ khi, __half* __restrict__ klo,
                                                   __half* __restrict__ vhi, __half* __restrict__ vlo,
                                                   const float* __restrict__ freqs)
{
    extern __shared__ char sm[];
    const uint32_t smb = smem_u32(sm);
    const int tid  = threadIdx.x;
    const int lane = tid & 31;
    const int warp = tid >> 5;
    const int wm   = warp >> 1;
    const int wn   = warp & 1;
    const int lq   = lane >> 2;
    const int lt   = lane & 3;
    const int lrow = lane & 7;
    const int lsel = lane >> 3;

    const int bx = blockIdx.x;
    int mode; const __half* Bm; int bnl;
    if (bx < 32)      { mode = 0; Bm = WQ; bnl = bx * 128; }
    else if (bx < 40) { mode = 1; Bm = WK; bnl = (bx - 32) * 128; }
    else              { mode = 2; Bm = WV; bnl = (bx - 40) * 128; }
    const int bm = blockIdx.y * 128;

    GEMM_MAINLOOP(A, Bm, DIMS)

    // ---- fused epilogue: RoPE (Q,K) + hi/lo split + head-major store ----
    const float qscale = 0.088388347648318447f;   // 1/sqrt(128)
    const int nh  = (mode == 0) ? NH : NKV;
    __half* hiB = (mode == 0) ? qhi : (mode == 1) ? khi : vhi;
    __half* loB = (mode == 0) ? qlo : (mode == 1) ? klo : vlo;
    const float scl = (mode == 0) ? qscale : 1.0f;

#pragma unroll
    for (int mt = 0; mt < 2; mt++) {
        const int r0 = bm + wm * 32 + mt * 16 + lq;
#pragma unroll
        for (int nt = 0; nt < 8; nt++) {
            const int c  = bnl + wn * 64 + nt * 8 + 2 * lt;   // even
            const int h  = c >> 7;
            const int d  = c & 127;
            if (mode == 2) {
#pragma unroll
                for (int rr = 0; rr < 2; rr++) {
                    const int r = r0 + rr * 8;
                    const int l = r & (LL - 1), bq = r >> 10;
                    size_t idx = (((size_t)(bq * nh + h) * LL + l) * HD + d);
                    split_store(hiB, loB, idx, acc[mt][nt][rr * 2], acc[mt][nt][rr * 2 + 1]);
                }
            } else {
                const int d2 = d >> 1;
#pragma unroll
                for (int rr = 0; rr < 2; rr++) {
                    const int r = r0 + rr * 8;
                    const int l = r & (LL - 1), bq = r >> 10;
                    const float f = freqs[l * 64 + d2];
                    const float cs = cosf(f), sn = sinf(f);
                    const float a0 = acc[mt][nt][rr * 2], a1 = acc[mt][nt][rr * 2 + 1];
                    const float x0 = (a0 * cs - a1 * sn) * scl;
                    const float x1 = (a0 * sn + a1 * cs) * scl;
                    size_t idx = (((size_t)(bq * nh + h) * LL + l) * HD + d);
                    split_store(hiB, loB, idx, x0, x1);
                }
            }
        }
    }
}

// ============ plain fp16 GEMM (wo projection), fp32 C out ==================
__global__ __launch_bounds__(256, 2) void gemm_h(const __half* __restrict__ A,
                                                 const __half* __restrict__ Bw,
                                                 float* __restrict__ C,
                                                 int N, int K)
{
    extern __shared__ char sm[];
    const uint32_t smb = smem_u32(sm);
    const int tid  = threadIdx.x;
    const int lane = tid & 31;
    const int warp = tid >> 5;
    const int wm   = warp >> 1;
    const int wn   = warp & 1;
    const int lq   = lane >> 2;
    const int lt   = lane & 3;
    const int lrow = lane & 7;
    const int lsel = lane >> 3;
    const int bm  = blockIdx.y * 128;
    const int bnl = blockIdx.x * 128;

    GEMM_MAINLOOP(A, Bw, K)

#pragma unroll
    for (int mt = 0; mt < 2; mt++) {
        int r0 = bm + wm * 32 + mt * 16 + lq;
#pragma unroll
        for (int nt = 0; nt < 8; nt++) {
            int c = bnl + wn * 64 + nt * 8 + 2 * lt;
            *(float2*)(C + (size_t)r0 * N + c)       = make_float2(acc[mt][nt][0], acc[mt][nt][1]);
            *(float2*)(C + (size_t)(r0 + 8) * N + c) = make_float2(acc[mt][nt][2], acc[mt][nt][3]);
        }
    }
}

// ======== MMA flash attention: pre-split fp16, 64-row Q tiles ==============
// Staged KV waits: compute S with K while V is still in flight.
#define PIT   272
#define AQHI  0
#define AQLO  17408
#define AKHI  34816
#define AKLO  52224
#define AVHI  69632
#define AVLO  87040
#define ATTN_SMEM 104448   // x2 CTAs = 208896 <= 228KB/SM

__global__ __launch_bounds__(128, 2) void attn_mma(const __half* __restrict__ qhi,
                                                   const __half* __restrict__ qlo,
                                                   const __half* __restrict__ khi,
                                                   const __half* __restrict__ klo,
                                                   const __half* __restrict__ vhi,
                                                   const __half* __restrict__ vlo,
                                                   __half* __restrict__ o)
{
    extern __shared__ char smx[];
    const uint32_t smb = smem_u32(smx);
    const int tid = threadIdx.x, lane = tid & 31, w = tid >> 5;
    const int lq = lane >> 2, lt = lane & 3, lrow = lane & 7, lsel = lane >> 3;
    const int qt = (gridDim.x - 1) - blockIdx.x;   // heavy tiles first
    const int h = blockIdx.y, b = blockIdx.z;
    const int qbase = qt * 64;
    const int kvh = h >> 2;

    const __half* qhg = qhi + (((size_t)(b * NH + h) * LL + qbase) * HD);
    const __half* qlg = qlo + (((size_t)(b * NH + h) * LL + qbase) * HD);
#pragma unroll
    for (int j = 0; j < 16; j++) {
        int idx = tid + j * 128;
        int arr = idx >> 10;
        int e = idx & 1023;
        int r = e >> 4, c = e & 15;
        const __half* src = (arr ? qlg : qhg) + (size_t)r * HD + c * 8;
        cpa16(smb + (arr ? AQLO : AQHI) + r * PIT + c * 16, src);
    }
    asm volatile("cp.async.commit_group;" ::: "memory");

    float oacc[16][4];
#pragma unroll
    for (int j = 0; j < 16; j++)
#pragma unroll
        for (int i = 0; i < 4; i++) oacc[j][i] = 0.0f;
    float m0 = -1e30f, m1 = -1e30f, l0 = 0.0f, l1 = 0.0f;

    const __half* khg = khi + ((size_t)(b * NKV + kvh) * LL) * HD;
    const __half* klg = klo + ((size_t)(b * NKV + kvh) * LL) * HD;
    const __half* vhg = vhi + ((size_t)(b * NKV + kvh) * LL) * HD;
    const __half* vlg = vlo + ((size_t)(b * NKV + kvh) * LL) * HD;

    const uint32_t qOff = (uint32_t)(w * 16 + (lsel & 1) * 8 + lrow) * PIT
                        + (uint32_t)(lsel >> 1) * 16;
    const uint32_t kOff = (uint32_t)((lsel >> 1) * 8 + lrow) * PIT
                        + (uint32_t)(lsel & 1) * 16;
    const uint32_t vRow = (uint32_t)((lsel & 1) * 8 + lrow) * PIT
                        + (uint32_t)(lsel >> 1) * 16;

    for (int kt = 0; kt <= qt; kt++) {
        __syncthreads();   // prior reads of K/V smem done before overwrite
        // ---- K tile (khi+klo): 16 chunks/thread, own commit group ----
#pragma unroll
        for (int j = 0; j < 16; j++) {
            int idx = tid + j * 128;          // 0..2047
            int arr = idx >> 10;              // 0=khi 1=klo
            int e = idx & 1023;
            int r = e >> 4, c = e & 15;
            size_t go = (size_t)(kt * 64 + r) * HD + c * 8;
            cpa16(smb + (arr ? AKLO : AKHI) + r * PIT + c * 16,
                  (arr ? klg : khg) + go);
        }
        asm volatile("cp.async.commit_group;" ::: "memory");
        // ---- V tile (vhi+vlo): separate group, stays in flight during S ---
#pragma unroll
        for (int j = 0; j < 16; j++) {
            int idx = tid + j * 128;
            int arr = idx >> 10;              // 0=vhi 1=vlo
            int e = idx & 1023;
            int r = e >> 4, c = e & 15;
            size_t go = (size_t)(kt * 64 + r) * HD + c * 8;
            cpa16(smb + (arr ? AVLO : AVHI) + r * PIT + c * 16,
                  (arr ? vlg : vhg) + go);
        }
        asm volatile("cp.async.commit_group;" ::: "memory");
        asm volatile("cp.async.wait_group 1;" ::: "memory");   // Q+K ready
        __syncthreads();

        // ---- S = Q K^T (hh + hl + lh) — V still loading underneath ----
        float sacc[8][4];
#pragma unroll
        for (int nt = 0; nt < 8; nt++)
#pragma unroll
            for (int i = 0; i < 4; i++) sacc[nt][i] = 0.0f;

#pragma unroll
        for (int c = 0; c < 8; c++) {
            uint32_t qh[4], ql[4];
            ldx4(qh, smb + AQHI + qOff + c * 32);
            ldx4(ql, smb + AQLO + qOff + c * 32);
#pragma unroll
            for (int p = 0; p < 4; p++) {
                uint32_t kh[4], kl[4];
                ldx4(kh, smb + AKHI + kOff + p * (16 * PIT) + c * 32);
                ldx4(kl, smb + AKLO + kOff + p * (16 * PIT) + c * 32);
                mma16816(sacc[2 * p],     qh, kh[0], kh[1]);
                mma16816(sacc[2 * p],     qh, kl[0], kl[1]);
                mma16816(sacc[2 * p],     ql, kh[0], kh[1]);
                mma16816(sacc[2 * p + 1], qh, kh[2], kh[3]);
                mma16816(sacc[2 * p + 1], qh, kl[2], kl[3]);
                mma16816(sacc[2 * p + 1], ql, kh[2], kh[3]);
            }
        }

        if (kt == qt) {
            const int qg0 = qbase + w * 16 + lq;
            const int qg1 = qg0 + 8;
            const int kvb = kt * 64;
#pragma unroll
            for (int nt = 0; nt < 8; nt++) {
                int cv = kvb + nt * 8 + 2 * lt;
                if (cv     > qg0) sacc[nt][0] = -1e30f;
                if (cv + 1 > qg0) sacc[nt][1] = -1e30f;
                if (cv     > qg1) sacc[nt][2] = -1e30f;
                if (cv + 1 > qg1) sacc[nt][3] = -1e30f;
            }
        }

        float mx0 = -1e30f, mx1 = -1e30f;
#pragma unroll
        for (int nt = 0; nt < 8; nt++) {
            mx0 = fmaxf(mx0, fmaxf(sacc[nt][0], sacc[nt][1]));
            mx1 = fmaxf(mx1, fmaxf(sacc[nt][2], sacc[nt][3]));
        }
        mx0 = fmaxf(mx0, __shfl_xor_sync(0xffffffffu, mx0, 1));
        mx0 = fmaxf(mx0, __shfl_xor_sync(0xffffffffu, mx0, 2));
        mx1 = fmaxf(mx1, __shfl_xor_sync(0xffffffffu, mx1, 1));
        mx1 = fmaxf(mx1, __shfl_xor_sync(0xffffffffu, mx1, 2));
        float mn0 = fmaxf(m0, mx0), mn1 = fmaxf(m1, mx1);
        float cr0 = __expf(m0 - mn0), cr1 = __expf(m1 - mn1);
        m0 = mn0; m1 = mn1;
        float sum0 = 0.0f, sum1 = 0.0f;
#pragma unroll
        for (int nt = 0; nt < 8; nt++) {
            sacc[nt][0] = __expf(sacc[nt][0] - m0); sum0 += sacc[nt][0];
            sacc[nt][1] = __expf(sacc[nt][1] - m0); sum0 += sacc[nt][1];
            sacc[nt][2] = __expf(sacc[nt][2] - m1); sum1 += sacc[nt][2];
            sacc[nt][3] = __expf(sacc[nt][3] - m1); sum1 += sacc[nt][3];
        }
        sum0 += __shfl_xor_sync(0xffffffffu, sum0, 1);
        sum0 += __shfl_xor_sync(0xffffffffu, sum0, 2);
        sum1 += __shfl_xor_sync(0xffffffffu, sum1, 1);
        sum1 += __shfl_xor_sync(0xffffffffu, sum1, 2);
        l0 = l0 * cr0 + sum0;
        l1 = l1 * cr1 + sum1;
#pragma unroll
        for (int j = 0; j < 16; j++) {
            oacc[j][0] *= cr0; oacc[j][1] *= cr0;
            oacc[j][2] *= cr1; oacc[j][3] *= cr1;
        }

        // ---- now require V ----
        asm volatile("cp.async.wait_group 0;" ::: "memory");
        __syncthreads();

#pragma unroll
        for (int c = 0; c < 4; c++) {
            uint32_t phi[4], plo[4];
#pragma unroll
            for (int u = 0; u < 4; u++) {
                float pa = sacc[2 * c + (u >> 1)][(u & 1) * 2];
                float pb = sacc[2 * c + (u >> 1)][(u & 1) * 2 + 1];
                __half ha = __float2half_rn(pa), hb = __float2half_rn(pb);
                __half2 hh = __halves2half2(ha, hb);
                __half2 llv = __floats2half2_rn(pa - __half2float(ha), pb - __half2float(hb));
                phi[u] = *(uint32_t*)&hh;
                plo[u] = *(uint32_t*)&llv;
            }
#pragma unroll
            for (int jp = 0; jp < 8; jp++) {
                uint32_t vh[4], vl[4];
                uint32_t va = smb + vRow + c * (16 * PIT) + jp * 32;
                ldx4t(vh, va + AVHI);
                ldx4t(vl, va + AVLO);
                mma16816(oacc[2 * jp],     phi, vh[0], vh[1]);
                mma16816(oacc[2 * jp],     phi, vl[0], vl[1]);
                mma16816(oacc[2 * jp],     plo, vh[0], vh[1]);
                mma16816(oacc[2 * jp + 1], phi, vh[2], vh[3]);
                mma16816(oacc[2 * jp + 1], phi, vl[2], vl[3]);
                mma16816(oacc[2 * jp + 1], plo, vh[2], vh[3]);
            }
        }
    }

    const float i0 = 1.0f / l0, i1 = 1.0f / l1;
    const int row0 = qbase + w * 16 + lq;
    __half* ob0 = o + (size_t)(b * LL + row0) * DIMS + h * HD;
    __half* ob1 = ob0 + (size_t)8 * DIMS;
#pragma unroll
    for (int j = 0; j < 16; j++) {
        int col = j * 8 + 2 * lt;
        __half2 h0 = __floats2half2_rn(oacc[j][0] * i0, oacc[j][1] * i0);
        __half2 h1 = __floats2half2_rn(oacc[j][2] * i1, oacc[j][3] * i1);
        *(uint32_t*)(ob0 + col) = *(uint32_t*)&h0;
        *(uint32_t*)(ob1 + col) = *(uint32_t*)&h1;
    }
}

// ---------------------------------------------------------------------------
extern "C" void kernel_launch(void* const* d_in, const int* in_sizes, int n_in,
                              void* d_out, int out_size)
{
    const float* x  = (const float*)d_in[0];
    const float* wq = (const float*)d_in[1];
    const float* wk = (const float*)d_in[2];
    const float* wv = (const float*)d_in[3];
    const float* wo = (const float*)d_in[4];
    const float* fr = (const float*)d_in[5];
    float* out = (float*)d_out;

    __half *xh, *wqh, *wkh, *wvh, *woh, *ah;
    __half *qhi, *qlo, *khi, *klo, *vhi, *vlo;
    cudaGetSymbolAddress((void**)&xh,  g_xh);
    cudaGetSymbolAddress((void**)&wqh, g_wqh);
    cudaGetSymbolAddress((void**)&wkh, g_wkh);
    cudaGetSymbolAddress((void**)&wvh, g_wvh);
    cudaGetSymbolAddress((void**)&woh, g_woh);
    cudaGetSymbolAddress((void**)&ah,  g_ah);
    cudaGetSymbolAddress((void**)&qhi, g_qhi);
    cudaGetSymbolAddress((void**)&qlo, g_qlo);
    cudaGetSymbolAddress((void**)&khi, g_khi);
    cudaGetSymbolAddress((void**)&klo, g_klo);
    cudaGetSymbolAddress((void**)&vhi, g_vhi);
    cudaGetSymbolAddress((void**)&vlo, g_vlo);

    cudaFuncSetAttribute(gemm_qkv, cudaFuncAttributeMaxDynamicSharedMemorySize, GEMM_SMEM);
    cudaFuncSetAttribute(gemm_h,   cudaFuncAttributeMaxDynamicSharedMemorySize, GEMM_SMEM);
    cudaFuncSetAttribute(attn_mma, cudaFuncAttributeMaxDynamicSharedMemorySize, ATTN_SMEM);

    // One fused conversion pass (grid-stride, deep MLP)
    cvt_all<<<2048, 256>>>(x, wq, wk, wv, wo, xh, wqh, wkh, wvh, woh);

    // Fused QKV projections + RoPE + split (one launch, 48x32 CTAs)
    gemm_qkv<<<dim3(48, MM / 128), 256, GEMM_SMEM>>>(
        xh, wqh, wkh, wvh, qhi, qlo, khi, klo, vhi, vlo, fr);

    attn_mma<<<dim3(LL / 64, NH, BB), 128, ATTN_SMEM>>>(qhi, qlo, khi, klo, vhi, vlo, ah);

    gemm_h<<<dim3(DIMS / 128, MM / 128), 256, GEMM_SMEM>>>(ah, woh, out, DIMS, DIMS);
}